// round 3
// baseline (speedup 1.0000x reference)
#include <cuda_runtime.h>
#include <math_constants.h>

// Problem constants (fixed by the reference)
static constexpr int MODEL_DIM = 1024;
static constexpr int HEAD      = 16;
static constexpr int HEAD_DIM  = 64;   // MODEL_DIM / HEAD
static constexpr int BATCH     = 2;
static constexpr int SEQ       = 2048;
static constexpr int TOK       = BATCH * SEQ;      // 4096
static constexpr int QKV_DIM   = 3 * MODEL_DIM;    // 3072

// Scratch (allocation-free rule: __device__ globals)
__device__ float g_qkv[TOK * QKV_DIM];   // 48 MB: [token][3*D] (q|k|v packed per head)
__device__ float g_z[TOK * MODEL_DIM];   // 16 MB: attention output, [token][h*64+d]

// ---------------------------------------------------------------------------
// SGEMM: C[M,N] = A[M,K] @ B[K,N] + bias[N]
// BM=BN=128, BK=8, 256 threads, 8x8 per thread, float4 global loads.
// M,N,K are multiples of the tile sizes for both call sites (no bounds checks).
// ---------------------------------------------------------------------------
__global__ __launch_bounds__(256)
void sgemm_bias_kernel(const float* __restrict__ A, const float* __restrict__ B,
                       const float* __restrict__ bias, float* __restrict__ C,
                       int M, int N, int K)
{
    constexpr int BM = 128, BN = 128, BK = 8;
    __shared__ float As[BK][BM];  // A staged transposed: As[k][m]
    __shared__ float Bs[BK][BN];

    const int t  = threadIdx.x;
    const int bm = blockIdx.y * BM;
    const int bn = blockIdx.x * BN;
    const int tx = t & 15;        // 0..15 -> 8 output cols each
    const int ty = t >> 4;        // 0..15 -> 8 output rows each

    // A load mapping: 128 rows x 8 cols = 256 float4
    const int a_r  = t >> 1;          // 0..127
    const int a_c4 = (t & 1) * 4;     // 0 or 4
    // B load mapping: 8 rows x 128 cols = 256 float4
    const int b_r  = t >> 5;          // 0..7
    const int b_c4 = (t & 31) * 4;    // 0..124

    float acc[8][8];
#pragma unroll
    for (int i = 0; i < 8; i++)
#pragma unroll
        for (int j = 0; j < 8; j++) acc[i][j] = 0.0f;

    for (int k0 = 0; k0 < K; k0 += BK) {
        float4 av = *reinterpret_cast<const float4*>(A + (size_t)(bm + a_r) * K + k0 + a_c4);
        As[a_c4 + 0][a_r] = av.x;
        As[a_c4 + 1][a_r] = av.y;
        As[a_c4 + 2][a_r] = av.z;
        As[a_c4 + 3][a_r] = av.w;
        *reinterpret_cast<float4*>(&Bs[b_r][b_c4]) =
            *reinterpret_cast<const float4*>(B + (size_t)(k0 + b_r) * N + bn + b_c4);
        __syncthreads();

#pragma unroll
        for (int k = 0; k < BK; k++) {
            float a[8], b[8];
            *reinterpret_cast<float4*>(&a[0]) = *reinterpret_cast<const float4*>(&As[k][ty * 8]);
            *reinterpret_cast<float4*>(&a[4]) = *reinterpret_cast<const float4*>(&As[k][ty * 8 + 4]);
            *reinterpret_cast<float4*>(&b[0]) = *reinterpret_cast<const float4*>(&Bs[k][tx * 8]);
            *reinterpret_cast<float4*>(&b[4]) = *reinterpret_cast<const float4*>(&Bs[k][tx * 8 + 4]);
#pragma unroll
            for (int i = 0; i < 8; i++)
#pragma unroll
                for (int j = 0; j < 8; j++)
                    acc[i][j] = fmaf(a[i], b[j], acc[i][j]);
        }
        __syncthreads();
    }

    // Epilogue with bias
#pragma unroll
    for (int i = 0; i < 8; i++) {
        float* crow = C + (size_t)(bm + ty * 8 + i) * N + bn + tx * 8;
#pragma unroll
        for (int j = 0; j < 8; j++)
            crow[j] = acc[i][j] + bias[bn + tx * 8 + j];
    }
}

// ---------------------------------------------------------------------------
// Flash-style attention. One block = 64 query rows of one (b,h).
// Streams K/V in 64-row tiles with online softmax; never materializes scores.
// 256 threads: 16x16 layout, 4x4 micro-tile per thread for both QK^T and P@V.
// Dynamic smem: Qs,Ks,Vs,Ss each 64x65 fp32 + 3x64 row stats = 67328 B.
// ---------------------------------------------------------------------------
#define SM_PITCH 65
__global__ __launch_bounds__(256)
void attn_kernel(const float* __restrict__ qkv, float* __restrict__ z)
{
    extern __shared__ float smem[];
    float* Qs    = smem;                    // [64][65]
    float* Ks    = Qs + 64 * SM_PITCH;      // [64][65]
    float* Vs    = Ks + 64 * SM_PITCH;      // [64][65]
    float* Ss    = Vs + 64 * SM_PITCH;      // [64][65]
    float* row_m = Ss + 64 * SM_PITCH;      // [64]
    float* row_l = row_m + 64;              // [64]
    float* row_c = row_l + 64;              // [64]

    const int t  = threadIdx.x;
    const int tx = t & 15;
    const int ty = t >> 4;
    const int bh = blockIdx.y;
    const int b  = bh / HEAD;
    const int h  = bh % HEAD;
    const int q0 = blockIdx.x * 64;

    const size_t tok_base = (size_t)b * SEQ;
    const int q_col = h * HEAD_DIM;          // q at col offset h*64
    const int k_col = MODEL_DIM + q_col;     // k at +1024
    const int v_col = 2 * MODEL_DIM + q_col; // v at +2048

    // Load Q tile (pre-scaled by 1/sqrt(64) = 0.125)
    for (int idx = t; idx < 64 * 64; idx += 256) {
        int r = idx >> 6, c = idx & 63;
        Qs[r * SM_PITCH + c] =
            qkv[(tok_base + q0 + r) * QKV_DIM + q_col + c] * 0.125f;
    }
    if (t < 64) { row_m[t] = -CUDART_INF_F; row_l[t] = 0.0f; }

    float acc[4][4];
#pragma unroll
    for (int i = 0; i < 4; i++)
#pragma unroll
        for (int j = 0; j < 4; j++) acc[i][j] = 0.0f;

    __syncthreads();

    for (int kt = 0; kt < SEQ / 64; kt++) {
        const int kk0 = kt * 64;
        // Load K and V tiles
        for (int idx = t; idx < 64 * 64; idx += 256) {
            int r = idx >> 6, c = idx & 63;
            Ks[r * SM_PITCH + c] = qkv[(tok_base + kk0 + r) * QKV_DIM + k_col + c];
            Vs[r * SM_PITCH + c] = qkv[(tok_base + kk0 + r) * QKV_DIM + v_col + c];
        }
        __syncthreads();

        // S = Q K^T  (64x64), 4x4 per thread
        float s[4][4];
#pragma unroll
        for (int i = 0; i < 4; i++)
#pragma unroll
            for (int j = 0; j < 4; j++) s[i][j] = 0.0f;
#pragma unroll 8
        for (int d = 0; d < 64; d++) {
            float a[4], bb[4];
#pragma unroll
            for (int i = 0; i < 4; i++) a[i]  = Qs[(ty * 4 + i) * SM_PITCH + d];
#pragma unroll
            for (int j = 0; j < 4; j++) bb[j] = Ks[(tx * 4 + j) * SM_PITCH + d];
#pragma unroll
            for (int i = 0; i < 4; i++)
#pragma unroll
                for (int j = 0; j < 4; j++)
                    s[i][j] = fmaf(a[i], bb[j], s[i][j]);
        }
#pragma unroll
        for (int i = 0; i < 4; i++)
#pragma unroll
            for (int j = 0; j < 4; j++)
                Ss[(ty * 4 + i) * SM_PITCH + tx * 4 + j] = s[i][j];
        __syncthreads();

        // Online softmax: one thread per row
        if (t < 64) {
            float m_old = row_m[t];
            float m = m_old;
            float* srow = Ss + t * SM_PITCH;
#pragma unroll 8
            for (int c = 0; c < 64; c++) m = fmaxf(m, srow[c]);
            float corr = __expf(m_old - m);   // exp(-inf)=0 on first tile
            float l = row_l[t] * corr;
#pragma unroll 8
            for (int c = 0; c < 64; c++) {
                float p = __expf(srow[c] - m);
                srow[c] = p;
                l += p;
            }
            row_m[t] = m; row_l[t] = l; row_c[t] = corr;
        }
        __syncthreads();

        // Rescale accumulator, then acc += P @ V
        float ci[4];
#pragma unroll
        for (int i = 0; i < 4; i++) ci[i] = row_c[ty * 4 + i];
#pragma unroll
        for (int i = 0; i < 4; i++)
#pragma unroll
            for (int j = 0; j < 4; j++) acc[i][j] *= ci[i];

#pragma unroll 8
        for (int d = 0; d < 64; d++) {
            float p[4], v[4];
#pragma unroll
            for (int i = 0; i < 4; i++) p[i] = Ss[(ty * 4 + i) * SM_PITCH + d];
#pragma unroll
            for (int j = 0; j < 4; j++) v[j] = Vs[d * SM_PITCH + tx * 4 + j];
#pragma unroll
            for (int i = 0; i < 4; i++)
#pragma unroll
                for (int j = 0; j < 4; j++)
                    acc[i][j] = fmaf(p[i], v[j], acc[i][j]);
        }
        __syncthreads();
    }

    // Epilogue: out = acc / l, written directly in [token][h*64+d] layout
    float inv_l[4];
#pragma unroll
    for (int i = 0; i < 4; i++) inv_l[i] = 1.0f / row_l[ty * 4 + i];
#pragma unroll
    for (int i = 0; i < 4; i++) {
        float* zrow = z + (tok_base + q0 + ty * 4 + i) * MODEL_DIM + q_col + tx * 4;
#pragma unroll
        for (int j = 0; j < 4; j++)
            zrow[j] = acc[i][j] * inv_l[i];
    }
}

// ---------------------------------------------------------------------------
// Launch
// ---------------------------------------------------------------------------
extern "C" void kernel_launch(void* const* d_in, const int* in_sizes, int n_in,
                              void* d_out, int out_size)
{
    const float* x     = (const float*)d_in[0];   // [2,2048,1024]
    const float* w_qkv = (const float*)d_in[1];   // [1024,3072]
    const float* b_qkv = (const float*)d_in[2];   // [3072]
    const float* w_out = (const float*)d_in[3];   // [1024,1024]
    const float* b_out = (const float*)d_in[4];   // [1024]
    float* out = (float*)d_out;                   // [2,2048,1024]

    float *qkv_buf, *z_buf;
    cudaGetSymbolAddress((void**)&qkv_buf, g_qkv);
    cudaGetSymbolAddress((void**)&z_buf, g_z);

    // 1. QKV projection: [4096,3072] = x[4096,1024] @ w_qkv + b_qkv
    {
        dim3 grid(QKV_DIM / 128, TOK / 128);
        sgemm_bias_kernel<<<grid, 256>>>(x, w_qkv, b_qkv, qkv_buf,
                                         TOK, QKV_DIM, MODEL_DIM);
    }

    // 2. Attention (flash-style, online softmax)
    {
        const int smem_bytes = (4 * 64 * SM_PITCH + 3 * 64) * (int)sizeof(float); // 67328
        cudaFuncSetAttribute(attn_kernel,
                             cudaFuncAttributeMaxDynamicSharedMemorySize, smem_bytes);
        dim3 grid(SEQ / 64, BATCH * HEAD);
        attn_kernel<<<grid, 256, smem_bytes>>>(qkv_buf, z_buf);
    }

    // 3. Output projection: [4096,1024] = z @ w_out + b_out
    {
        dim3 grid(MODEL_DIM / 128, TOK / 128);
        sgemm_bias_kernel<<<grid, 256>>>(z_buf, w_out, b_out, out,
                                         TOK, MODEL_DIM, MODEL_DIM);
    }
}

// round 5
// speedup vs baseline: 1.3040x; 1.3040x over previous
#include <cuda_runtime.h>
#include <cuda_bf16.h>
#include <math_constants.h>
#include <cstdint>

// Problem constants
static constexpr int MODEL_DIM = 1024;
static constexpr int HEAD      = 16;
static constexpr int HEAD_DIM  = 64;
static constexpr int BATCH     = 2;
static constexpr int SEQ       = 2048;
static constexpr int TOK       = BATCH * SEQ;      // 4096
static constexpr int QKV_DIM   = 3 * MODEL_DIM;    // 3072

// Scratch (__device__ globals; no runtime allocation allowed)
__device__ float g_qkv[TOK * QKV_DIM];                    // [token][3*D] fp32
__device__ float g_z[TOK * MODEL_DIM];                    // attention out fp32
__device__ __nv_bfloat16 g_xh[TOK * MODEL_DIM];           // x hi/lo bf16
__device__ __nv_bfloat16 g_xl[TOK * MODEL_DIM];
__device__ __nv_bfloat16 g_zh[TOK * MODEL_DIM];           // z hi/lo bf16
__device__ __nv_bfloat16 g_zl[TOK * MODEL_DIM];
__device__ __nv_bfloat16 g_wqkvT_h[QKV_DIM * MODEL_DIM];  // w^T [N][K] bf16
__device__ __nv_bfloat16 g_wqkvT_l[QKV_DIM * MODEL_DIM];
__device__ __nv_bfloat16 g_woutT_h[MODEL_DIM * MODEL_DIM];
__device__ __nv_bfloat16 g_woutT_l[MODEL_DIM * MODEL_DIM];

// ---------------------------------------------------------------------------
// PTX helpers (all sm_80-compatible: work on plain compute_100 target)
// ---------------------------------------------------------------------------
__device__ __forceinline__ uint32_t smem_to_u32(const void* p) {
    uint32_t a;
    asm("{ .reg .u64 tmp; cvta.to.shared.u64 tmp, %1; cvt.u32.u64 %0, tmp; }"
        : "=r"(a) : "l"(p));
    return a;
}
__device__ __forceinline__ void ldsm_x4(uint32_t* r, uint32_t addr) {
    asm volatile("ldmatrix.sync.aligned.m8n8.x4.shared.b16 {%0,%1,%2,%3}, [%4];"
                 : "=r"(r[0]), "=r"(r[1]), "=r"(r[2]), "=r"(r[3]) : "r"(addr));
}
__device__ __forceinline__ void mma_bf16(float* c, const uint32_t* a, const uint32_t* b) {
    asm volatile(
        "mma.sync.aligned.m16n8k16.row.col.f32.bf16.bf16.f32 "
        "{%0,%1,%2,%3}, {%4,%5,%6,%7}, {%8,%9}, {%0,%1,%2,%3};"
        : "+f"(c[0]), "+f"(c[1]), "+f"(c[2]), "+f"(c[3])
        : "r"(a[0]), "r"(a[1]), "r"(a[2]), "r"(a[3]), "r"(b[0]), "r"(b[1]));
}
__device__ __forceinline__ void cp_async16(uint32_t dst, const void* src) {
    asm volatile("cp.async.cg.shared.global [%0], [%1], 16;" :: "r"(dst), "l"(src));
}
#define CP_COMMIT() asm volatile("cp.async.commit_group;" ::: "memory")
#define CP_WAIT1()  asm volatile("cp.async.wait_group 1;" ::: "memory")
#define CP_WAIT0()  asm volatile("cp.async.wait_group 0;" ::: "memory")

// ---------------------------------------------------------------------------
// x / z split: fp32 [M][K] -> hi/lo bf16 [M][K]
// ---------------------------------------------------------------------------
__global__ void split_kernel(const float* __restrict__ X,
                             __nv_bfloat16* __restrict__ Xh,
                             __nv_bfloat16* __restrict__ Xl, int n4)
{
    int i = blockIdx.x * blockDim.x + threadIdx.x;
    if (i >= n4) return;
    float4 v = reinterpret_cast<const float4*>(X)[i];
    __nv_bfloat16 h0 = __float2bfloat16(v.x), h1 = __float2bfloat16(v.y);
    __nv_bfloat16 h2 = __float2bfloat16(v.z), h3 = __float2bfloat16(v.w);
    __nv_bfloat162 ph0; ph0.x = h0; ph0.y = h1;
    __nv_bfloat162 ph1; ph1.x = h2; ph1.y = h3;
    __nv_bfloat162 pl0, pl1;
    pl0.x = __float2bfloat16(v.x - __bfloat162float(h0));
    pl0.y = __float2bfloat16(v.y - __bfloat162float(h1));
    pl1.x = __float2bfloat16(v.z - __bfloat162float(h2));
    pl1.y = __float2bfloat16(v.w - __bfloat162float(h3));
    reinterpret_cast<__nv_bfloat162*>(Xh)[i * 2]     = ph0;
    reinterpret_cast<__nv_bfloat162*>(Xh)[i * 2 + 1] = ph1;
    reinterpret_cast<__nv_bfloat162*>(Xl)[i * 2]     = pl0;
    reinterpret_cast<__nv_bfloat162*>(Xl)[i * 2 + 1] = pl1;
}

// ---------------------------------------------------------------------------
// Weight transpose + split: W[K][N] fp32 -> Th/Tl[N][K] bf16
// ---------------------------------------------------------------------------
__global__ void transpose_split_kernel(const float* __restrict__ W,
                                       __nv_bfloat16* __restrict__ Th,
                                       __nv_bfloat16* __restrict__ Tl,
                                       int K, int N)
{
    __shared__ float tile[32][33];
    const int n0 = blockIdx.x * 32, k0 = blockIdx.y * 32;
    const int tx = threadIdx.x, ty = threadIdx.y;  // 32 x 8
#pragma unroll
    for (int i = 0; i < 32; i += 8)
        tile[ty + i][tx] = W[(size_t)(k0 + ty + i) * N + n0 + tx];
    __syncthreads();
#pragma unroll
    for (int i = 0; i < 32; i += 8) {
        float v = tile[tx][ty + i];
        __nv_bfloat16 h = __float2bfloat16(v);
        __nv_bfloat16 l = __float2bfloat16(v - __bfloat162float(h));
        size_t o = (size_t)(n0 + ty + i) * K + k0 + tx;
        Th[o] = h;
        Tl[o] = l;
    }
}

// ---------------------------------------------------------------------------
// mma.sync split-bf16 GEMM: C[M,N] = A @ B^T + bias
// A given as Ah/Al [M][K] bf16; B given as Bh/Bl [N][K] bf16 (col-major frag).
// BM=BN=128, BK=32. 8 warps, warp tile 64x32. 2-stage cp.async pipeline.
// Smem rows padded to 80 B (5x16B -> (5r+c)%8 covers all ldmatrix banks).
// ---------------------------------------------------------------------------
static constexpr int TSTRIDE   = 80;                 // bytes per smem row
static constexpr int TILE_B    = 128 * TSTRIDE;      // 10240 B per tile
static constexpr int STAGE_B   = 4 * TILE_B;         // Ah,Al,Bh,Bl = 40960 B
static constexpr int GEMM_SMEM = 2 * STAGE_B;        // 81920 B

__global__ __launch_bounds__(256, 1)
void tc_gemm_kernel(const __nv_bfloat16* __restrict__ Ah,
                    const __nv_bfloat16* __restrict__ Al,
                    const __nv_bfloat16* __restrict__ Bh,
                    const __nv_bfloat16* __restrict__ Bl,
                    const float* __restrict__ bias,
                    float* __restrict__ C,
                    int M, int N, int K)
{
    extern __shared__ char smem[];
    const uint32_t sb = smem_to_u32(smem);
    const int t    = threadIdx.x;
    const int wid  = t >> 5;
    const int lane = t & 31;
    const int wm   = wid & 1;         // 0..1 (64 rows each)
    const int wn   = wid >> 1;        // 0..3 (32 cols each)
    const int bm   = blockIdx.y * 128;
    const int bn   = blockIdx.x * 128;

    // per-thread load mapping: 2 consecutive 16B chunks per tile
    const int ld_idx = t * 2;               // 0..510 of 512 chunks
    const int ld_r   = ld_idx >> 2;         // row 0..127
    const int ld_c   = (ld_idx & 3) * 16;   // byte col 0 or 32

    auto stage_load = [&](int s, int k0) {
        uint32_t dst0 = sb + s * STAGE_B + ld_r * TSTRIDE + ld_c;
        const char* a_src = (const char*)(Ah + (size_t)(bm + ld_r) * K + k0) + ld_c;
        const char* b_src;
        cp_async16(dst0,              a_src);
        cp_async16(dst0 + 16,         a_src + 16);
        a_src = (const char*)(Al + (size_t)(bm + ld_r) * K + k0) + ld_c;
        cp_async16(dst0 + TILE_B,     a_src);
        cp_async16(dst0 + TILE_B + 16, a_src + 16);
        b_src = (const char*)(Bh + (size_t)(bn + ld_r) * K + k0) + ld_c;
        cp_async16(dst0 + 2 * TILE_B,      b_src);
        cp_async16(dst0 + 2 * TILE_B + 16, b_src + 16);
        b_src = (const char*)(Bl + (size_t)(bn + ld_r) * K + k0) + ld_c;
        cp_async16(dst0 + 3 * TILE_B,      b_src);
        cp_async16(dst0 + 3 * TILE_B + 16, b_src + 16);
    };

    float acc[4][4][4];
#pragma unroll
    for (int i = 0; i < 4; i++)
#pragma unroll
        for (int j = 0; j < 4; j++)
#pragma unroll
            for (int k = 0; k < 4; k++) acc[i][j][k] = 0.0f;

    stage_load(0, 0);  CP_COMMIT();
    stage_load(1, 32); CP_COMMIT();

    // ldmatrix per-lane addressing
    const int sel  = lane >> 3;       // 0..3
    const int lrow = lane & 7;
    // A: sel0 rows0-7/k0-7, sel1 rows8-15/k0-7, sel2 rows0-7/k8-15, sel3 rows8-15/k8-15
    const int a_row_off = ((sel & 1) ? 8 : 0) + lrow;
    const int a_kc      = sel >> 1;
    // B: sel0 n0-7/k0-7, sel1 n0-7/k8-15, sel2 n8-15/k0-7, sel3 n8-15/k8-15
    const int b_row_off = ((sel >> 1) ? 8 : 0) + lrow;
    const int b_kc      = sel & 1;

    const int nch = K / 32;
    for (int ch = 0; ch < nch; ch++) {
        CP_WAIT1();
        __syncthreads();
        const uint32_t st = sb + (ch & 1) * STAGE_B;

#pragma unroll
        for (int ks = 0; ks < 2; ks++) {
            const uint32_t kbyte = (ks * 2) * 16;
            // A hi fragments: 4 m-tiles
            uint32_t afr[4][4];
#pragma unroll
            for (int mt = 0; mt < 4; mt++)
                ldsm_x4(afr[mt], st + (wm * 64 + mt * 16 + a_row_off) * TSTRIDE
                                    + kbyte + a_kc * 16);
            // B hi fragments: 2 ldmatrix.x4 = 4 n-tiles
            uint32_t bhfr[2][4];
#pragma unroll
            for (int p = 0; p < 2; p++)
                ldsm_x4(bhfr[p], st + 2 * TILE_B
                                    + (wn * 32 + p * 16 + b_row_off) * TSTRIDE
                                    + kbyte + b_kc * 16);
            // Ah * Bh
#pragma unroll
            for (int mt = 0; mt < 4; mt++)
#pragma unroll
                for (int nt = 0; nt < 4; nt++)
                    mma_bf16(acc[mt][nt], afr[mt], &bhfr[nt >> 1][(nt & 1) * 2]);
            // B lo fragments
            uint32_t blfr[2][4];
#pragma unroll
            for (int p = 0; p < 2; p++)
                ldsm_x4(blfr[p], st + 3 * TILE_B
                                    + (wn * 32 + p * 16 + b_row_off) * TSTRIDE
                                    + kbyte + b_kc * 16);
            // Ah * Bl
#pragma unroll
            for (int mt = 0; mt < 4; mt++)
#pragma unroll
                for (int nt = 0; nt < 4; nt++)
                    mma_bf16(acc[mt][nt], afr[mt], &blfr[nt >> 1][(nt & 1) * 2]);
            // A lo fragments (reuse afr)
#pragma unroll
            for (int mt = 0; mt < 4; mt++)
                ldsm_x4(afr[mt], st + TILE_B
                                    + (wm * 64 + mt * 16 + a_row_off) * TSTRIDE
                                    + kbyte + a_kc * 16);
            // Al * Bh
#pragma unroll
            for (int mt = 0; mt < 4; mt++)
#pragma unroll
                for (int nt = 0; nt < 4; nt++)
                    mma_bf16(acc[mt][nt], afr[mt], &bhfr[nt >> 1][(nt & 1) * 2]);
        }

        __syncthreads();
        if (ch + 2 < nch) stage_load((ch & 1), (ch + 2) * 32);
        CP_COMMIT();
    }
    CP_WAIT0();

    // Epilogue: c0=(g,t*2) c1=(g,t*2+1) c2=(g+8,t*2) c3=(g+8,t*2+1)
    const int g  = lane >> 2;
    const int tq = lane & 3;
#pragma unroll
    for (int mt = 0; mt < 4; mt++) {
#pragma unroll
        for (int nt = 0; nt < 4; nt++) {
            int row = bm + wm * 64 + mt * 16 + g;
            int col = bn + wn * 32 + nt * 8 + tq * 2;
            float b0 = bias[col], b1 = bias[col + 1];
            float2 v0 = make_float2(acc[mt][nt][0] + b0, acc[mt][nt][1] + b1);
            float2 v1 = make_float2(acc[mt][nt][2] + b0, acc[mt][nt][3] + b1);
            *reinterpret_cast<float2*>(C + (size_t)row * N + col)       = v0;
            *reinterpret_cast<float2*>(C + (size_t)(row + 8) * N + col) = v1;
        }
    }
}

// ---------------------------------------------------------------------------
// Flash-style attention (unchanged baseline)
// ---------------------------------------------------------------------------
#define SM_PITCH 65
__global__ __launch_bounds__(256)
void attn_kernel(const float* __restrict__ qkv, float* __restrict__ z)
{
    extern __shared__ float smemf[];
    float* Qs    = smemf;
    float* Ks    = Qs + 64 * SM_PITCH;
    float* Vs    = Ks + 64 * SM_PITCH;
    float* Ss    = Vs + 64 * SM_PITCH;
    float* row_m = Ss + 64 * SM_PITCH;
    float* row_l = row_m + 64;
    float* row_c = row_l + 64;

    const int t  = threadIdx.x;
    const int tx = t & 15;
    const int ty = t >> 4;
    const int bh = blockIdx.y;
    const int b  = bh / HEAD;
    const int h  = bh % HEAD;
    const int q0 = blockIdx.x * 64;

    const size_t tok_base = (size_t)b * SEQ;
    const int q_col = h * HEAD_DIM;
    const int k_col = MODEL_DIM + q_col;
    const int v_col = 2 * MODEL_DIM + q_col;

    for (int idx = t; idx < 64 * 64; idx += 256) {
        int r = idx >> 6, c = idx & 63;
        Qs[r * SM_PITCH + c] =
            qkv[(tok_base + q0 + r) * QKV_DIM + q_col + c] * 0.125f;
    }
    if (t < 64) { row_m[t] = -CUDART_INF_F; row_l[t] = 0.0f; }

    float acc[4][4];
#pragma unroll
    for (int i = 0; i < 4; i++)
#pragma unroll
        for (int j = 0; j < 4; j++) acc[i][j] = 0.0f;

    __syncthreads();

    for (int kt = 0; kt < SEQ / 64; kt++) {
        const int kk0 = kt * 64;
        for (int idx = t; idx < 64 * 64; idx += 256) {
            int r = idx >> 6, c = idx & 63;
            Ks[r * SM_PITCH + c] = qkv[(tok_base + kk0 + r) * QKV_DIM + k_col + c];
            Vs[r * SM_PITCH + c] = qkv[(tok_base + kk0 + r) * QKV_DIM + v_col + c];
        }
        __syncthreads();

        float s[4][4];
#pragma unroll
        for (int i = 0; i < 4; i++)
#pragma unroll
            for (int j = 0; j < 4; j++) s[i][j] = 0.0f;
#pragma unroll 8
        for (int d = 0; d < 64; d++) {
            float a[4], bb[4];
#pragma unroll
            for (int i = 0; i < 4; i++) a[i]  = Qs[(ty * 4 + i) * SM_PITCH + d];
#pragma unroll
            for (int j = 0; j < 4; j++) bb[j] = Ks[(tx * 4 + j) * SM_PITCH + d];
#pragma unroll
            for (int i = 0; i < 4; i++)
#pragma unroll
                for (int j = 0; j < 4; j++)
                    s[i][j] = fmaf(a[i], bb[j], s[i][j]);
        }
#pragma unroll
        for (int i = 0; i < 4; i++)
#pragma unroll
            for (int j = 0; j < 4; j++)
                Ss[(ty * 4 + i) * SM_PITCH + tx * 4 + j] = s[i][j];
        __syncthreads();

        if (t < 64) {
            float m_old = row_m[t];
            float m = m_old;
            float* srow = Ss + t * SM_PITCH;
#pragma unroll 8
            for (int c = 0; c < 64; c++) m = fmaxf(m, srow[c]);
            float corr = __expf(m_old - m);
            float l = row_l[t] * corr;
#pragma unroll 8
            for (int c = 0; c < 64; c++) {
                float p = __expf(srow[c] - m);
                srow[c] = p;
                l += p;
            }
            row_m[t] = m; row_l[t] = l; row_c[t] = corr;
        }
        __syncthreads();

        float ci[4];
#pragma unroll
        for (int i = 0; i < 4; i++) ci[i] = row_c[ty * 4 + i];
#pragma unroll
        for (int i = 0; i < 4; i++)
#pragma unroll
            for (int j = 0; j < 4; j++) acc[i][j] *= ci[i];

#pragma unroll 8
        for (int d = 0; d < 64; d++) {
            float p[4], v[4];
#pragma unroll
            for (int i = 0; i < 4; i++) p[i] = Ss[(ty * 4 + i) * SM_PITCH + d];
#pragma unroll
            for (int j = 0; j < 4; j++) v[j] = Vs[d * SM_PITCH + tx * 4 + j];
#pragma unroll
            for (int i = 0; i < 4; i++)
#pragma unroll
                for (int j = 0; j < 4; j++)
                    acc[i][j] = fmaf(p[i], v[j], acc[i][j]);
        }
        __syncthreads();
    }

    float inv_l[4];
#pragma unroll
    for (int i = 0; i < 4; i++) inv_l[i] = 1.0f / row_l[ty * 4 + i];
#pragma unroll
    for (int i = 0; i < 4; i++) {
        float* zrow = z + (tok_base + q0 + ty * 4 + i) * MODEL_DIM + q_col + tx * 4;
#pragma unroll
        for (int j = 0; j < 4; j++)
            zrow[j] = acc[i][j] * inv_l[i];
    }
}

// ---------------------------------------------------------------------------
// Launch
// ---------------------------------------------------------------------------
extern "C" void kernel_launch(void* const* d_in, const int* in_sizes, int n_in,
                              void* d_out, int out_size)
{
    const float* x     = (const float*)d_in[0];
    const float* w_qkv = (const float*)d_in[1];
    const float* b_qkv = (const float*)d_in[2];
    const float* w_out = (const float*)d_in[3];
    const float* b_out = (const float*)d_in[4];
    float* out = (float*)d_out;

    float *qkv_buf, *z_buf;
    __nv_bfloat16 *xh, *xl, *zh, *zl, *wqkvT_h, *wqkvT_l, *woutT_h, *woutT_l;
    cudaGetSymbolAddress((void**)&qkv_buf, g_qkv);
    cudaGetSymbolAddress((void**)&z_buf, g_z);
    cudaGetSymbolAddress((void**)&xh, g_xh);
    cudaGetSymbolAddress((void**)&xl, g_xl);
    cudaGetSymbolAddress((void**)&zh, g_zh);
    cudaGetSymbolAddress((void**)&zl, g_zl);
    cudaGetSymbolAddress((void**)&wqkvT_h, g_wqkvT_h);
    cudaGetSymbolAddress((void**)&wqkvT_l, g_wqkvT_l);
    cudaGetSymbolAddress((void**)&woutT_h, g_woutT_h);
    cudaGetSymbolAddress((void**)&woutT_l, g_woutT_l);

    cudaFuncSetAttribute(tc_gemm_kernel,
                         cudaFuncAttributeMaxDynamicSharedMemorySize, GEMM_SMEM);

    // 0. Preprocess: split x; transpose+split weights
    {
        int n4 = TOK * MODEL_DIM / 4;
        split_kernel<<<(n4 + 255) / 256, 256>>>(x, xh, xl, n4);
        transpose_split_kernel<<<dim3(QKV_DIM / 32, MODEL_DIM / 32), dim3(32, 8)>>>(
            w_qkv, wqkvT_h, wqkvT_l, MODEL_DIM, QKV_DIM);
        transpose_split_kernel<<<dim3(MODEL_DIM / 32, MODEL_DIM / 32), dim3(32, 8)>>>(
            w_out, woutT_h, woutT_l, MODEL_DIM, MODEL_DIM);
    }

    // 1. QKV projection (tensor cores, split bf16)
    tc_gemm_kernel<<<dim3(QKV_DIM / 128, TOK / 128), 256, GEMM_SMEM>>>(
        xh, xl, wqkvT_h, wqkvT_l, b_qkv, qkv_buf, TOK, QKV_DIM, MODEL_DIM);

    // 2. Attention
    {
        const int smem_bytes = (4 * 64 * SM_PITCH + 3 * 64) * (int)sizeof(float);
        cudaFuncSetAttribute(attn_kernel,
                             cudaFuncAttributeMaxDynamicSharedMemorySize, smem_bytes);
        attn_kernel<<<dim3(SEQ / 64, BATCH * HEAD), 256, smem_bytes>>>(qkv_buf, z_buf);
    }

    // 3. Split z, then output projection (tensor cores, split bf16)
    {
        int n4 = TOK * MODEL_DIM / 4;
        split_kernel<<<(n4 + 255) / 256, 256>>>(z_buf, zh, zl, n4);
    }
    tc_gemm_kernel<<<dim3(MODEL_DIM / 128, TOK / 128), 256, GEMM_SMEM>>>(
        zh, zl, woutT_h, woutT_l, b_out, out, TOK, MODEL_DIM, MODEL_DIM);
}

// round 6
// speedup vs baseline: 2.6168x; 2.0067x over previous
#include <cuda_runtime.h>
#include <cuda_bf16.h>
#include <math_constants.h>
#include <cstdint>

// Problem constants
static constexpr int MODEL_DIM = 1024;
static constexpr int HEAD      = 16;
static constexpr int HEAD_DIM  = 64;
static constexpr int BATCH     = 2;
static constexpr int SEQ       = 2048;
static constexpr int TOK       = BATCH * SEQ;      // 4096
static constexpr int QKV_DIM   = 3 * MODEL_DIM;    // 3072
static constexpr int BH        = BATCH * HEAD;     // 32

// Scratch (__device__ globals; no runtime allocation allowed)
__device__ float g_qkv[TOK * QKV_DIM];                    // [token][3*D] fp32
__device__ float g_z[TOK * MODEL_DIM];                    // attention out fp32
__device__ __nv_bfloat16 g_xh[TOK * MODEL_DIM];
__device__ __nv_bfloat16 g_xl[TOK * MODEL_DIM];
__device__ __nv_bfloat16 g_zh[TOK * MODEL_DIM];
__device__ __nv_bfloat16 g_zl[TOK * MODEL_DIM];
__device__ __nv_bfloat16 g_wqkvT_h[QKV_DIM * MODEL_DIM];
__device__ __nv_bfloat16 g_wqkvT_l[QKV_DIM * MODEL_DIM];
__device__ __nv_bfloat16 g_woutT_h[MODEL_DIM * MODEL_DIM];
__device__ __nv_bfloat16 g_woutT_l[MODEL_DIM * MODEL_DIM];
// Attention operands, split bf16. Q pre-scaled by 0.125.
__device__ __nv_bfloat16 g_qh[BH * SEQ * HEAD_DIM];   // [bh][s][d]
__device__ __nv_bfloat16 g_ql[BH * SEQ * HEAD_DIM];
__device__ __nv_bfloat16 g_kh[BH * SEQ * HEAD_DIM];   // [bh][s][d]
__device__ __nv_bfloat16 g_kl[BH * SEQ * HEAD_DIM];
__device__ __nv_bfloat16 g_vth[BH * HEAD_DIM * SEQ];  // [bh][d][s] (transposed)
__device__ __nv_bfloat16 g_vtl[BH * HEAD_DIM * SEQ];

// ---------------------------------------------------------------------------
// PTX helpers (sm_80-compatible)
// ---------------------------------------------------------------------------
__device__ __forceinline__ uint32_t smem_to_u32(const void* p) {
    uint32_t a;
    asm("{ .reg .u64 tmp; cvta.to.shared.u64 tmp, %1; cvt.u32.u64 %0, tmp; }"
        : "=r"(a) : "l"(p));
    return a;
}
__device__ __forceinline__ void ldsm_x4(uint32_t* r, uint32_t addr) {
    asm volatile("ldmatrix.sync.aligned.m8n8.x4.shared.b16 {%0,%1,%2,%3}, [%4];"
                 : "=r"(r[0]), "=r"(r[1]), "=r"(r[2]), "=r"(r[3]) : "r"(addr));
}
__device__ __forceinline__ void mma_bf16(float* c, const uint32_t* a, const uint32_t* b) {
    asm volatile(
        "mma.sync.aligned.m16n8k16.row.col.f32.bf16.bf16.f32 "
        "{%0,%1,%2,%3}, {%4,%5,%6,%7}, {%8,%9}, {%0,%1,%2,%3};"
        : "+f"(c[0]), "+f"(c[1]), "+f"(c[2]), "+f"(c[3])
        : "r"(a[0]), "r"(a[1]), "r"(a[2]), "r"(a[3]), "r"(b[0]), "r"(b[1]));
}
__device__ __forceinline__ void cp_async16(uint32_t dst, const void* src) {
    asm volatile("cp.async.cg.shared.global [%0], [%1], 16;" :: "r"(dst), "l"(src));
}
#define CP_COMMIT() asm volatile("cp.async.commit_group;" ::: "memory")
#define CP_WAIT1()  asm volatile("cp.async.wait_group 1;" ::: "memory")
#define CP_WAIT0()  asm volatile("cp.async.wait_group 0;" ::: "memory")
// pack two fp32 -> bf16x2 reg, lo in low half
__device__ __forceinline__ uint32_t pack_bf16x2(float lo, float hi) {
    uint32_t r;
    asm("cvt.rn.bf16x2.f32 %0, %1, %2;" : "=r"(r) : "f"(hi), "f"(lo));
    return r;
}

// ---------------------------------------------------------------------------
// x / z split: fp32 -> hi/lo bf16
// ---------------------------------------------------------------------------
__global__ void split_kernel(const float* __restrict__ X,
                             __nv_bfloat16* __restrict__ Xh,
                             __nv_bfloat16* __restrict__ Xl, int n4)
{
    int i = blockIdx.x * blockDim.x + threadIdx.x;
    if (i >= n4) return;
    float4 v = reinterpret_cast<const float4*>(X)[i];
    __nv_bfloat16 h0 = __float2bfloat16(v.x), h1 = __float2bfloat16(v.y);
    __nv_bfloat16 h2 = __float2bfloat16(v.z), h3 = __float2bfloat16(v.w);
    __nv_bfloat162 ph0; ph0.x = h0; ph0.y = h1;
    __nv_bfloat162 ph1; ph1.x = h2; ph1.y = h3;
    __nv_bfloat162 pl0, pl1;
    pl0.x = __float2bfloat16(v.x - __bfloat162float(h0));
    pl0.y = __float2bfloat16(v.y - __bfloat162float(h1));
    pl1.x = __float2bfloat16(v.z - __bfloat162float(h2));
    pl1.y = __float2bfloat16(v.w - __bfloat162float(h3));
    reinterpret_cast<__nv_bfloat162*>(Xh)[i * 2]     = ph0;
    reinterpret_cast<__nv_bfloat162*>(Xh)[i * 2 + 1] = ph1;
    reinterpret_cast<__nv_bfloat162*>(Xl)[i * 2]     = pl0;
    reinterpret_cast<__nv_bfloat162*>(Xl)[i * 2 + 1] = pl1;
}

// ---------------------------------------------------------------------------
// Weight transpose + split: W[K][N] fp32 -> Th/Tl[N][K] bf16
// ---------------------------------------------------------------------------
__global__ void transpose_split_kernel(const float* __restrict__ W,
                                       __nv_bfloat16* __restrict__ Th,
                                       __nv_bfloat16* __restrict__ Tl,
                                       int K, int N)
{
    __shared__ float tile[32][33];
    const int n0 = blockIdx.x * 32, k0 = blockIdx.y * 32;
    const int tx = threadIdx.x, ty = threadIdx.y;
#pragma unroll
    for (int i = 0; i < 32; i += 8)
        tile[ty + i][tx] = W[(size_t)(k0 + ty + i) * N + n0 + tx];
    __syncthreads();
#pragma unroll
    for (int i = 0; i < 32; i += 8) {
        float v = tile[tx][ty + i];
        __nv_bfloat16 h = __float2bfloat16(v);
        __nv_bfloat16 l = __float2bfloat16(v - __bfloat162float(h));
        size_t o = (size_t)(n0 + ty + i) * K + k0 + tx;
        Th[o] = h;
        Tl[o] = l;
    }
}

// ---------------------------------------------------------------------------
// QKV split pre-pass: g_qkv fp32 -> Q(hi/lo, x0.125), K(hi/lo), V^T(hi/lo)
// One block = 64 seq rows of one (b,h). 256 threads.
// ---------------------------------------------------------------------------
__global__ __launch_bounds__(256)
void split_qkv_kernel(const float* __restrict__ qkv)
{
    __shared__ float vs[64][65];
    const int t  = threadIdx.x;
    const int bh = blockIdx.y;
    const int b  = bh >> 4, h = bh & 15;
    const int s0 = blockIdx.x * 64;
    const size_t tokb = (size_t)b * SEQ + s0;

    for (int idx = t; idx < 64 * 64; idx += 256) {
        int r = idx >> 6, c = idx & 63;
        const float* row = qkv + (tokb + r) * QKV_DIM + h * HEAD_DIM + c;
        float qv = row[0] * 0.125f;
        float kv = row[MODEL_DIM];
        float vv = row[2 * MODEL_DIM];
        size_t o = ((size_t)bh * SEQ + s0 + r) * HEAD_DIM + c;
        __nv_bfloat16 qhh = __float2bfloat16(qv);
        g_qh[o] = qhh;
        g_ql[o] = __float2bfloat16(qv - __bfloat162float(qhh));
        __nv_bfloat16 khh = __float2bfloat16(kv);
        g_kh[o] = khh;
        g_kl[o] = __float2bfloat16(kv - __bfloat162float(khh));
        vs[r][c] = vv;
    }
    __syncthreads();
    for (int idx = t; idx < 64 * 64; idx += 256) {
        int d = idx >> 6, c = idx & 63;       // d = hd row, c = seq col
        float vv = vs[c][d];
        size_t o = ((size_t)bh * HEAD_DIM + d) * SEQ + s0 + c;
        __nv_bfloat16 vh = __float2bfloat16(vv);
        g_vth[o] = vh;
        g_vtl[o] = __float2bfloat16(vv - __bfloat162float(vh));
    }
}

// ---------------------------------------------------------------------------
// mma.sync split-bf16 GEMM (unchanged from R5, verified)
// ---------------------------------------------------------------------------
static constexpr int TSTRIDE   = 80;
static constexpr int TILE_B    = 128 * TSTRIDE;
static constexpr int STAGE_B   = 4 * TILE_B;
static constexpr int GEMM_SMEM = 2 * STAGE_B;

__global__ __launch_bounds__(256, 1)
void tc_gemm_kernel(const __nv_bfloat16* __restrict__ Ah,
                    const __nv_bfloat16* __restrict__ Al,
                    const __nv_bfloat16* __restrict__ Bh,
                    const __nv_bfloat16* __restrict__ Bl,
                    const float* __restrict__ bias,
                    float* __restrict__ C,
                    int M, int N, int K)
{
    extern __shared__ char smem[];
    const uint32_t sb = smem_to_u32(smem);
    const int t    = threadIdx.x;
    const int wid  = t >> 5;
    const int lane = t & 31;
    const int wm   = wid & 1;
    const int wn   = wid >> 1;
    const int bm   = blockIdx.y * 128;
    const int bn   = blockIdx.x * 128;

    const int ld_idx = t * 2;
    const int ld_r   = ld_idx >> 2;
    const int ld_c   = (ld_idx & 3) * 16;

    auto stage_load = [&](int s, int k0) {
        uint32_t dst0 = sb + s * STAGE_B + ld_r * TSTRIDE + ld_c;
        const char* a_src = (const char*)(Ah + (size_t)(bm + ld_r) * K + k0) + ld_c;
        const char* b_src;
        cp_async16(dst0,              a_src);
        cp_async16(dst0 + 16,         a_src + 16);
        a_src = (const char*)(Al + (size_t)(bm + ld_r) * K + k0) + ld_c;
        cp_async16(dst0 + TILE_B,     a_src);
        cp_async16(dst0 + TILE_B + 16, a_src + 16);
        b_src = (const char*)(Bh + (size_t)(bn + ld_r) * K + k0) + ld_c;
        cp_async16(dst0 + 2 * TILE_B,      b_src);
        cp_async16(dst0 + 2 * TILE_B + 16, b_src + 16);
        b_src = (const char*)(Bl + (size_t)(bn + ld_r) * K + k0) + ld_c;
        cp_async16(dst0 + 3 * TILE_B,      b_src);
        cp_async16(dst0 + 3 * TILE_B + 16, b_src + 16);
    };

    float acc[4][4][4];
#pragma unroll
    for (int i = 0; i < 4; i++)
#pragma unroll
        for (int j = 0; j < 4; j++)
#pragma unroll
            for (int k = 0; k < 4; k++) acc[i][j][k] = 0.0f;

    stage_load(0, 0);  CP_COMMIT();
    stage_load(1, 32); CP_COMMIT();

    const int sel  = lane >> 3;
    const int lrow = lane & 7;
    const int a_row_off = ((sel & 1) ? 8 : 0) + lrow;
    const int a_kc      = sel >> 1;
    const int b_row_off = ((sel >> 1) ? 8 : 0) + lrow;
    const int b_kc      = sel & 1;

    const int nch = K / 32;
    for (int ch = 0; ch < nch; ch++) {
        CP_WAIT1();
        __syncthreads();
        const uint32_t st = sb + (ch & 1) * STAGE_B;

#pragma unroll
        for (int ks = 0; ks < 2; ks++) {
            const uint32_t kbyte = (ks * 2) * 16;
            uint32_t afr[4][4];
#pragma unroll
            for (int mt = 0; mt < 4; mt++)
                ldsm_x4(afr[mt], st + (wm * 64 + mt * 16 + a_row_off) * TSTRIDE
                                    + kbyte + a_kc * 16);
            uint32_t bhfr[2][4];
#pragma unroll
            for (int p = 0; p < 2; p++)
                ldsm_x4(bhfr[p], st + 2 * TILE_B
                                    + (wn * 32 + p * 16 + b_row_off) * TSTRIDE
                                    + kbyte + b_kc * 16);
#pragma unroll
            for (int mt = 0; mt < 4; mt++)
#pragma unroll
                for (int nt = 0; nt < 4; nt++)
                    mma_bf16(acc[mt][nt], afr[mt], &bhfr[nt >> 1][(nt & 1) * 2]);
            uint32_t blfr[2][4];
#pragma unroll
            for (int p = 0; p < 2; p++)
                ldsm_x4(blfr[p], st + 3 * TILE_B
                                    + (wn * 32 + p * 16 + b_row_off) * TSTRIDE
                                    + kbyte + b_kc * 16);
#pragma unroll
            for (int mt = 0; mt < 4; mt++)
#pragma unroll
                for (int nt = 0; nt < 4; nt++)
                    mma_bf16(acc[mt][nt], afr[mt], &blfr[nt >> 1][(nt & 1) * 2]);
#pragma unroll
            for (int mt = 0; mt < 4; mt++)
                ldsm_x4(afr[mt], st + TILE_B
                                    + (wm * 64 + mt * 16 + a_row_off) * TSTRIDE
                                    + kbyte + a_kc * 16);
#pragma unroll
            for (int mt = 0; mt < 4; mt++)
#pragma unroll
                for (int nt = 0; nt < 4; nt++)
                    mma_bf16(acc[mt][nt], afr[mt], &bhfr[nt >> 1][(nt & 1) * 2]);
        }

        __syncthreads();
        if (ch + 2 < nch) stage_load((ch & 1), (ch + 2) * 32);
        CP_COMMIT();
    }
    CP_WAIT0();

    const int g  = lane >> 2;
    const int tq = lane & 3;
#pragma unroll
    for (int mt = 0; mt < 4; mt++) {
#pragma unroll
        for (int nt = 0; nt < 4; nt++) {
            int row = bm + wm * 64 + mt * 16 + g;
            int col = bn + wn * 32 + nt * 8 + tq * 2;
            float b0 = bias[col], b1 = bias[col + 1];
            float2 v0 = make_float2(acc[mt][nt][0] + b0, acc[mt][nt][1] + b1);
            float2 v1 = make_float2(acc[mt][nt][2] + b0, acc[mt][nt][3] + b1);
            *reinterpret_cast<float2*>(C + (size_t)row * N + col)       = v0;
            *reinterpret_cast<float2*>(C + (size_t)(row + 8) * N + col) = v1;
        }
    }
}

// ---------------------------------------------------------------------------
// Tensor-core flash attention. Block = 128 q rows of one (b,h); 8 warps x 16 rows.
// Bk=64. 2-stage cp.async pipeline. Split bf16, 3 mma passes for QK^T and P@V.
// Smem rows 144B (9x16B): 4-bank rotation/row -> conflict-free ldmatrix.
// ---------------------------------------------------------------------------
static constexpr int AT_STRIDE = 144;
static constexpr int AT_TILE   = 64 * AT_STRIDE;   // 9216
static constexpr int AT_STAGE  = 4 * AT_TILE;      // Kh,Kl,Vh,Vl = 36864
static constexpr int AT_SMEM   = 2 * AT_STAGE;     // 73728

__global__ __launch_bounds__(256, 1)
void attn_tc_kernel(float* __restrict__ z)
{
    extern __shared__ char smem[];
    const uint32_t sb = smem_to_u32(smem);
    const int t    = threadIdx.x;
    const int wid  = t >> 5;
    const int lane = t & 31;
    const int g    = lane >> 2;
    const int tq   = lane & 3;
    const int bh   = blockIdx.y;
    const int q0   = blockIdx.x * 128;
    const int wrow = wid * 16;

    const int sel  = lane >> 3;
    const int lrow = lane & 7;
    const int b_row_off = ((sel >> 1) ? 8 : 0) + lrow;
    const int b_kc      = sel & 1;

    // Q fragments (persistent in registers)
    uint32_t qhf[4][4], qlf[4][4];
    {
        const size_t r0 = ((size_t)bh * SEQ + q0 + wrow + g) * HEAD_DIM;
        const size_t r1 = r0 + 8 * HEAD_DIM;
#pragma unroll
        for (int ks = 0; ks < 4; ks++) {
            int c0 = ks * 16 + tq * 2, c1 = c0 + 8;
            qhf[ks][0] = *reinterpret_cast<const uint32_t*>(g_qh + r0 + c0);
            qhf[ks][1] = *reinterpret_cast<const uint32_t*>(g_qh + r1 + c0);
            qhf[ks][2] = *reinterpret_cast<const uint32_t*>(g_qh + r0 + c1);
            qhf[ks][3] = *reinterpret_cast<const uint32_t*>(g_qh + r1 + c1);
            qlf[ks][0] = *reinterpret_cast<const uint32_t*>(g_ql + r0 + c0);
            qlf[ks][1] = *reinterpret_cast<const uint32_t*>(g_ql + r1 + c0);
            qlf[ks][2] = *reinterpret_cast<const uint32_t*>(g_ql + r0 + c1);
            qlf[ks][3] = *reinterpret_cast<const uint32_t*>(g_ql + r1 + c1);
        }
    }

    // Tile loader: 2048 x 16B chunks (Kh,Kl: [s][d] rows; Vh,Vl: [d][s] rows)
    auto load_stage = [&](int s, int kk0) {
        const char* baseK  = (const char*)(g_kh + ((size_t)bh * SEQ + kk0) * HEAD_DIM);
        const char* baseKl = (const char*)(g_kl + ((size_t)bh * SEQ + kk0) * HEAD_DIM);
        const char* baseV  = (const char*)(g_vth + (size_t)bh * HEAD_DIM * SEQ + kk0);
        const char* baseVl = (const char*)(g_vtl + (size_t)bh * HEAD_DIM * SEQ + kk0);
#pragma unroll
        for (int i = 0; i < 8; i++) {
            int idx = t + i * 256;           // 0..2047
            int tensor = idx >> 9;           // 0..3
            int rem = idx & 511;
            int r = rem >> 3;                // 0..63
            int c16 = (rem & 7) * 16;        // byte col within 128B row
            const char* src;
            if (tensor == 0)      src = baseK  + (size_t)r * 128 + c16;
            else if (tensor == 1) src = baseKl + (size_t)r * 128 + c16;
            else if (tensor == 2) src = baseV  + (size_t)r * (SEQ * 2) + c16;
            else                  src = baseVl + (size_t)r * (SEQ * 2) + c16;
            cp_async16(sb + s * AT_STAGE + tensor * AT_TILE + r * AT_STRIDE + c16, src);
        }
    };

    float o[8][4];
#pragma unroll
    for (int i = 0; i < 8; i++)
#pragma unroll
        for (int j = 0; j < 4; j++) o[i][j] = 0.0f;
    float m0 = -CUDART_INF_F, m1 = -CUDART_INF_F, l0 = 0.0f, l1 = 0.0f;

    load_stage(0, 0);  CP_COMMIT();
    load_stage(1, 64); CP_COMMIT();

    const int nkt = SEQ / 64;
    for (int kt = 0; kt < nkt; kt++) {
        CP_WAIT1();
        __syncthreads();
        const uint32_t st = sb + (kt & 1) * AT_STAGE;

        // ---- S = Q K^T (3 passes) ----
        float s[8][4];
#pragma unroll
        for (int i = 0; i < 8; i++)
#pragma unroll
            for (int j = 0; j < 4; j++) s[i][j] = 0.0f;
#pragma unroll
        for (int ks = 0; ks < 4; ks++) {        // hd chunks of 16
            const uint32_t kbyte = ks * 32 + b_kc * 16;
#pragma unroll
            for (int ng = 0; ng < 4; ng++) {    // key groups of 16
                uint32_t kf[4];
                ldsm_x4(kf, st + (ng * 16 + b_row_off) * AT_STRIDE + kbyte);
                mma_bf16(s[ng * 2],     qhf[ks], &kf[0]);
                mma_bf16(s[ng * 2 + 1], qhf[ks], &kf[2]);
                mma_bf16(s[ng * 2],     qlf[ks], &kf[0]);
                mma_bf16(s[ng * 2 + 1], qlf[ks], &kf[2]);
                uint32_t klf[4];
                ldsm_x4(klf, st + AT_TILE + (ng * 16 + b_row_off) * AT_STRIDE + kbyte);
                mma_bf16(s[ng * 2],     qhf[ks], &klf[0]);
                mma_bf16(s[ng * 2 + 1], qhf[ks], &klf[2]);
            }
        }

        // ---- online softmax (rows g and g+8) ----
        float mt0 = -CUDART_INF_F, mt1 = -CUDART_INF_F;
#pragma unroll
        for (int nt = 0; nt < 8; nt++) {
            mt0 = fmaxf(mt0, fmaxf(s[nt][0], s[nt][1]));
            mt1 = fmaxf(mt1, fmaxf(s[nt][2], s[nt][3]));
        }
        mt0 = fmaxf(mt0, __shfl_xor_sync(0xFFFFFFFF, mt0, 1));
        mt0 = fmaxf(mt0, __shfl_xor_sync(0xFFFFFFFF, mt0, 2));
        mt1 = fmaxf(mt1, __shfl_xor_sync(0xFFFFFFFF, mt1, 1));
        mt1 = fmaxf(mt1, __shfl_xor_sync(0xFFFFFFFF, mt1, 2));
        float mn0 = fmaxf(m0, mt0), mn1 = fmaxf(m1, mt1);
        float c0 = __expf(m0 - mn0), c1 = __expf(m1 - mn1);
        m0 = mn0; m1 = mn1;
        float ls0 = 0.0f, ls1 = 0.0f;
#pragma unroll
        for (int nt = 0; nt < 8; nt++) {
            s[nt][0] = __expf(s[nt][0] - m0);
            s[nt][1] = __expf(s[nt][1] - m0);
            s[nt][2] = __expf(s[nt][2] - m1);
            s[nt][3] = __expf(s[nt][3] - m1);
            ls0 += s[nt][0] + s[nt][1];
            ls1 += s[nt][2] + s[nt][3];
        }
        l0 = l0 * c0 + ls0;
        l1 = l1 * c1 + ls1;
#pragma unroll
        for (int nt = 0; nt < 8; nt++) {
            o[nt][0] *= c0; o[nt][1] *= c0;
            o[nt][2] *= c1; o[nt][3] *= c1;
        }

        // ---- O += P V (3 passes) ----
#pragma unroll
        for (int ks = 0; ks < 4; ks++) {        // seq chunks of 16 = S tiles 2ks,2ks+1
            uint32_t pah[4], pal[4];
#pragma unroll
            for (int half = 0; half < 2; half++) {
                const float* sp = s[2 * ks + half];
                float h0 = __bfloat162float(__float2bfloat16(sp[0]));
                float h1 = __bfloat162float(__float2bfloat16(sp[1]));
                float h2 = __bfloat162float(__float2bfloat16(sp[2]));
                float h3 = __bfloat162float(__float2bfloat16(sp[3]));
                pah[half * 2]     = pack_bf16x2(sp[0], sp[1]);
                pah[half * 2 + 1] = pack_bf16x2(sp[2], sp[3]);
                pal[half * 2]     = pack_bf16x2(sp[0] - h0, sp[1] - h1);
                pal[half * 2 + 1] = pack_bf16x2(sp[2] - h2, sp[3] - h3);
            }
            // pah = {a0=(g,k0-7 of tile2ks), a1=(g+8,..), a2/a3 = tile2ks+1} -> reorder:
            uint32_t pa_h[4] = {pah[0], pah[1], pah[2], pah[3]};
            uint32_t pa_l[4] = {pal[0], pal[1], pal[2], pal[3]};
            const uint32_t kbyte = ks * 32 + b_kc * 16;
#pragma unroll
            for (int ng = 0; ng < 4; ng++) {    // hd groups of 16
                uint32_t vf[4];
                ldsm_x4(vf, st + 2 * AT_TILE + (ng * 16 + b_row_off) * AT_STRIDE + kbyte);
                mma_bf16(o[ng * 2],     pa_h, &vf[0]);
                mma_bf16(o[ng * 2 + 1], pa_h, &vf[2]);
                mma_bf16(o[ng * 2],     pa_l, &vf[0]);
                mma_bf16(o[ng * 2 + 1], pa_l, &vf[2]);
                uint32_t vlf[4];
                ldsm_x4(vlf, st + 3 * AT_TILE + (ng * 16 + b_row_off) * AT_STRIDE + kbyte);
                mma_bf16(o[ng * 2],     pa_h, &vlf[0]);
                mma_bf16(o[ng * 2 + 1], pa_h, &vlf[2]);
            }
        }

        __syncthreads();
        if (kt + 2 < nkt) load_stage(kt & 1, (kt + 2) * 64);
        CP_COMMIT();
    }
    CP_WAIT0();

    // ---- finalize ----
    l0 += __shfl_xor_sync(0xFFFFFFFF, l0, 1);
    l0 += __shfl_xor_sync(0xFFFFFFFF, l0, 2);
    l1 += __shfl_xor_sync(0xFFFFFFFF, l1, 1);
    l1 += __shfl_xor_sync(0xFFFFFFFF, l1, 2);
    float inv0 = 1.0f / l0, inv1 = 1.0f / l1;

    const int b = bh >> 4, h = bh & 15;
    const size_t tok0 = (size_t)b * SEQ + q0 + wrow + g;
#pragma unroll
    for (int nt = 0; nt < 8; nt++) {
        int col = h * HEAD_DIM + nt * 8 + tq * 2;
        float2 v0 = make_float2(o[nt][0] * inv0, o[nt][1] * inv0);
        float2 v1 = make_float2(o[nt][2] * inv1, o[nt][3] * inv1);
        *reinterpret_cast<float2*>(z + tok0 * MODEL_DIM + col)       = v0;
        *reinterpret_cast<float2*>(z + (tok0 + 8) * MODEL_DIM + col) = v1;
    }
}

// ---------------------------------------------------------------------------
// Launch
// ---------------------------------------------------------------------------
extern "C" void kernel_launch(void* const* d_in, const int* in_sizes, int n_in,
                              void* d_out, int out_size)
{
    const float* x     = (const float*)d_in[0];
    const float* w_qkv = (const float*)d_in[1];
    const float* b_qkv = (const float*)d_in[2];
    const float* w_out = (const float*)d_in[3];
    const float* b_out = (const float*)d_in[4];
    float* out = (float*)d_out;

    float *qkv_buf, *z_buf;
    __nv_bfloat16 *xh, *xl, *zh, *zl, *wqkvT_h, *wqkvT_l, *woutT_h, *woutT_l;
    cudaGetSymbolAddress((void**)&qkv_buf, g_qkv);
    cudaGetSymbolAddress((void**)&z_buf, g_z);
    cudaGetSymbolAddress((void**)&xh, g_xh);
    cudaGetSymbolAddress((void**)&xl, g_xl);
    cudaGetSymbolAddress((void**)&zh, g_zh);
    cudaGetSymbolAddress((void**)&zl, g_zl);
    cudaGetSymbolAddress((void**)&wqkvT_h, g_wqkvT_h);
    cudaGetSymbolAddress((void**)&wqkvT_l, g_wqkvT_l);
    cudaGetSymbolAddress((void**)&woutT_h, g_woutT_h);
    cudaGetSymbolAddress((void**)&woutT_l, g_woutT_l);

    cudaFuncSetAttribute(tc_gemm_kernel,
                         cudaFuncAttributeMaxDynamicSharedMemorySize, GEMM_SMEM);
    cudaFuncSetAttribute(attn_tc_kernel,
                         cudaFuncAttributeMaxDynamicSharedMemorySize, AT_SMEM);

    // 0. Preprocess: split x; transpose+split weights
    {
        int n4 = TOK * MODEL_DIM / 4;
        split_kernel<<<(n4 + 255) / 256, 256>>>(x, xh, xl, n4);
        transpose_split_kernel<<<dim3(QKV_DIM / 32, MODEL_DIM / 32), dim3(32, 8)>>>(
            w_qkv, wqkvT_h, wqkvT_l, MODEL_DIM, QKV_DIM);
        transpose_split_kernel<<<dim3(MODEL_DIM / 32, MODEL_DIM / 32), dim3(32, 8)>>>(
            w_out, woutT_h, woutT_l, MODEL_DIM, MODEL_DIM);
    }

    // 1. QKV projection (tensor cores)
    tc_gemm_kernel<<<dim3(QKV_DIM / 128, TOK / 128), 256, GEMM_SMEM>>>(
        xh, xl, wqkvT_h, wqkvT_l, b_qkv, qkv_buf, TOK, QKV_DIM, MODEL_DIM);

    // 2. Split qkv into attention operand layouts
    split_qkv_kernel<<<dim3(SEQ / 64, BH), 256>>>(qkv_buf);

    // 3. Tensor-core flash attention
    attn_tc_kernel<<<dim3(SEQ / 128, BH), 256, AT_SMEM>>>(z_buf);

    // 4. Split z, then output projection (tensor cores)
    {
        int n4 = TOK * MODEL_DIM / 4;
        split_kernel<<<(n4 + 255) / 256, 256>>>(z_buf, zh, zl, n4);
    }
    tc_gemm_kernel<<<dim3(MODEL_DIM / 128, TOK / 128), 256, GEMM_SMEM>>>(
        zh, zl, woutT_h, woutT_l, b_out, out, TOK, MODEL_DIM, MODEL_DIM);
}

// round 7
// speedup vs baseline: 2.6786x; 1.0236x over previous
#include <cuda_runtime.h>
#include <cuda_bf16.h>
#include <math_constants.h>
#include <cstdint>

// Problem constants
static constexpr int MODEL_DIM = 1024;
static constexpr int HEAD      = 16;
static constexpr int HEAD_DIM  = 64;
static constexpr int BATCH     = 2;
static constexpr int SEQ       = 2048;
static constexpr int TOK       = BATCH * SEQ;      // 4096
static constexpr int QKV_DIM   = 3 * MODEL_DIM;    // 3072
static constexpr int BH        = BATCH * HEAD;     // 32

// Scratch (__device__ globals; no runtime allocation allowed)
__device__ float g_qkv[TOK * QKV_DIM];                    // [token][3*D] fp32
__device__ __nv_bfloat16 g_xh[TOK * MODEL_DIM];
__device__ __nv_bfloat16 g_xl[TOK * MODEL_DIM];
__device__ __nv_bfloat16 g_zh[TOK * MODEL_DIM];
__device__ __nv_bfloat16 g_zl[TOK * MODEL_DIM];
__device__ __nv_bfloat16 g_wqkvT_h[QKV_DIM * MODEL_DIM];
__device__ __nv_bfloat16 g_wqkvT_l[QKV_DIM * MODEL_DIM];
__device__ __nv_bfloat16 g_woutT_h[MODEL_DIM * MODEL_DIM];
__device__ __nv_bfloat16 g_woutT_l[MODEL_DIM * MODEL_DIM];
// Attention operands, split bf16. Q pre-scaled by 0.125.
__device__ __nv_bfloat16 g_qh[BH * SEQ * HEAD_DIM];   // [bh][s][d]
__device__ __nv_bfloat16 g_ql[BH * SEQ * HEAD_DIM];
__device__ __nv_bfloat16 g_kh[BH * SEQ * HEAD_DIM];   // [bh][s][d]
__device__ __nv_bfloat16 g_kl[BH * SEQ * HEAD_DIM];
__device__ __nv_bfloat16 g_vth[BH * HEAD_DIM * SEQ];  // [bh][d][s] (transposed)
__device__ __nv_bfloat16 g_vtl[BH * HEAD_DIM * SEQ];

// ---------------------------------------------------------------------------
// PTX helpers (sm_80-compatible)
// ---------------------------------------------------------------------------
__device__ __forceinline__ uint32_t smem_to_u32(const void* p) {
    uint32_t a;
    asm("{ .reg .u64 tmp; cvta.to.shared.u64 tmp, %1; cvt.u32.u64 %0, tmp; }"
        : "=r"(a) : "l"(p));
    return a;
}
__device__ __forceinline__ void ldsm_x4(uint32_t* r, uint32_t addr) {
    asm volatile("ldmatrix.sync.aligned.m8n8.x4.shared.b16 {%0,%1,%2,%3}, [%4];"
                 : "=r"(r[0]), "=r"(r[1]), "=r"(r[2]), "=r"(r[3]) : "r"(addr));
}
__device__ __forceinline__ void mma_bf16(float* c, const uint32_t* a, const uint32_t* b) {
    asm volatile(
        "mma.sync.aligned.m16n8k16.row.col.f32.bf16.bf16.f32 "
        "{%0,%1,%2,%3}, {%4,%5,%6,%7}, {%8,%9}, {%0,%1,%2,%3};"
        : "+f"(c[0]), "+f"(c[1]), "+f"(c[2]), "+f"(c[3])
        : "r"(a[0]), "r"(a[1]), "r"(a[2]), "r"(a[3]), "r"(b[0]), "r"(b[1]));
}
__device__ __forceinline__ void cp_async16(uint32_t dst, const void* src) {
    asm volatile("cp.async.cg.shared.global [%0], [%1], 16;" :: "r"(dst), "l"(src));
}
#define CP_COMMIT() asm volatile("cp.async.commit_group;" ::: "memory")
#define CP_WAIT1()  asm volatile("cp.async.wait_group 1;" ::: "memory")
#define CP_WAIT0()  asm volatile("cp.async.wait_group 0;" ::: "memory")
__device__ __forceinline__ uint32_t pack_bf16x2(float lo, float hi) {
    uint32_t r;
    asm("cvt.rn.bf16x2.f32 %0, %1, %2;" : "=r"(r) : "f"(hi), "f"(lo));
    return r;
}

// ---------------------------------------------------------------------------
// x split: fp32 -> hi/lo bf16
// ---------------------------------------------------------------------------
__global__ void split_kernel(const float* __restrict__ X,
                             __nv_bfloat16* __restrict__ Xh,
                             __nv_bfloat16* __restrict__ Xl, int n4)
{
    int i = blockIdx.x * blockDim.x + threadIdx.x;
    if (i >= n4) return;
    float4 v = reinterpret_cast<const float4*>(X)[i];
    __nv_bfloat16 h0 = __float2bfloat16(v.x), h1 = __float2bfloat16(v.y);
    __nv_bfloat16 h2 = __float2bfloat16(v.z), h3 = __float2bfloat16(v.w);
    __nv_bfloat162 ph0; ph0.x = h0; ph0.y = h1;
    __nv_bfloat162 ph1; ph1.x = h2; ph1.y = h3;
    __nv_bfloat162 pl0, pl1;
    pl0.x = __float2bfloat16(v.x - __bfloat162float(h0));
    pl0.y = __float2bfloat16(v.y - __bfloat162float(h1));
    pl1.x = __float2bfloat16(v.z - __bfloat162float(h2));
    pl1.y = __float2bfloat16(v.w - __bfloat162float(h3));
    reinterpret_cast<__nv_bfloat162*>(Xh)[i * 2]     = ph0;
    reinterpret_cast<__nv_bfloat162*>(Xh)[i * 2 + 1] = ph1;
    reinterpret_cast<__nv_bfloat162*>(Xl)[i * 2]     = pl0;
    reinterpret_cast<__nv_bfloat162*>(Xl)[i * 2 + 1] = pl1;
}

// ---------------------------------------------------------------------------
// Weight transpose + split: W[K][N] fp32 -> Th/Tl[N][K] bf16
// ---------------------------------------------------------------------------
__global__ void transpose_split_kernel(const float* __restrict__ W,
                                       __nv_bfloat16* __restrict__ Th,
                                       __nv_bfloat16* __restrict__ Tl,
                                       int K, int N)
{
    __shared__ float tile[32][33];
    const int n0 = blockIdx.x * 32, k0 = blockIdx.y * 32;
    const int tx = threadIdx.x, ty = threadIdx.y;
#pragma unroll
    for (int i = 0; i < 32; i += 8)
        tile[ty + i][tx] = W[(size_t)(k0 + ty + i) * N + n0 + tx];
    __syncthreads();
#pragma unroll
    for (int i = 0; i < 32; i += 8) {
        float v = tile[tx][ty + i];
        __nv_bfloat16 h = __float2bfloat16(v);
        __nv_bfloat16 l = __float2bfloat16(v - __bfloat162float(h));
        size_t o = (size_t)(n0 + ty + i) * K + k0 + tx;
        Th[o] = h;
        Tl[o] = l;
    }
}

// ---------------------------------------------------------------------------
// QKV split pre-pass: g_qkv fp32 -> Q(hi/lo, x0.125), K(hi/lo), V^T(hi/lo)
// ---------------------------------------------------------------------------
__global__ __launch_bounds__(256)
void split_qkv_kernel(const float* __restrict__ qkv)
{
    __shared__ float vs[64][65];
    const int t  = threadIdx.x;
    const int bh = blockIdx.y;
    const int b  = bh >> 4, h = bh & 15;
    const int s0 = blockIdx.x * 64;
    const size_t tokb = (size_t)b * SEQ + s0;

    for (int idx = t; idx < 64 * 64; idx += 256) {
        int r = idx >> 6, c = idx & 63;
        const float* row = qkv + (tokb + r) * QKV_DIM + h * HEAD_DIM + c;
        float qv = row[0] * 0.125f;
        float kv = row[MODEL_DIM];
        float vv = row[2 * MODEL_DIM];
        size_t o = ((size_t)bh * SEQ + s0 + r) * HEAD_DIM + c;
        __nv_bfloat16 qhh = __float2bfloat16(qv);
        g_qh[o] = qhh;
        g_ql[o] = __float2bfloat16(qv - __bfloat162float(qhh));
        __nv_bfloat16 khh = __float2bfloat16(kv);
        g_kh[o] = khh;
        g_kl[o] = __float2bfloat16(kv - __bfloat162float(khh));
        vs[r][c] = vv;
    }
    __syncthreads();
    for (int idx = t; idx < 64 * 64; idx += 256) {
        int d = idx >> 6, c = idx & 63;
        float vv = vs[c][d];
        size_t o = ((size_t)bh * HEAD_DIM + d) * SEQ + s0 + c;
        __nv_bfloat16 vh = __float2bfloat16(vv);
        g_vth[o] = vh;
        g_vtl[o] = __float2bfloat16(vv - __bfloat162float(vh));
    }
}

// ---------------------------------------------------------------------------
// mma.sync split-bf16 GEMM. 3-stage cp.async pipeline, hoisted ldsm bursts.
// ---------------------------------------------------------------------------
static constexpr int TSTRIDE   = 80;
static constexpr int TILE_B    = 128 * TSTRIDE;      // 10240
static constexpr int STAGE_B   = 4 * TILE_B;         // 40960
static constexpr int GEMM_SMEM = 3 * STAGE_B;        // 122880

__global__ __launch_bounds__(256, 1)
void tc_gemm_kernel(const __nv_bfloat16* __restrict__ Ah,
                    const __nv_bfloat16* __restrict__ Al,
                    const __nv_bfloat16* __restrict__ Bh,
                    const __nv_bfloat16* __restrict__ Bl,
                    const float* __restrict__ bias,
                    float* __restrict__ C,
                    int M, int N, int K)
{
    extern __shared__ char smem[];
    const uint32_t sb = smem_to_u32(smem);
    const int t    = threadIdx.x;
    const int wid  = t >> 5;
    const int lane = t & 31;
    const int wm   = wid & 1;
    const int wn   = wid >> 1;
    const int bm   = blockIdx.y * 128;
    const int bn   = blockIdx.x * 128;

    const int ld_idx = t * 2;
    const int ld_r   = ld_idx >> 2;
    const int ld_c   = (ld_idx & 3) * 16;

    auto stage_load = [&](int s, int k0) {
        uint32_t dst0 = sb + s * STAGE_B + ld_r * TSTRIDE + ld_c;
        const char* a_src = (const char*)(Ah + (size_t)(bm + ld_r) * K + k0) + ld_c;
        const char* b_src;
        cp_async16(dst0,               a_src);
        cp_async16(dst0 + 16,          a_src + 16);
        a_src = (const char*)(Al + (size_t)(bm + ld_r) * K + k0) + ld_c;
        cp_async16(dst0 + TILE_B,      a_src);
        cp_async16(dst0 + TILE_B + 16, a_src + 16);
        b_src = (const char*)(Bh + (size_t)(bn + ld_r) * K + k0) + ld_c;
        cp_async16(dst0 + 2 * TILE_B,      b_src);
        cp_async16(dst0 + 2 * TILE_B + 16, b_src + 16);
        b_src = (const char*)(Bl + (size_t)(bn + ld_r) * K + k0) + ld_c;
        cp_async16(dst0 + 3 * TILE_B,      b_src);
        cp_async16(dst0 + 3 * TILE_B + 16, b_src + 16);
    };

    float acc[4][4][4];
#pragma unroll
    for (int i = 0; i < 4; i++)
#pragma unroll
        for (int j = 0; j < 4; j++)
#pragma unroll
            for (int k = 0; k < 4; k++) acc[i][j][k] = 0.0f;

    stage_load(0, 0);  CP_COMMIT();
    stage_load(1, 32); CP_COMMIT();

    const int sel  = lane >> 3;
    const int lrow = lane & 7;
    const int a_row_off = ((sel & 1) ? 8 : 0) + lrow;
    const int a_kc      = sel >> 1;
    const int b_row_off = ((sel >> 1) ? 8 : 0) + lrow;
    const int b_kc      = sel & 1;

    const int nch = K / 32;
    for (int ch = 0; ch < nch; ch++) {
        CP_WAIT1();
        __syncthreads();
        // early prefetch of chunk ch+2 into stage just freed at ch-1
        if (ch + 2 < nch) stage_load((ch + 2) % 3, (ch + 2) * 32);
        CP_COMMIT();
        const uint32_t st = sb + (ch % 3) * STAGE_B;

#pragma unroll
        for (int ks = 0; ks < 2; ks++) {
            const uint32_t kbyte = (ks * 2) * 16;
            // hoisted fragment loads: 12 ldsm up front
            uint32_t ah[4][4], al[4][4], bhf[2][4], blf[2][4];
#pragma unroll
            for (int mt = 0; mt < 4; mt++)
                ldsm_x4(ah[mt], st + (wm * 64 + mt * 16 + a_row_off) * TSTRIDE
                                   + kbyte + a_kc * 16);
#pragma unroll
            for (int mt = 0; mt < 4; mt++)
                ldsm_x4(al[mt], st + TILE_B + (wm * 64 + mt * 16 + a_row_off) * TSTRIDE
                                   + kbyte + a_kc * 16);
#pragma unroll
            for (int p = 0; p < 2; p++)
                ldsm_x4(bhf[p], st + 2 * TILE_B
                                   + (wn * 32 + p * 16 + b_row_off) * TSTRIDE
                                   + kbyte + b_kc * 16);
#pragma unroll
            for (int p = 0; p < 2; p++)
                ldsm_x4(blf[p], st + 3 * TILE_B
                                   + (wn * 32 + p * 16 + b_row_off) * TSTRIDE
                                   + kbyte + b_kc * 16);
            // uninterrupted 48-mma burst
#pragma unroll
            for (int mt = 0; mt < 4; mt++)
#pragma unroll
                for (int nt = 0; nt < 4; nt++)
                    mma_bf16(acc[mt][nt], ah[mt], &bhf[nt >> 1][(nt & 1) * 2]);
#pragma unroll
            for (int mt = 0; mt < 4; mt++)
#pragma unroll
                for (int nt = 0; nt < 4; nt++)
                    mma_bf16(acc[mt][nt], ah[mt], &blf[nt >> 1][(nt & 1) * 2]);
#pragma unroll
            for (int mt = 0; mt < 4; mt++)
#pragma unroll
                for (int nt = 0; nt < 4; nt++)
                    mma_bf16(acc[mt][nt], al[mt], &bhf[nt >> 1][(nt & 1) * 2]);
        }
        __syncthreads();
    }
    CP_WAIT0();

    const int g  = lane >> 2;
    const int tq = lane & 3;
#pragma unroll
    for (int mt = 0; mt < 4; mt++) {
#pragma unroll
        for (int nt = 0; nt < 4; nt++) {
            int row = bm + wm * 64 + mt * 16 + g;
            int col = bn + wn * 32 + nt * 8 + tq * 2;
            float b0 = bias[col], b1 = bias[col + 1];
            float2 v0 = make_float2(acc[mt][nt][0] + b0, acc[mt][nt][1] + b1);
            float2 v1 = make_float2(acc[mt][nt][2] + b0, acc[mt][nt][3] + b1);
            *reinterpret_cast<float2*>(C + (size_t)row * N + col)       = v0;
            *reinterpret_cast<float2*>(C + (size_t)(row + 8) * N + col) = v1;
        }
    }
}

// ---------------------------------------------------------------------------
// Tensor-core flash attention. 3-stage pipeline, hoisted ldsm, fused z split.
// ---------------------------------------------------------------------------
static constexpr int AT_STRIDE = 144;
static constexpr int AT_TILE   = 64 * AT_STRIDE;   // 9216
static constexpr int AT_STAGE  = 4 * AT_TILE;      // 36864
static constexpr int AT_SMEM   = 3 * AT_STAGE;     // 110592

__global__ __launch_bounds__(256, 1)
void attn_tc_kernel()
{
    extern __shared__ char smem[];
    const uint32_t sb = smem_to_u32(smem);
    const int t    = threadIdx.x;
    const int wid  = t >> 5;
    const int lane = t & 31;
    const int g    = lane >> 2;
    const int tq   = lane & 3;
    const int bh   = blockIdx.y;
    const int q0   = blockIdx.x * 128;
    const int wrow = wid * 16;

    const int sel  = lane >> 3;
    const int lrow = lane & 7;
    const int b_row_off = ((sel >> 1) ? 8 : 0) + lrow;
    const int b_kc      = sel & 1;

    // Q fragments (persistent)
    uint32_t qhf[4][4], qlf[4][4];
    {
        const size_t r0 = ((size_t)bh * SEQ + q0 + wrow + g) * HEAD_DIM;
        const size_t r1 = r0 + 8 * HEAD_DIM;
#pragma unroll
        for (int ks = 0; ks < 4; ks++) {
            int c0 = ks * 16 + tq * 2, c1 = c0 + 8;
            qhf[ks][0] = *reinterpret_cast<const uint32_t*>(g_qh + r0 + c0);
            qhf[ks][1] = *reinterpret_cast<const uint32_t*>(g_qh + r1 + c0);
            qhf[ks][2] = *reinterpret_cast<const uint32_t*>(g_qh + r0 + c1);
            qhf[ks][3] = *reinterpret_cast<const uint32_t*>(g_qh + r1 + c1);
            qlf[ks][0] = *reinterpret_cast<const uint32_t*>(g_ql + r0 + c0);
            qlf[ks][1] = *reinterpret_cast<const uint32_t*>(g_ql + r1 + c0);
            qlf[ks][2] = *reinterpret_cast<const uint32_t*>(g_ql + r0 + c1);
            qlf[ks][3] = *reinterpret_cast<const uint32_t*>(g_ql + r1 + c1);
        }
    }

    auto load_stage = [&](int s, int kk0) {
        const char* baseK  = (const char*)(g_kh + ((size_t)bh * SEQ + kk0) * HEAD_DIM);
        const char* baseKl = (const char*)(g_kl + ((size_t)bh * SEQ + kk0) * HEAD_DIM);
        const char* baseV  = (const char*)(g_vth + (size_t)bh * HEAD_DIM * SEQ + kk0);
        const char* baseVl = (const char*)(g_vtl + (size_t)bh * HEAD_DIM * SEQ + kk0);
#pragma unroll
        for (int i = 0; i < 8; i++) {
            int idx = t + i * 256;
            int tensor = idx >> 9;
            int rem = idx & 511;
            int r = rem >> 3;
            int c16 = (rem & 7) * 16;
            const char* src;
            if (tensor == 0)      src = baseK  + (size_t)r * 128 + c16;
            else if (tensor == 1) src = baseKl + (size_t)r * 128 + c16;
            else if (tensor == 2) src = baseV  + (size_t)r * (SEQ * 2) + c16;
            else                  src = baseVl + (size_t)r * (SEQ * 2) + c16;
            cp_async16(sb + s * AT_STAGE + tensor * AT_TILE + r * AT_STRIDE + c16, src);
        }
    };

    float o[8][4];
#pragma unroll
    for (int i = 0; i < 8; i++)
#pragma unroll
        for (int j = 0; j < 4; j++) o[i][j] = 0.0f;
    float m0 = -CUDART_INF_F, m1 = -CUDART_INF_F, l0 = 0.0f, l1 = 0.0f;

    load_stage(0, 0);  CP_COMMIT();
    load_stage(1, 64); CP_COMMIT();

    const int nkt = SEQ / 64;
    for (int kt = 0; kt < nkt; kt++) {
        CP_WAIT1();
        __syncthreads();
        if (kt + 2 < nkt) load_stage((kt + 2) % 3, (kt + 2) * 64);
        CP_COMMIT();
        const uint32_t st = sb + (kt % 3) * AT_STAGE;

        // ---- S = Q K^T (hoisted ldsm per ks, then 24-mma burst) ----
        float s[8][4];
#pragma unroll
        for (int i = 0; i < 8; i++)
#pragma unroll
            for (int j = 0; j < 4; j++) s[i][j] = 0.0f;
#pragma unroll
        for (int ks = 0; ks < 4; ks++) {
            const uint32_t kbyte = ks * 32 + b_kc * 16;
            uint32_t kf[4][4], klf[4][4];
#pragma unroll
            for (int ng = 0; ng < 4; ng++)
                ldsm_x4(kf[ng], st + (ng * 16 + b_row_off) * AT_STRIDE + kbyte);
#pragma unroll
            for (int ng = 0; ng < 4; ng++)
                ldsm_x4(klf[ng], st + AT_TILE + (ng * 16 + b_row_off) * AT_STRIDE + kbyte);
#pragma unroll
            for (int ng = 0; ng < 4; ng++) {
                mma_bf16(s[ng * 2],     qhf[ks], &kf[ng][0]);
                mma_bf16(s[ng * 2 + 1], qhf[ks], &kf[ng][2]);
            }
#pragma unroll
            for (int ng = 0; ng < 4; ng++) {
                mma_bf16(s[ng * 2],     qlf[ks], &kf[ng][0]);
                mma_bf16(s[ng * 2 + 1], qlf[ks], &kf[ng][2]);
            }
#pragma unroll
            for (int ng = 0; ng < 4; ng++) {
                mma_bf16(s[ng * 2],     qhf[ks], &klf[ng][0]);
                mma_bf16(s[ng * 2 + 1], qhf[ks], &klf[ng][2]);
            }
        }

        // ---- online softmax ----
        float mt0 = -CUDART_INF_F, mt1 = -CUDART_INF_F;
#pragma unroll
        for (int nt = 0; nt < 8; nt++) {
            mt0 = fmaxf(mt0, fmaxf(s[nt][0], s[nt][1]));
            mt1 = fmaxf(mt1, fmaxf(s[nt][2], s[nt][3]));
        }
        mt0 = fmaxf(mt0, __shfl_xor_sync(0xFFFFFFFF, mt0, 1));
        mt0 = fmaxf(mt0, __shfl_xor_sync(0xFFFFFFFF, mt0, 2));
        mt1 = fmaxf(mt1, __shfl_xor_sync(0xFFFFFFFF, mt1, 1));
        mt1 = fmaxf(mt1, __shfl_xor_sync(0xFFFFFFFF, mt1, 2));
        float mn0 = fmaxf(m0, mt0), mn1 = fmaxf(m1, mt1);
        float c0 = __expf(m0 - mn0), c1 = __expf(m1 - mn1);
        m0 = mn0; m1 = mn1;
        float ls0 = 0.0f, ls1 = 0.0f;
#pragma unroll
        for (int nt = 0; nt < 8; nt++) {
            s[nt][0] = __expf(s[nt][0] - m0);
            s[nt][1] = __expf(s[nt][1] - m0);
            s[nt][2] = __expf(s[nt][2] - m1);
            s[nt][3] = __expf(s[nt][3] - m1);
            ls0 += s[nt][0] + s[nt][1];
            ls1 += s[nt][2] + s[nt][3];
        }
        l0 = l0 * c0 + ls0;
        l1 = l1 * c1 + ls1;
#pragma unroll
        for (int nt = 0; nt < 8; nt++) {
            o[nt][0] *= c0; o[nt][1] *= c0;
            o[nt][2] *= c1; o[nt][3] *= c1;
        }

        // ---- O += P V (hoisted ldsm, 24-mma burst per ks) ----
#pragma unroll
        for (int ks = 0; ks < 4; ks++) {
            uint32_t pa_h[4], pa_l[4];
#pragma unroll
            for (int half = 0; half < 2; half++) {
                const float* sp = s[2 * ks + half];
                float h0 = __bfloat162float(__float2bfloat16(sp[0]));
                float h1 = __bfloat162float(__float2bfloat16(sp[1]));
                float h2 = __bfloat162float(__float2bfloat16(sp[2]));
                float h3 = __bfloat162float(__float2bfloat16(sp[3]));
                pa_h[half * 2]     = pack_bf16x2(sp[0], sp[1]);
                pa_h[half * 2 + 1] = pack_bf16x2(sp[2], sp[3]);
                pa_l[half * 2]     = pack_bf16x2(sp[0] - h0, sp[1] - h1);
                pa_l[half * 2 + 1] = pack_bf16x2(sp[2] - h2, sp[3] - h3);
            }
            const uint32_t kbyte = ks * 32 + b_kc * 16;
            uint32_t vf[4][4], vlf[4][4];
#pragma unroll
            for (int ng = 0; ng < 4; ng++)
                ldsm_x4(vf[ng], st + 2 * AT_TILE + (ng * 16 + b_row_off) * AT_STRIDE + kbyte);
#pragma unroll
            for (int ng = 0; ng < 4; ng++)
                ldsm_x4(vlf[ng], st + 3 * AT_TILE + (ng * 16 + b_row_off) * AT_STRIDE + kbyte);
#pragma unroll
            for (int ng = 0; ng < 4; ng++) {
                mma_bf16(o[ng * 2],     pa_h, &vf[ng][0]);
                mma_bf16(o[ng * 2 + 1], pa_h, &vf[ng][2]);
            }
#pragma unroll
            for (int ng = 0; ng < 4; ng++) {
                mma_bf16(o[ng * 2],     pa_l, &vf[ng][0]);
                mma_bf16(o[ng * 2 + 1], pa_l, &vf[ng][2]);
            }
#pragma unroll
            for (int ng = 0; ng < 4; ng++) {
                mma_bf16(o[ng * 2],     pa_h, &vlf[ng][0]);
                mma_bf16(o[ng * 2 + 1], pa_h, &vlf[ng][2]);
            }
        }
        __syncthreads();
    }
    CP_WAIT0();

    // ---- finalize: write split bf16 z directly ----
    l0 += __shfl_xor_sync(0xFFFFFFFF, l0, 1);
    l0 += __shfl_xor_sync(0xFFFFFFFF, l0, 2);
    l1 += __shfl_xor_sync(0xFFFFFFFF, l1, 1);
    l1 += __shfl_xor_sync(0xFFFFFFFF, l1, 2);
    float inv0 = 1.0f / l0, inv1 = 1.0f / l1;

    const int b = bh >> 4, h = bh & 15;
    const size_t tok0 = (size_t)b * SEQ + q0 + wrow + g;
#pragma unroll
    for (int nt = 0; nt < 8; nt++) {
        int col = h * HEAD_DIM + nt * 8 + tq * 2;
        float a0 = o[nt][0] * inv0, a1 = o[nt][1] * inv0;
        float a2 = o[nt][2] * inv1, a3 = o[nt][3] * inv1;
        __nv_bfloat16 h0 = __float2bfloat16(a0), h1 = __float2bfloat16(a1);
        __nv_bfloat16 h2 = __float2bfloat16(a2), h3 = __float2bfloat16(a3);
        __nv_bfloat162 ph0; ph0.x = h0; ph0.y = h1;
        __nv_bfloat162 ph1; ph1.x = h2; ph1.y = h3;
        __nv_bfloat162 pl0, pl1;
        pl0.x = __float2bfloat16(a0 - __bfloat162float(h0));
        pl0.y = __float2bfloat16(a1 - __bfloat162float(h1));
        pl1.x = __float2bfloat16(a2 - __bfloat162float(h2));
        pl1.y = __float2bfloat16(a3 - __bfloat162float(h3));
        *reinterpret_cast<__nv_bfloat162*>(g_zh + tok0 * MODEL_DIM + col)       = ph0;
        *reinterpret_cast<__nv_bfloat162*>(g_zl + tok0 * MODEL_DIM + col)       = pl0;
        *reinterpret_cast<__nv_bfloat162*>(g_zh + (tok0 + 8) * MODEL_DIM + col) = ph1;
        *reinterpret_cast<__nv_bfloat162*>(g_zl + (tok0 + 8) * MODEL_DIM + col) = pl1;
    }
}

// ---------------------------------------------------------------------------
// Launch
// ---------------------------------------------------------------------------
extern "C" void kernel_launch(void* const* d_in, const int* in_sizes, int n_in,
                              void* d_out, int out_size)
{
    const float* x     = (const float*)d_in[0];
    const float* w_qkv = (const float*)d_in[1];
    const float* b_qkv = (const float*)d_in[2];
    const float* w_out = (const float*)d_in[3];
    const float* b_out = (const float*)d_in[4];
    float* out = (float*)d_out;

    float* qkv_buf;
    __nv_bfloat16 *xh, *xl, *zh, *zl, *wqkvT_h, *wqkvT_l, *woutT_h, *woutT_l;
    cudaGetSymbolAddress((void**)&qkv_buf, g_qkv);
    cudaGetSymbolAddress((void**)&xh, g_xh);
    cudaGetSymbolAddress((void**)&xl, g_xl);
    cudaGetSymbolAddress((void**)&zh, g_zh);
    cudaGetSymbolAddress((void**)&zl, g_zl);
    cudaGetSymbolAddress((void**)&wqkvT_h, g_wqkvT_h);
    cudaGetSymbolAddress((void**)&wqkvT_l, g_wqkvT_l);
    cudaGetSymbolAddress((void**)&woutT_h, g_woutT_h);
    cudaGetSymbolAddress((void**)&woutT_l, g_woutT_l);

    cudaFuncSetAttribute(tc_gemm_kernel,
                         cudaFuncAttributeMaxDynamicSharedMemorySize, GEMM_SMEM);
    cudaFuncSetAttribute(attn_tc_kernel,
                         cudaFuncAttributeMaxDynamicSharedMemorySize, AT_SMEM);

    // 0. Preprocess: split x; transpose+split weights
    {
        int n4 = TOK * MODEL_DIM / 4;
        split_kernel<<<(n4 + 255) / 256, 256>>>(x, xh, xl, n4);
        transpose_split_kernel<<<dim3(QKV_DIM / 32, MODEL_DIM / 32), dim3(32, 8)>>>(
            w_qkv, wqkvT_h, wqkvT_l, MODEL_DIM, QKV_DIM);
        transpose_split_kernel<<<dim3(MODEL_DIM / 32, MODEL_DIM / 32), dim3(32, 8)>>>(
            w_out, woutT_h, woutT_l, MODEL_DIM, MODEL_DIM);
    }

    // 1. QKV projection
    tc_gemm_kernel<<<dim3(QKV_DIM / 128, TOK / 128), 256, GEMM_SMEM>>>(
        xh, xl, wqkvT_h, wqkvT_l, b_qkv, qkv_buf, TOK, QKV_DIM, MODEL_DIM);

    // 2. Split qkv into attention operand layouts
    split_qkv_kernel<<<dim3(SEQ / 64, BH), 256>>>(qkv_buf);

    // 3. Tensor-core flash attention (writes g_zh/g_zl directly)
    attn_tc_kernel<<<dim3(SEQ / 128, BH), 256, AT_SMEM>>>();

    // 4. Output projection
    tc_gemm_kernel<<<dim3(MODEL_DIM / 128, TOK / 128), 256, GEMM_SMEM>>>(
        zh, zl, woutT_h, woutT_l, b_out, out, TOK, MODEL_DIM, MODEL_DIM);
}

// round 8
// speedup vs baseline: 2.9593x; 1.1048x over previous
#include <cuda_runtime.h>
#include <cuda_bf16.h>
#include <math_constants.h>
#include <cstdint>

// Problem constants
static constexpr int MODEL_DIM = 1024;
static constexpr int HEAD      = 16;
static constexpr int HEAD_DIM  = 64;
static constexpr int BATCH     = 2;
static constexpr int SEQ       = 2048;
static constexpr int TOK       = BATCH * SEQ;      // 4096
static constexpr int QKV_DIM   = 3 * MODEL_DIM;    // 3072
static constexpr int BH        = BATCH * HEAD;     // 32

// Scratch (__device__ globals; no runtime allocation allowed)
__device__ float g_qkv[TOK * QKV_DIM];
__device__ __nv_bfloat16 g_xh[TOK * MODEL_DIM];
__device__ __nv_bfloat16 g_xl[TOK * MODEL_DIM];
__device__ __nv_bfloat16 g_zh[TOK * MODEL_DIM];
__device__ __nv_bfloat16 g_zl[TOK * MODEL_DIM];
__device__ __nv_bfloat16 g_wqkvT_h[QKV_DIM * MODEL_DIM];
__device__ __nv_bfloat16 g_wqkvT_l[QKV_DIM * MODEL_DIM];
__device__ __nv_bfloat16 g_woutT_h[MODEL_DIM * MODEL_DIM];
__device__ __nv_bfloat16 g_woutT_l[MODEL_DIM * MODEL_DIM];
// Attention operands, split bf16. Q pre-scaled by 0.125.
__device__ __nv_bfloat16 g_qh[BH * SEQ * HEAD_DIM];   // [bh][s][d]
__device__ __nv_bfloat16 g_ql[BH * SEQ * HEAD_DIM];
__device__ __nv_bfloat16 g_kh[BH * SEQ * HEAD_DIM];   // [bh][s][d]
__device__ __nv_bfloat16 g_kl[BH * SEQ * HEAD_DIM];
__device__ __nv_bfloat16 g_vth[BH * HEAD_DIM * SEQ];  // [bh][d][s]
__device__ __nv_bfloat16 g_vtl[BH * HEAD_DIM * SEQ];

// ---------------------------------------------------------------------------
// PTX helpers (sm_80-compatible)
// ---------------------------------------------------------------------------
__device__ __forceinline__ uint32_t smem_to_u32(const void* p) {
    uint32_t a;
    asm("{ .reg .u64 tmp; cvta.to.shared.u64 tmp, %1; cvt.u32.u64 %0, tmp; }"
        : "=r"(a) : "l"(p));
    return a;
}
__device__ __forceinline__ void ldsm_x4(uint32_t* r, uint32_t addr) {
    asm volatile("ldmatrix.sync.aligned.m8n8.x4.shared.b16 {%0,%1,%2,%3}, [%4];"
                 : "=r"(r[0]), "=r"(r[1]), "=r"(r[2]), "=r"(r[3]) : "r"(addr));
}
__device__ __forceinline__ void mma_bf16(float* c, const uint32_t* a, const uint32_t* b) {
    asm volatile(
        "mma.sync.aligned.m16n8k16.row.col.f32.bf16.bf16.f32 "
        "{%0,%1,%2,%3}, {%4,%5,%6,%7}, {%8,%9}, {%0,%1,%2,%3};"
        : "+f"(c[0]), "+f"(c[1]), "+f"(c[2]), "+f"(c[3])
        : "r"(a[0]), "r"(a[1]), "r"(a[2]), "r"(a[3]), "r"(b[0]), "r"(b[1]));
}
__device__ __forceinline__ void cp_async16(uint32_t dst, const void* src) {
    asm volatile("cp.async.cg.shared.global [%0], [%1], 16;" :: "r"(dst), "l"(src));
}
#define CP_COMMIT() asm volatile("cp.async.commit_group;" ::: "memory")
#define CP_WAIT1()  asm volatile("cp.async.wait_group 1;" ::: "memory")
#define CP_WAIT0()  asm volatile("cp.async.wait_group 0;" ::: "memory")
__device__ __forceinline__ uint32_t pack_bf16x2(float lo, float hi) {
    uint32_t r;
    asm("cvt.rn.bf16x2.f32 %0, %1, %2;" : "=r"(r) : "f"(hi), "f"(lo));
    return r;
}

// ---------------------------------------------------------------------------
// x split: fp32 -> hi/lo bf16
// ---------------------------------------------------------------------------
__global__ void split_kernel(const float* __restrict__ X,
                             __nv_bfloat16* __restrict__ Xh,
                             __nv_bfloat16* __restrict__ Xl, int n4)
{
    int i = blockIdx.x * blockDim.x + threadIdx.x;
    if (i >= n4) return;
    float4 v = reinterpret_cast<const float4*>(X)[i];
    __nv_bfloat16 h0 = __float2bfloat16(v.x), h1 = __float2bfloat16(v.y);
    __nv_bfloat16 h2 = __float2bfloat16(v.z), h3 = __float2bfloat16(v.w);
    __nv_bfloat162 ph0; ph0.x = h0; ph0.y = h1;
    __nv_bfloat162 ph1; ph1.x = h2; ph1.y = h3;
    __nv_bfloat162 pl0, pl1;
    pl0.x = __float2bfloat16(v.x - __bfloat162float(h0));
    pl0.y = __float2bfloat16(v.y - __bfloat162float(h1));
    pl1.x = __float2bfloat16(v.z - __bfloat162float(h2));
    pl1.y = __float2bfloat16(v.w - __bfloat162float(h3));
    reinterpret_cast<__nv_bfloat162*>(Xh)[i * 2]     = ph0;
    reinterpret_cast<__nv_bfloat162*>(Xh)[i * 2 + 1] = ph1;
    reinterpret_cast<__nv_bfloat162*>(Xl)[i * 2]     = pl0;
    reinterpret_cast<__nv_bfloat162*>(Xl)[i * 2 + 1] = pl1;
}

// ---------------------------------------------------------------------------
// Weight transpose + split: W[K][N] fp32 -> Th/Tl[N][K] bf16
// ---------------------------------------------------------------------------
__global__ void transpose_split_kernel(const float* __restrict__ W,
                                       __nv_bfloat16* __restrict__ Th,
                                       __nv_bfloat16* __restrict__ Tl,
                                       int K, int N)
{
    __shared__ float tile[32][33];
    const int n0 = blockIdx.x * 32, k0 = blockIdx.y * 32;
    const int tx = threadIdx.x, ty = threadIdx.y;
#pragma unroll
    for (int i = 0; i < 32; i += 8)
        tile[ty + i][tx] = W[(size_t)(k0 + ty + i) * N + n0 + tx];
    __syncthreads();
#pragma unroll
    for (int i = 0; i < 32; i += 8) {
        float v = tile[tx][ty + i];
        __nv_bfloat16 h = __float2bfloat16(v);
        __nv_bfloat16 l = __float2bfloat16(v - __bfloat162float(h));
        size_t o = (size_t)(n0 + ty + i) * K + k0 + tx;
        Th[o] = h;
        Tl[o] = l;
    }
}

// ---------------------------------------------------------------------------
// QKV split pre-pass
// ---------------------------------------------------------------------------
__global__ __launch_bounds__(256)
void split_qkv_kernel(const float* __restrict__ qkv)
{
    __shared__ float vs[64][65];
    const int t  = threadIdx.x;
    const int bh = blockIdx.y;
    const int b  = bh >> 4, h = bh & 15;
    const int s0 = blockIdx.x * 64;
    const size_t tokb = (size_t)b * SEQ + s0;

    for (int idx = t; idx < 64 * 64; idx += 256) {
        int r = idx >> 6, c = idx & 63;
        const float* row = qkv + (tokb + r) * QKV_DIM + h * HEAD_DIM + c;
        float qv = row[0] * 0.125f;
        float kv = row[MODEL_DIM];
        float vv = row[2 * MODEL_DIM];
        size_t o = ((size_t)bh * SEQ + s0 + r) * HEAD_DIM + c;
        __nv_bfloat16 qhh = __float2bfloat16(qv);
        g_qh[o] = qhh;
        g_ql[o] = __float2bfloat16(qv - __bfloat162float(qhh));
        __nv_bfloat16 khh = __float2bfloat16(kv);
        g_kh[o] = khh;
        g_kl[o] = __float2bfloat16(kv - __bfloat162float(khh));
        vs[r][c] = vv;
    }
    __syncthreads();
    for (int idx = t; idx < 64 * 64; idx += 256) {
        int d = idx >> 6, c = idx & 63;
        float vv = vs[c][d];
        size_t o = ((size_t)bh * HEAD_DIM + d) * SEQ + s0 + c;
        __nv_bfloat16 vh = __float2bfloat16(vv);
        g_vth[o] = vh;
        g_vtl[o] = __float2bfloat16(vv - __bfloat162float(vh));
    }
}

// ---------------------------------------------------------------------------
// mma.sync split-bf16 GEMM. 2-stage pipeline, 2 CTAs/SM, staggered frag loads.
// ---------------------------------------------------------------------------
static constexpr int TSTRIDE   = 80;
static constexpr int TILE_B    = 128 * TSTRIDE;      // 10240
static constexpr int STAGE_B   = 4 * TILE_B;         // 40960
static constexpr int GEMM_SMEM = 2 * STAGE_B;        // 81920 (x2 CTA = 163840)

__global__ __launch_bounds__(256, 2)
void tc_gemm_kernel(const __nv_bfloat16* __restrict__ Ah,
                    const __nv_bfloat16* __restrict__ Al,
                    const __nv_bfloat16* __restrict__ Bh,
                    const __nv_bfloat16* __restrict__ Bl,
                    const float* __restrict__ bias,
                    float* __restrict__ C,
                    int M, int N, int K)
{
    extern __shared__ char smem[];
    const uint32_t sb = smem_to_u32(smem);
    const int t    = threadIdx.x;
    const int wid  = t >> 5;
    const int lane = t & 31;
    const int wm   = wid & 1;
    const int wn   = wid >> 1;
    const int bm   = blockIdx.y * 128;
    const int bn   = blockIdx.x * 128;

    const int ld_idx = t * 2;
    const int ld_r   = ld_idx >> 2;
    const int ld_c   = (ld_idx & 3) * 16;

    auto stage_load = [&](int s, int k0) {
        uint32_t dst0 = sb + s * STAGE_B + ld_r * TSTRIDE + ld_c;
        const char* a_src = (const char*)(Ah + (size_t)(bm + ld_r) * K + k0) + ld_c;
        const char* b_src;
        cp_async16(dst0,               a_src);
        cp_async16(dst0 + 16,          a_src + 16);
        a_src = (const char*)(Al + (size_t)(bm + ld_r) * K + k0) + ld_c;
        cp_async16(dst0 + TILE_B,      a_src);
        cp_async16(dst0 + TILE_B + 16, a_src + 16);
        b_src = (const char*)(Bh + (size_t)(bn + ld_r) * K + k0) + ld_c;
        cp_async16(dst0 + 2 * TILE_B,      b_src);
        cp_async16(dst0 + 2 * TILE_B + 16, b_src + 16);
        b_src = (const char*)(Bl + (size_t)(bn + ld_r) * K + k0) + ld_c;
        cp_async16(dst0 + 3 * TILE_B,      b_src);
        cp_async16(dst0 + 3 * TILE_B + 16, b_src + 16);
    };

    float acc[4][4][4];
#pragma unroll
    for (int i = 0; i < 4; i++)
#pragma unroll
        for (int j = 0; j < 4; j++)
#pragma unroll
            for (int k = 0; k < 4; k++) acc[i][j][k] = 0.0f;

    stage_load(0, 0);  CP_COMMIT();
    stage_load(1, 32); CP_COMMIT();

    const int sel  = lane >> 3;
    const int lrow = lane & 7;
    const int a_row_off = ((sel & 1) ? 8 : 0) + lrow;
    const int a_kc      = sel >> 1;
    const int b_row_off = ((sel >> 1) ? 8 : 0) + lrow;
    const int b_kc      = sel & 1;

    const int nch = K / 32;
    for (int ch = 0; ch < nch; ch++) {
        CP_WAIT1();
        __syncthreads();
        const uint32_t st = sb + (ch & 1) * STAGE_B;

#pragma unroll
        for (int ks = 0; ks < 2; ks++) {
            const uint32_t kbyte = ks * 32;
            uint32_t af[4][4], bhf[2][4], blf[2][4];
            // A-hi + B-hi, burst 1
#pragma unroll
            for (int mt = 0; mt < 4; mt++)
                ldsm_x4(af[mt], st + (wm * 64 + mt * 16 + a_row_off) * TSTRIDE
                                   + kbyte + a_kc * 16);
#pragma unroll
            for (int p = 0; p < 2; p++)
                ldsm_x4(bhf[p], st + 2 * TILE_B
                                   + (wn * 32 + p * 16 + b_row_off) * TSTRIDE
                                   + kbyte + b_kc * 16);
#pragma unroll
            for (int mt = 0; mt < 4; mt++)
#pragma unroll
                for (int nt = 0; nt < 4; nt++)
                    mma_bf16(acc[mt][nt], af[mt], &bhf[nt >> 1][(nt & 1) * 2]);
            // B-lo, burst 2
#pragma unroll
            for (int p = 0; p < 2; p++)
                ldsm_x4(blf[p], st + 3 * TILE_B
                                   + (wn * 32 + p * 16 + b_row_off) * TSTRIDE
                                   + kbyte + b_kc * 16);
#pragma unroll
            for (int mt = 0; mt < 4; mt++)
#pragma unroll
                for (int nt = 0; nt < 4; nt++)
                    mma_bf16(acc[mt][nt], af[mt], &blf[nt >> 1][(nt & 1) * 2]);
            // A-lo overwrites af, burst 3 (uses bhf)
#pragma unroll
            for (int mt = 0; mt < 4; mt++)
                ldsm_x4(af[mt], st + TILE_B + (wm * 64 + mt * 16 + a_row_off) * TSTRIDE
                                   + kbyte + a_kc * 16);
#pragma unroll
            for (int mt = 0; mt < 4; mt++)
#pragma unroll
                for (int nt = 0; nt < 4; nt++)
                    mma_bf16(acc[mt][nt], af[mt], &bhf[nt >> 1][(nt & 1) * 2]);
        }
        __syncthreads();
        if (ch + 2 < nch) stage_load(ch & 1, (ch + 2) * 32);
        CP_COMMIT();
    }
    CP_WAIT0();

    const int g  = lane >> 2;
    const int tq = lane & 3;
#pragma unroll
    for (int mt = 0; mt < 4; mt++) {
#pragma unroll
        for (int nt = 0; nt < 4; nt++) {
            int row = bm + wm * 64 + mt * 16 + g;
            int col = bn + wn * 32 + nt * 8 + tq * 2;
            float b0 = bias[col], b1 = bias[col + 1];
            float2 v0 = make_float2(acc[mt][nt][0] + b0, acc[mt][nt][1] + b1);
            float2 v1 = make_float2(acc[mt][nt][2] + b0, acc[mt][nt][3] + b1);
            *reinterpret_cast<float2*>(C + (size_t)row * N + col)       = v0;
            *reinterpret_cast<float2*>(C + (size_t)(row + 8) * N + col) = v1;
        }
    }
}

// ---------------------------------------------------------------------------
// Tensor-core flash attention. 2-stage KV pipeline, Q in smem, 2 CTAs/SM.
// ---------------------------------------------------------------------------
static constexpr int AT_STRIDE = 144;
static constexpr int AT_TILE   = 64 * AT_STRIDE;    // 9216
static constexpr int AT_STAGE  = 4 * AT_TILE;       // 36864
static constexpr int Q_TILE    = 128 * AT_STRIDE;   // 18432
static constexpr int QS_OFF    = 2 * AT_STAGE;      // 73728
static constexpr int AT_SMEM   = QS_OFF + 2 * Q_TILE;  // 110592 (x2 = 221184)

__global__ __launch_bounds__(256, 2)
void attn_tc_kernel()
{
    extern __shared__ char smem[];
    const uint32_t sb = smem_to_u32(smem);
    const int t    = threadIdx.x;
    const int wid  = t >> 5;
    const int lane = t & 31;
    const int g    = lane >> 2;
    const int tq   = lane & 3;
    const int bh   = blockIdx.y;
    const int q0   = blockIdx.x * 128;
    const int wrow = wid * 16;

    const int sel  = lane >> 3;
    const int lrow = lane & 7;
    const int a_row_off = ((sel & 1) ? 8 : 0) + lrow;
    const int a_kc      = sel >> 1;
    const int b_row_off = ((sel >> 1) ? 8 : 0) + lrow;
    const int b_kc      = sel & 1;

    // Q tile load into smem (hi+lo), grouped with KV stage 0's commit
    {
        const char* baseQh = (const char*)(g_qh + ((size_t)bh * SEQ + q0) * HEAD_DIM);
        const char* baseQl = (const char*)(g_ql + ((size_t)bh * SEQ + q0) * HEAD_DIM);
#pragma unroll
        for (int i = 0; i < 4; i++) {
            int idx = t + i * 256;          // 0..1023
            int r = idx >> 3, c16 = (idx & 7) * 16;
            cp_async16(sb + QS_OFF + r * AT_STRIDE + c16, baseQh + (size_t)r * 128 + c16);
            cp_async16(sb + QS_OFF + Q_TILE + r * AT_STRIDE + c16, baseQl + (size_t)r * 128 + c16);
        }
    }

    auto load_stage = [&](int s, int kk0) {
        const char* baseK  = (const char*)(g_kh + ((size_t)bh * SEQ + kk0) * HEAD_DIM);
        const char* baseKl = (const char*)(g_kl + ((size_t)bh * SEQ + kk0) * HEAD_DIM);
        const char* baseV  = (const char*)(g_vth + (size_t)bh * HEAD_DIM * SEQ + kk0);
        const char* baseVl = (const char*)(g_vtl + (size_t)bh * HEAD_DIM * SEQ + kk0);
#pragma unroll
        for (int i = 0; i < 8; i++) {
            int idx = t + i * 256;
            int tensor = idx >> 9;
            int rem = idx & 511;
            int r = rem >> 3;
            int c16 = (rem & 7) * 16;
            const char* src;
            if (tensor == 0)      src = baseK  + (size_t)r * 128 + c16;
            else if (tensor == 1) src = baseKl + (size_t)r * 128 + c16;
            else if (tensor == 2) src = baseV  + (size_t)r * (SEQ * 2) + c16;
            else                  src = baseVl + (size_t)r * (SEQ * 2) + c16;
            cp_async16(sb + s * AT_STAGE + tensor * AT_TILE + r * AT_STRIDE + c16, src);
        }
    };

    float o[8][4];
#pragma unroll
    for (int i = 0; i < 8; i++)
#pragma unroll
        for (int j = 0; j < 4; j++) o[i][j] = 0.0f;
    float m0 = -CUDART_INF_F, m1 = -CUDART_INF_F, l0 = 0.0f, l1 = 0.0f;

    load_stage(0, 0);  CP_COMMIT();   // group also carries Q
    load_stage(1, 64); CP_COMMIT();

    const int nkt = SEQ / 64;
    for (int kt = 0; kt < nkt; kt++) {
        CP_WAIT1();
        __syncthreads();
        const uint32_t st = sb + (kt & 1) * AT_STAGE;

        // ---- S = Q K^T ----
        float s[8][4];
#pragma unroll
        for (int i = 0; i < 8; i++)
#pragma unroll
            for (int j = 0; j < 4; j++) s[i][j] = 0.0f;
#pragma unroll
        for (int ks = 0; ks < 4; ks++) {
            const uint32_t kbyte = ks * 32;
            const uint32_t qaddr = sb + QS_OFF + (wrow + a_row_off) * AT_STRIDE
                                   + kbyte + a_kc * 16;
            uint32_t qh4[4], ql4[4];
            ldsm_x4(qh4, qaddr);
            ldsm_x4(ql4, qaddr + Q_TILE);
            uint32_t kf[4][4], klf[4][4];
#pragma unroll
            for (int ng = 0; ng < 4; ng++)
                ldsm_x4(kf[ng], st + (ng * 16 + b_row_off) * AT_STRIDE + kbyte + b_kc * 16);
#pragma unroll
            for (int ng = 0; ng < 4; ng++)
                ldsm_x4(klf[ng], st + AT_TILE + (ng * 16 + b_row_off) * AT_STRIDE + kbyte + b_kc * 16);
#pragma unroll
            for (int ng = 0; ng < 4; ng++) {
                mma_bf16(s[ng * 2],     qh4, &kf[ng][0]);
                mma_bf16(s[ng * 2 + 1], qh4, &kf[ng][2]);
            }
#pragma unroll
            for (int ng = 0; ng < 4; ng++) {
                mma_bf16(s[ng * 2],     ql4, &kf[ng][0]);
                mma_bf16(s[ng * 2 + 1], ql4, &kf[ng][2]);
            }
#pragma unroll
            for (int ng = 0; ng < 4; ng++) {
                mma_bf16(s[ng * 2],     qh4, &klf[ng][0]);
                mma_bf16(s[ng * 2 + 1], qh4, &klf[ng][2]);
            }
        }

        // ---- online softmax ----
        float mt0 = -CUDART_INF_F, mt1 = -CUDART_INF_F;
#pragma unroll
        for (int nt = 0; nt < 8; nt++) {
            mt0 = fmaxf(mt0, fmaxf(s[nt][0], s[nt][1]));
            mt1 = fmaxf(mt1, fmaxf(s[nt][2], s[nt][3]));
        }
        mt0 = fmaxf(mt0, __shfl_xor_sync(0xFFFFFFFF, mt0, 1));
        mt0 = fmaxf(mt0, __shfl_xor_sync(0xFFFFFFFF, mt0, 2));
        mt1 = fmaxf(mt1, __shfl_xor_sync(0xFFFFFFFF, mt1, 1));
        mt1 = fmaxf(mt1, __shfl_xor_sync(0xFFFFFFFF, mt1, 2));
        float mn0 = fmaxf(m0, mt0), mn1 = fmaxf(m1, mt1);
        float c0 = __expf(m0 - mn0), c1 = __expf(m1 - mn1);
        m0 = mn0; m1 = mn1;
        float ls0 = 0.0f, ls1 = 0.0f;
#pragma unroll
        for (int nt = 0; nt < 8; nt++) {
            s[nt][0] = __expf(s[nt][0] - m0);
            s[nt][1] = __expf(s[nt][1] - m0);
            s[nt][2] = __expf(s[nt][2] - m1);
            s[nt][3] = __expf(s[nt][3] - m1);
            ls0 += s[nt][0] + s[nt][1];
            ls1 += s[nt][2] + s[nt][3];
        }
        l0 = l0 * c0 + ls0;
        l1 = l1 * c1 + ls1;
#pragma unroll
        for (int nt = 0; nt < 8; nt++) {
            o[nt][0] *= c0; o[nt][1] *= c0;
            o[nt][2] *= c1; o[nt][3] *= c1;
        }

        // ---- O += P V ----
#pragma unroll
        for (int ks = 0; ks < 4; ks++) {
            uint32_t pa_h[4], pa_l[4];
#pragma unroll
            for (int half = 0; half < 2; half++) {
                const float* sp = s[2 * ks + half];
                float h0 = __bfloat162float(__float2bfloat16(sp[0]));
                float h1 = __bfloat162float(__float2bfloat16(sp[1]));
                float h2 = __bfloat162float(__float2bfloat16(sp[2]));
                float h3 = __bfloat162float(__float2bfloat16(sp[3]));
                pa_h[half * 2]     = pack_bf16x2(sp[0], sp[1]);
                pa_h[half * 2 + 1] = pack_bf16x2(sp[2], sp[3]);
                pa_l[half * 2]     = pack_bf16x2(sp[0] - h0, sp[1] - h1);
                pa_l[half * 2 + 1] = pack_bf16x2(sp[2] - h2, sp[3] - h3);
            }
            const uint32_t kbyte = ks * 32 + b_kc * 16;
            uint32_t vf[4][4], vlf[4][4];
#pragma unroll
            for (int ng = 0; ng < 4; ng++)
                ldsm_x4(vf[ng], st + 2 * AT_TILE + (ng * 16 + b_row_off) * AT_STRIDE + kbyte);
#pragma unroll
            for (int ng = 0; ng < 4; ng++)
                ldsm_x4(vlf[ng], st + 3 * AT_TILE + (ng * 16 + b_row_off) * AT_STRIDE + kbyte);
#pragma unroll
            for (int ng = 0; ng < 4; ng++) {
                mma_bf16(o[ng * 2],     pa_h, &vf[ng][0]);
                mma_bf16(o[ng * 2 + 1], pa_h, &vf[ng][2]);
            }
#pragma unroll
            for (int ng = 0; ng < 4; ng++) {
                mma_bf16(o[ng * 2],     pa_l, &vf[ng][0]);
                mma_bf16(o[ng * 2 + 1], pa_l, &vf[ng][2]);
            }
#pragma unroll
            for (int ng = 0; ng < 4; ng++) {
                mma_bf16(o[ng * 2],     pa_h, &vlf[ng][0]);
                mma_bf16(o[ng * 2 + 1], pa_h, &vlf[ng][2]);
            }
        }
        __syncthreads();
        if (kt + 2 < nkt) load_stage(kt & 1, (kt + 2) * 64);
        CP_COMMIT();
    }
    CP_WAIT0();

    // ---- finalize: write split bf16 z directly ----
    l0 += __shfl_xor_sync(0xFFFFFFFF, l0, 1);
    l0 += __shfl_xor_sync(0xFFFFFFFF, l0, 2);
    l1 += __shfl_xor_sync(0xFFFFFFFF, l1, 1);
    l1 += __shfl_xor_sync(0xFFFFFFFF, l1, 2);
    float inv0 = 1.0f / l0, inv1 = 1.0f / l1;

    const int b = bh >> 4, h = bh & 15;
    const size_t tok0 = (size_t)b * SEQ + q0 + wrow + g;
#pragma unroll
    for (int nt = 0; nt < 8; nt++) {
        int col = h * HEAD_DIM + nt * 8 + tq * 2;
        float a0 = o[nt][0] * inv0, a1 = o[nt][1] * inv0;
        float a2 = o[nt][2] * inv1, a3 = o[nt][3] * inv1;
        __nv_bfloat16 h0 = __float2bfloat16(a0), h1 = __float2bfloat16(a1);
        __nv_bfloat16 h2 = __float2bfloat16(a2), h3 = __float2bfloat16(a3);
        __nv_bfloat162 ph0; ph0.x = h0; ph0.y = h1;
        __nv_bfloat162 ph1; ph1.x = h2; ph1.y = h3;
        __nv_bfloat162 pl0, pl1;
        pl0.x = __float2bfloat16(a0 - __bfloat162float(h0));
        pl0.y = __float2bfloat16(a1 - __bfloat162float(h1));
        pl1.x = __float2bfloat16(a2 - __bfloat162float(h2));
        pl1.y = __float2bfloat16(a3 - __bfloat162float(h3));
        *reinterpret_cast<__nv_bfloat162*>(g_zh + tok0 * MODEL_DIM + col)       = ph0;
        *reinterpret_cast<__nv_bfloat162*>(g_zl + tok0 * MODEL_DIM + col)       = pl0;
        *reinterpret_cast<__nv_bfloat162*>(g_zh + (tok0 + 8) * MODEL_DIM + col) = ph1;
        *reinterpret_cast<__nv_bfloat162*>(g_zl + (tok0 + 8) * MODEL_DIM + col) = pl1;
    }
}

// ---------------------------------------------------------------------------
// Launch
// ---------------------------------------------------------------------------
extern "C" void kernel_launch(void* const* d_in, const int* in_sizes, int n_in,
                              void* d_out, int out_size)
{
    const float* x     = (const float*)d_in[0];
    const float* w_qkv = (const float*)d_in[1];
    const float* b_qkv = (const float*)d_in[2];
    const float* w_out = (const float*)d_in[3];
    const float* b_out = (const float*)d_in[4];
    float* out = (float*)d_out;

    float* qkv_buf;
    __nv_bfloat16 *xh, *xl, *zh, *zl, *wqkvT_h, *wqkvT_l, *woutT_h, *woutT_l;
    cudaGetSymbolAddress((void**)&qkv_buf, g_qkv);
    cudaGetSymbolAddress((void**)&xh, g_xh);
    cudaGetSymbolAddress((void**)&xl, g_xl);
    cudaGetSymbolAddress((void**)&zh, g_zh);
    cudaGetSymbolAddress((void**)&zl, g_zl);
    cudaGetSymbolAddress((void**)&wqkvT_h, g_wqkvT_h);
    cudaGetSymbolAddress((void**)&wqkvT_l, g_wqkvT_l);
    cudaGetSymbolAddress((void**)&woutT_h, g_woutT_h);
    cudaGetSymbolAddress((void**)&woutT_l, g_woutT_l);

    cudaFuncSetAttribute(tc_gemm_kernel,
                         cudaFuncAttributeMaxDynamicSharedMemorySize, GEMM_SMEM);
    cudaFuncSetAttribute(attn_tc_kernel,
                         cudaFuncAttributeMaxDynamicSharedMemorySize, AT_SMEM);

    // 0. Preprocess: split x; transpose+split weights
    {
        int n4 = TOK * MODEL_DIM / 4;
        split_kernel<<<(n4 + 255) / 256, 256>>>(x, xh, xl, n4);
        transpose_split_kernel<<<dim3(QKV_DIM / 32, MODEL_DIM / 32), dim3(32, 8)>>>(
            w_qkv, wqkvT_h, wqkvT_l, MODEL_DIM, QKV_DIM);
        transpose_split_kernel<<<dim3(MODEL_DIM / 32, MODEL_DIM / 32), dim3(32, 8)>>>(
            w_out, woutT_h, woutT_l, MODEL_DIM, MODEL_DIM);
    }

    // 1. QKV projection
    tc_gemm_kernel<<<dim3(QKV_DIM / 128, TOK / 128), 256, GEMM_SMEM>>>(
        xh, xl, wqkvT_h, wqkvT_l, b_qkv, qkv_buf, TOK, QKV_DIM, MODEL_DIM);

    // 2. Split qkv into attention operand layouts
    split_qkv_kernel<<<dim3(SEQ / 64, BH), 256>>>(qkv_buf);

    // 3. Tensor-core flash attention (writes g_zh/g_zl directly)
    attn_tc_kernel<<<dim3(SEQ / 128, BH), 256, AT_SMEM>>>();

    // 4. Output projection
    tc_gemm_kernel<<<dim3(MODEL_DIM / 128, TOK / 128), 256, GEMM_SMEM>>>(
        zh, zl, woutT_h, woutT_l, b_out, out, TOK, MODEL_DIM, MODEL_DIM);
}

// round 10
// speedup vs baseline: 3.0367x; 1.0262x over previous
#include <cuda_runtime.h>
#include <cuda_bf16.h>
#include <math_constants.h>
#include <cstdint>

// Problem constants
static constexpr int MODEL_DIM = 1024;
static constexpr int HEAD      = 16;
static constexpr int HEAD_DIM  = 64;
static constexpr int BATCH     = 2;
static constexpr int SEQ       = 2048;
static constexpr int TOK       = BATCH * SEQ;      // 4096
static constexpr int QKV_DIM   = 3 * MODEL_DIM;    // 3072
static constexpr int BH        = BATCH * HEAD;     // 32

// Scratch (__device__ globals; no runtime allocation allowed)
__device__ __nv_bfloat16 g_xh[TOK * MODEL_DIM];
__device__ __nv_bfloat16 g_xl[TOK * MODEL_DIM];
__device__ __nv_bfloat16 g_zh[TOK * MODEL_DIM];
__device__ __nv_bfloat16 g_zl[TOK * MODEL_DIM];
__device__ __nv_bfloat16 g_wqkvT_h[QKV_DIM * MODEL_DIM];
__device__ __nv_bfloat16 g_wqkvT_l[QKV_DIM * MODEL_DIM];
__device__ __nv_bfloat16 g_woutT_h[MODEL_DIM * MODEL_DIM];
__device__ __nv_bfloat16 g_woutT_l[MODEL_DIM * MODEL_DIM];
// Attention operands, split bf16. Q pre-scaled by 0.125.
__device__ __nv_bfloat16 g_qh[BH * SEQ * HEAD_DIM];   // [bh][s][d]
__device__ __nv_bfloat16 g_ql[BH * SEQ * HEAD_DIM];
__device__ __nv_bfloat16 g_kh[BH * SEQ * HEAD_DIM];   // [bh][s][d]
__device__ __nv_bfloat16 g_kl[BH * SEQ * HEAD_DIM];
__device__ __nv_bfloat16 g_vth[BH * HEAD_DIM * SEQ];  // [bh][d][s]
__device__ __nv_bfloat16 g_vtl[BH * HEAD_DIM * SEQ];

// ---------------------------------------------------------------------------
// PTX helpers (sm_80-compatible)
// ---------------------------------------------------------------------------
__device__ __forceinline__ uint32_t smem_to_u32(const void* p) {
    uint32_t a;
    asm("{ .reg .u64 tmp; cvta.to.shared.u64 tmp, %1; cvt.u32.u64 %0, tmp; }"
        : "=r"(a) : "l"(p));
    return a;
}
__device__ __forceinline__ void ldsm_x4(uint32_t* r, uint32_t addr) {
    asm volatile("ldmatrix.sync.aligned.m8n8.x4.shared.b16 {%0,%1,%2,%3}, [%4];"
                 : "=r"(r[0]), "=r"(r[1]), "=r"(r[2]), "=r"(r[3]) : "r"(addr));
}
__device__ __forceinline__ void mma_bf16(float* c, const uint32_t* a, const uint32_t* b) {
    asm volatile(
        "mma.sync.aligned.m16n8k16.row.col.f32.bf16.bf16.f32 "
        "{%0,%1,%2,%3}, {%4,%5,%6,%7}, {%8,%9}, {%0,%1,%2,%3};"
        : "+f"(c[0]), "+f"(c[1]), "+f"(c[2]), "+f"(c[3])
        : "r"(a[0]), "r"(a[1]), "r"(a[2]), "r"(a[3]), "r"(b[0]), "r"(b[1]));
}
__device__ __forceinline__ void cp_async16(uint32_t dst, const void* src) {
    asm volatile("cp.async.cg.shared.global [%0], [%1], 16;" :: "r"(dst), "l"(src));
}
#define CP_COMMIT() asm volatile("cp.async.commit_group;" ::: "memory")
#define CP_WAIT1()  asm volatile("cp.async.wait_group 1;" ::: "memory")
#define CP_WAIT0()  asm volatile("cp.async.wait_group 0;" ::: "memory")
__device__ __forceinline__ uint32_t pack_bf16x2(float lo, float hi) {
    uint32_t r;
    asm("cvt.rn.bf16x2.f32 %0, %1, %2;" : "=r"(r) : "f"(hi), "f"(lo));
    return r;
}

// ---------------------------------------------------------------------------
// x split: fp32 -> hi/lo bf16
// ---------------------------------------------------------------------------
__global__ void split_kernel(const float* __restrict__ X,
                             __nv_bfloat16* __restrict__ Xh,
                             __nv_bfloat16* __restrict__ Xl, int n4)
{
    int i = blockIdx.x * blockDim.x + threadIdx.x;
    if (i >= n4) return;
    float4 v = reinterpret_cast<const float4*>(X)[i];
    __nv_bfloat16 h0 = __float2bfloat16(v.x), h1 = __float2bfloat16(v.y);
    __nv_bfloat16 h2 = __float2bfloat16(v.z), h3 = __float2bfloat16(v.w);
    __nv_bfloat162 ph0; ph0.x = h0; ph0.y = h1;
    __nv_bfloat162 ph1; ph1.x = h2; ph1.y = h3;
    __nv_bfloat162 pl0, pl1;
    pl0.x = __float2bfloat16(v.x - __bfloat162float(h0));
    pl0.y = __float2bfloat16(v.y - __bfloat162float(h1));
    pl1.x = __float2bfloat16(v.z - __bfloat162float(h2));
    pl1.y = __float2bfloat16(v.w - __bfloat162float(h3));
    reinterpret_cast<__nv_bfloat162*>(Xh)[i * 2]     = ph0;
    reinterpret_cast<__nv_bfloat162*>(Xh)[i * 2 + 1] = ph1;
    reinterpret_cast<__nv_bfloat162*>(Xl)[i * 2]     = pl0;
    reinterpret_cast<__nv_bfloat162*>(Xl)[i * 2 + 1] = pl1;
}

// ---------------------------------------------------------------------------
// Weight transpose + split: W[K][N] fp32 -> Th/Tl[N][K] bf16
// ---------------------------------------------------------------------------
__global__ void transpose_split_kernel(const float* __restrict__ W,
                                       __nv_bfloat16* __restrict__ Th,
                                       __nv_bfloat16* __restrict__ Tl,
                                       int K, int N)
{
    __shared__ float tile[32][33];
    const int n0 = blockIdx.x * 32, k0 = blockIdx.y * 32;
    const int tx = threadIdx.x, ty = threadIdx.y;
#pragma unroll
    for (int i = 0; i < 32; i += 8)
        tile[ty + i][tx] = W[(size_t)(k0 + ty + i) * N + n0 + tx];
    __syncthreads();
#pragma unroll
    for (int i = 0; i < 32; i += 8) {
        float v = tile[tx][ty + i];
        __nv_bfloat16 h = __float2bfloat16(v);
        __nv_bfloat16 l = __float2bfloat16(v - __bfloat162float(h));
        size_t o = (size_t)(n0 + ty + i) * K + k0 + tx;
        Th[o] = h;
        Tl[o] = l;
    }
}

// ---------------------------------------------------------------------------
// mma.sync split-bf16 GEMM. 2-stage pipeline, 2 CTAs/SM.
// QKV_EPI=true: fused epilogue writing split attention operand layouts.
// QKV_EPI=false: fp32 C + bias (output projection).
// ---------------------------------------------------------------------------
static constexpr int TSTRIDE   = 80;
static constexpr int TILE_B    = 128 * TSTRIDE;      // 10240
static constexpr int STAGE_B   = 4 * TILE_B;         // 40960
static constexpr int GEMM_SMEM = 2 * STAGE_B;        // 81920 (x2 CTA = 163840)

template <bool QKV_EPI>
__global__ __launch_bounds__(256, 2)
void tc_gemm_kernel(const __nv_bfloat16* __restrict__ Ah,
                    const __nv_bfloat16* __restrict__ Al,
                    const __nv_bfloat16* __restrict__ Bh,
                    const __nv_bfloat16* __restrict__ Bl,
                    const float* __restrict__ bias,
                    float* __restrict__ C,
                    int M, int N, int K)
{
    extern __shared__ char smem[];
    const uint32_t sb = smem_to_u32(smem);
    const int t    = threadIdx.x;
    const int wid  = t >> 5;
    const int lane = t & 31;
    const int wm   = wid & 1;
    const int wn   = wid >> 1;
    const int bm   = blockIdx.y * 128;
    const int bn   = blockIdx.x * 128;

    const int ld_idx = t * 2;
    const int ld_r   = ld_idx >> 2;
    const int ld_c   = (ld_idx & 3) * 16;

    auto stage_load = [&](int s, int k0) {
        uint32_t dst0 = sb + s * STAGE_B + ld_r * TSTRIDE + ld_c;
        const char* a_src = (const char*)(Ah + (size_t)(bm + ld_r) * K + k0) + ld_c;
        const char* b_src;
        cp_async16(dst0,               a_src);
        cp_async16(dst0 + 16,          a_src + 16);
        a_src = (const char*)(Al + (size_t)(bm + ld_r) * K + k0) + ld_c;
        cp_async16(dst0 + TILE_B,      a_src);
        cp_async16(dst0 + TILE_B + 16, a_src + 16);
        b_src = (const char*)(Bh + (size_t)(bn + ld_r) * K + k0) + ld_c;
        cp_async16(dst0 + 2 * TILE_B,      b_src);
        cp_async16(dst0 + 2 * TILE_B + 16, b_src + 16);
        b_src = (const char*)(Bl + (size_t)(bn + ld_r) * K + k0) + ld_c;
        cp_async16(dst0 + 3 * TILE_B,      b_src);
        cp_async16(dst0 + 3 * TILE_B + 16, b_src + 16);
    };

    float acc[4][4][4];
#pragma unroll
    for (int i = 0; i < 4; i++)
#pragma unroll
        for (int j = 0; j < 4; j++)
#pragma unroll
            for (int k = 0; k < 4; k++) acc[i][j][k] = 0.0f;

    stage_load(0, 0);  CP_COMMIT();
    stage_load(1, 32); CP_COMMIT();

    const int sel  = lane >> 3;
    const int lrow = lane & 7;
    const int a_row_off = ((sel & 1) ? 8 : 0) + lrow;
    const int a_kc      = sel >> 1;
    const int b_row_off = ((sel >> 1) ? 8 : 0) + lrow;
    const int b_kc      = sel & 1;

    const int nch = K / 32;
    for (int ch = 0; ch < nch; ch++) {
        CP_WAIT1();
        __syncthreads();
        const uint32_t st = sb + (ch & 1) * STAGE_B;

#pragma unroll
        for (int ks = 0; ks < 2; ks++) {
            const uint32_t kbyte = ks * 32;
            uint32_t af[4][4], bhf[2][4], blf[2][4];
#pragma unroll
            for (int mt = 0; mt < 4; mt++)
                ldsm_x4(af[mt], st + (wm * 64 + mt * 16 + a_row_off) * TSTRIDE
                                   + kbyte + a_kc * 16);
#pragma unroll
            for (int p = 0; p < 2; p++)
                ldsm_x4(bhf[p], st + 2 * TILE_B
                                   + (wn * 32 + p * 16 + b_row_off) * TSTRIDE
                                   + kbyte + b_kc * 16);
#pragma unroll
            for (int mt = 0; mt < 4; mt++)
#pragma unroll
                for (int nt = 0; nt < 4; nt++)
                    mma_bf16(acc[mt][nt], af[mt], &bhf[nt >> 1][(nt & 1) * 2]);
#pragma unroll
            for (int p = 0; p < 2; p++)
                ldsm_x4(blf[p], st + 3 * TILE_B
                                   + (wn * 32 + p * 16 + b_row_off) * TSTRIDE
                                   + kbyte + b_kc * 16);
#pragma unroll
            for (int mt = 0; mt < 4; mt++)
#pragma unroll
                for (int nt = 0; nt < 4; nt++)
                    mma_bf16(acc[mt][nt], af[mt], &blf[nt >> 1][(nt & 1) * 2]);
#pragma unroll
            for (int mt = 0; mt < 4; mt++)
                ldsm_x4(af[mt], st + TILE_B + (wm * 64 + mt * 16 + a_row_off) * TSTRIDE
                                   + kbyte + a_kc * 16);
#pragma unroll
            for (int mt = 0; mt < 4; mt++)
#pragma unroll
                for (int nt = 0; nt < 4; nt++)
                    mma_bf16(acc[mt][nt], af[mt], &bhf[nt >> 1][(nt & 1) * 2]);
        }
        __syncthreads();
        if (ch + 2 < nch) stage_load(ch & 1, (ch + 2) * 32);
        CP_COMMIT();
    }
    CP_WAIT0();

    const int g  = lane >> 2;
    const int tq = lane & 3;

    if constexpr (!QKV_EPI) {
        // fp32 C + bias (output projection)
#pragma unroll
        for (int mt = 0; mt < 4; mt++) {
#pragma unroll
            for (int nt = 0; nt < 4; nt++) {
                int row = bm + wm * 64 + mt * 16 + g;
                int col = bn + wn * 32 + nt * 8 + tq * 2;
                float b0 = bias[col], b1 = bias[col + 1];
                float2 v0 = make_float2(acc[mt][nt][0] + b0, acc[mt][nt][1] + b1);
                float2 v1 = make_float2(acc[mt][nt][2] + b0, acc[mt][nt][3] + b1);
                *reinterpret_cast<float2*>(C + (size_t)row * N + col)       = v0;
                *reinterpret_cast<float2*>(C + (size_t)(row + 8) * N + col) = v1;
            }
        }
    } else {
        // Fused QKV epilogue: write split bf16 attention operands directly.
        const int sec = bn >> 10;              // 0=q, 1=k, 2=v (tiles never cross)
        const float qscale = (sec == 0) ? 0.125f : 1.0f;
#pragma unroll
        for (int mt = 0; mt < 4; mt++) {
#pragma unroll
            for (int nt = 0; nt < 4; nt++) {
                int row = bm + wm * 64 + mt * 16 + g;         // token
                int col = bn + wn * 32 + nt * 8 + tq * 2;     // global qkv col
                float b0 = bias[col], b1 = bias[col + 1];
                float v0 = (acc[mt][nt][0] + b0) * qscale;
                float v1 = (acc[mt][nt][1] + b1) * qscale;
                float v2 = (acc[mt][nt][2] + b0) * qscale;
                float v3 = (acc[mt][nt][3] + b1) * qscale;
                __nv_bfloat16 h0 = __float2bfloat16(v0), h1 = __float2bfloat16(v1);
                __nv_bfloat16 h2 = __float2bfloat16(v2), h3 = __float2bfloat16(v3);
                __nv_bfloat16 l0 = __float2bfloat16(v0 - __bfloat162float(h0));
                __nv_bfloat16 l1 = __float2bfloat16(v1 - __bfloat162float(h1));
                __nv_bfloat16 l2 = __float2bfloat16(v2 - __bfloat162float(h2));
                __nv_bfloat16 l3 = __float2bfloat16(v3 - __bfloat162float(h3));
                int cc = col & 1023;           // col within section
                int h  = cc >> 6, d = cc & 63;
                int b  = row >> 11, sq = row & 2047;
                int bh = b * 16 + h;
                if (sec < 2) {
                    __nv_bfloat16* dh = (sec == 0) ? g_qh : g_kh;
                    __nv_bfloat16* dl = (sec == 0) ? g_ql : g_kl;
                    size_t o = ((size_t)bh * SEQ + sq) * HEAD_DIM + d;
                    __nv_bfloat162 ph0; ph0.x = h0; ph0.y = h1;
                    __nv_bfloat162 ph1; ph1.x = h2; ph1.y = h3;
                    __nv_bfloat162 pl0; pl0.x = l0; pl0.y = l1;
                    __nv_bfloat162 pl1; pl1.x = l2; pl1.y = l3;
                    *reinterpret_cast<__nv_bfloat162*>(dh + o)                 = ph0;
                    *reinterpret_cast<__nv_bfloat162*>(dl + o)                 = pl0;
                    *reinterpret_cast<__nv_bfloat162*>(dh + o + 8 * HEAD_DIM)  = ph1;
                    *reinterpret_cast<__nv_bfloat162*>(dl + o + 8 * HEAD_DIM)  = pl1;
                } else {
                    // V transposed: [bh][d][s]
                    size_t ob = (size_t)bh * HEAD_DIM * SEQ;
                    size_t o0 = ob + (size_t)d * SEQ + sq;
                    size_t o1 = ob + (size_t)(d + 1) * SEQ + sq;
                    g_vth[o0]     = h0;  g_vtl[o0]     = l0;
                    g_vth[o1]     = h1;  g_vtl[o1]     = l1;
                    g_vth[o0 + 8] = h2;  g_vtl[o0 + 8] = l2;
                    g_vth[o1 + 8] = h3;  g_vtl[o1 + 8] = l3;
                }
            }
        }
    }
}

// ---------------------------------------------------------------------------
// Tensor-core flash attention. 2-stage KV pipeline, Q in smem, 2 CTAs/SM.
// ---------------------------------------------------------------------------
static constexpr int AT_STRIDE = 144;
static constexpr int AT_TILE   = 64 * AT_STRIDE;    // 9216
static constexpr int AT_STAGE  = 4 * AT_TILE;       // 36864
static constexpr int Q_TILE    = 128 * AT_STRIDE;   // 18432
static constexpr int QS_OFF    = 2 * AT_STAGE;      // 73728
static constexpr int AT_SMEM   = QS_OFF + 2 * Q_TILE;  // 110592 (x2 = 221184)

__global__ __launch_bounds__(256, 2)
void attn_tc_kernel()
{
    extern __shared__ char smem[];
    const uint32_t sb = smem_to_u32(smem);
    const int t    = threadIdx.x;
    const int wid  = t >> 5;
    const int lane = t & 31;
    const int g    = lane >> 2;
    const int tq   = lane & 3;
    const int bh   = blockIdx.y;
    const int q0   = blockIdx.x * 128;
    const int wrow = wid * 16;

    const int sel  = lane >> 3;
    const int lrow = lane & 7;
    const int a_row_off = ((sel & 1) ? 8 : 0) + lrow;
    const int a_kc      = sel >> 1;
    const int b_row_off = ((sel >> 1) ? 8 : 0) + lrow;
    const int b_kc      = sel & 1;

    // Q tile load into smem (hi+lo)
    {
        const char* baseQh = (const char*)(g_qh + ((size_t)bh * SEQ + q0) * HEAD_DIM);
        const char* baseQl = (const char*)(g_ql + ((size_t)bh * SEQ + q0) * HEAD_DIM);
#pragma unroll
        for (int i = 0; i < 4; i++) {
            int idx = t + i * 256;
            int r = idx >> 3, c16 = (idx & 7) * 16;
            cp_async16(sb + QS_OFF + r * AT_STRIDE + c16, baseQh + (size_t)r * 128 + c16);
            cp_async16(sb + QS_OFF + Q_TILE + r * AT_STRIDE + c16, baseQl + (size_t)r * 128 + c16);
        }
    }

    auto load_stage = [&](int s, int kk0) {
        const char* baseK  = (const char*)(g_kh + ((size_t)bh * SEQ + kk0) * HEAD_DIM);
        const char* baseKl = (const char*)(g_kl + ((size_t)bh * SEQ + kk0) * HEAD_DIM);
        const char* baseV  = (const char*)(g_vth + (size_t)bh * HEAD_DIM * SEQ + kk0);
        const char* baseVl = (const char*)(g_vtl + (size_t)bh * HEAD_DIM * SEQ + kk0);
#pragma unroll
        for (int i = 0; i < 8; i++) {
            int idx = t + i * 256;
            int tensor = idx >> 9;
            int rem = idx & 511;
            int r = rem >> 3;
            int c16 = (rem & 7) * 16;
            const char* src;
            if (tensor == 0)      src = baseK  + (size_t)r * 128 + c16;
            else if (tensor == 1) src = baseKl + (size_t)r * 128 + c16;
            else if (tensor == 2) src = baseV  + (size_t)r * (SEQ * 2) + c16;
            else                  src = baseVl + (size_t)r * (SEQ * 2) + c16;
            cp_async16(sb + s * AT_STAGE + tensor * AT_TILE + r * AT_STRIDE + c16, src);
        }
    };

    float o[8][4];
#pragma unroll
    for (int i = 0; i < 8; i++)
#pragma unroll
        for (int j = 0; j < 4; j++) o[i][j] = 0.0f;
    float m0 = -CUDART_INF_F, m1 = -CUDART_INF_F, l0 = 0.0f, l1 = 0.0f;

    load_stage(0, 0);  CP_COMMIT();
    load_stage(1, 64); CP_COMMIT();

    const int nkt = SEQ / 64;
    for (int kt = 0; kt < nkt; kt++) {
        CP_WAIT1();
        __syncthreads();
        const uint32_t st = sb + (kt & 1) * AT_STAGE;

        // ---- S = Q K^T ----
        float s[8][4];
#pragma unroll
        for (int i = 0; i < 8; i++)
#pragma unroll
            for (int j = 0; j < 4; j++) s[i][j] = 0.0f;
#pragma unroll
        for (int ks = 0; ks < 4; ks++) {
            const uint32_t kbyte = ks * 32;
            const uint32_t qaddr = sb + QS_OFF + (wrow + a_row_off) * AT_STRIDE
                                   + kbyte + a_kc * 16;
            uint32_t qh4[4], ql4[4];
            ldsm_x4(qh4, qaddr);
            ldsm_x4(ql4, qaddr + Q_TILE);
            uint32_t kf[4][4], klf[4][4];
#pragma unroll
            for (int ng = 0; ng < 4; ng++)
                ldsm_x4(kf[ng], st + (ng * 16 + b_row_off) * AT_STRIDE + kbyte + b_kc * 16);
#pragma unroll
            for (int ng = 0; ng < 4; ng++)
                ldsm_x4(klf[ng], st + AT_TILE + (ng * 16 + b_row_off) * AT_STRIDE + kbyte + b_kc * 16);
#pragma unroll
            for (int ng = 0; ng < 4; ng++) {
                mma_bf16(s[ng * 2],     qh4, &kf[ng][0]);
                mma_bf16(s[ng * 2 + 1], qh4, &kf[ng][2]);
            }
#pragma unroll
            for (int ng = 0; ng < 4; ng++) {
                mma_bf16(s[ng * 2],     ql4, &kf[ng][0]);
                mma_bf16(s[ng * 2 + 1], ql4, &kf[ng][2]);
            }
#pragma unroll
            for (int ng = 0; ng < 4; ng++) {
                mma_bf16(s[ng * 2],     qh4, &klf[ng][0]);
                mma_bf16(s[ng * 2 + 1], qh4, &klf[ng][2]);
            }
        }

        // ---- online softmax ----
        float mt0 = -CUDART_INF_F, mt1 = -CUDART_INF_F;
#pragma unroll
        for (int nt = 0; nt < 8; nt++) {
            mt0 = fmaxf(mt0, fmaxf(s[nt][0], s[nt][1]));
            mt1 = fmaxf(mt1, fmaxf(s[nt][2], s[nt][3]));
        }
        mt0 = fmaxf(mt0, __shfl_xor_sync(0xFFFFFFFF, mt0, 1));
        mt0 = fmaxf(mt0, __shfl_xor_sync(0xFFFFFFFF, mt0, 2));
        mt1 = fmaxf(mt1, __shfl_xor_sync(0xFFFFFFFF, mt1, 1));
        mt1 = fmaxf(mt1, __shfl_xor_sync(0xFFFFFFFF, mt1, 2));
        float mn0 = fmaxf(m0, mt0), mn1 = fmaxf(m1, mt1);
        float c0 = __expf(m0 - mn0), c1 = __expf(m1 - mn1);
        m0 = mn0; m1 = mn1;
        float ls0 = 0.0f, ls1 = 0.0f;
#pragma unroll
        for (int nt = 0; nt < 8; nt++) {
            s[nt][0] = __expf(s[nt][0] - m0);
            s[nt][1] = __expf(s[nt][1] - m0);
            s[nt][2] = __expf(s[nt][2] - m1);
            s[nt][3] = __expf(s[nt][3] - m1);
            ls0 += s[nt][0] + s[nt][1];
            ls1 += s[nt][2] + s[nt][3];
        }
        l0 = l0 * c0 + ls0;
        l1 = l1 * c1 + ls1;
#pragma unroll
        for (int nt = 0; nt < 8; nt++) {
            o[nt][0] *= c0; o[nt][1] *= c0;
            o[nt][2] *= c1; o[nt][3] *= c1;
        }

        // ---- O += P V ----
#pragma unroll
        for (int ks = 0; ks < 4; ks++) {
            uint32_t pa_h[4], pa_l[4];
#pragma unroll
            for (int half = 0; half < 2; half++) {
                const float* sp = s[2 * ks + half];
                float h0 = __bfloat162float(__float2bfloat16(sp[0]));
                float h1 = __bfloat162float(__float2bfloat16(sp[1]));
                float h2 = __bfloat162float(__float2bfloat16(sp[2]));
                float h3 = __bfloat162float(__float2bfloat16(sp[3]));
                pa_h[half * 2]     = pack_bf16x2(sp[0], sp[1]);
                pa_h[half * 2 + 1] = pack_bf16x2(sp[2], sp[3]);
                pa_l[half * 2]     = pack_bf16x2(sp[0] - h0, sp[1] - h1);
                pa_l[half * 2 + 1] = pack_bf16x2(sp[2] - h2, sp[3] - h3);
            }
            const uint32_t kbyte = ks * 32 + b_kc * 16;
            uint32_t vf[4][4], vlf[4][4];
#pragma unroll
            for (int ng = 0; ng < 4; ng++)
                ldsm_x4(vf[ng], st + 2 * AT_TILE + (ng * 16 + b_row_off) * AT_STRIDE + kbyte);
#pragma unroll
            for (int ng = 0; ng < 4; ng++)
                ldsm_x4(vlf[ng], st + 3 * AT_TILE + (ng * 16 + b_row_off) * AT_STRIDE + kbyte);
#pragma unroll
            for (int ng = 0; ng < 4; ng++) {
                mma_bf16(o[ng * 2],     pa_h, &vf[ng][0]);
                mma_bf16(o[ng * 2 + 1], pa_h, &vf[ng][2]);
            }
#pragma unroll
            for (int ng = 0; ng < 4; ng++) {
                mma_bf16(o[ng * 2],     pa_l, &vf[ng][0]);
                mma_bf16(o[ng * 2 + 1], pa_l, &vf[ng][2]);
            }
#pragma unroll
            for (int ng = 0; ng < 4; ng++) {
                mma_bf16(o[ng * 2],     pa_h, &vlf[ng][0]);
                mma_bf16(o[ng * 2 + 1], pa_h, &vlf[ng][2]);
            }
        }
        __syncthreads();
        if (kt + 2 < nkt) load_stage(kt & 1, (kt + 2) * 64);
        CP_COMMIT();
    }
    CP_WAIT0();

    // ---- finalize: write split bf16 z directly ----
    l0 += __shfl_xor_sync(0xFFFFFFFF, l0, 1);
    l0 += __shfl_xor_sync(0xFFFFFFFF, l0, 2);
    l1 += __shfl_xor_sync(0xFFFFFFFF, l1, 1);
    l1 += __shfl_xor_sync(0xFFFFFFFF, l1, 2);
    float inv0 = 1.0f / l0, inv1 = 1.0f / l1;

    const int b = bh >> 4, h = bh & 15;
    const size_t tok0 = (size_t)b * SEQ + q0 + wrow + g;
#pragma unroll
    for (int nt = 0; nt < 8; nt++) {
        int col = h * HEAD_DIM + nt * 8 + tq * 2;
        float a0 = o[nt][0] * inv0, a1 = o[nt][1] * inv0;
        float a2 = o[nt][2] * inv1, a3 = o[nt][3] * inv1;
        __nv_bfloat16 h0 = __float2bfloat16(a0), h1 = __float2bfloat16(a1);
        __nv_bfloat16 h2 = __float2bfloat16(a2), h3 = __float2bfloat16(a3);
        __nv_bfloat162 ph0; ph0.x = h0; ph0.y = h1;
        __nv_bfloat162 ph1; ph1.x = h2; ph1.y = h3;
        __nv_bfloat162 pl0, pl1;
        pl0.x = __float2bfloat16(a0 - __bfloat162float(h0));
        pl0.y = __float2bfloat16(a1 - __bfloat162float(h1));
        pl1.x = __float2bfloat16(a2 - __bfloat162float(h2));
        pl1.y = __float2bfloat16(a3 - __bfloat162float(h3));
        *reinterpret_cast<__nv_bfloat162*>(g_zh + tok0 * MODEL_DIM + col)       = ph0;
        *reinterpret_cast<__nv_bfloat162*>(g_zl + tok0 * MODEL_DIM + col)       = pl0;
        *reinterpret_cast<__nv_bfloat162*>(g_zh + (tok0 + 8) * MODEL_DIM + col) = ph1;
        *reinterpret_cast<__nv_bfloat162*>(g_zl + (tok0 + 8) * MODEL_DIM + col) = pl1;
    }
}

// ---------------------------------------------------------------------------
// Launch
// ---------------------------------------------------------------------------
extern "C" void kernel_launch(void* const* d_in, const int* in_sizes, int n_in,
                              void* d_out, int out_size)
{
    const float* x     = (const float*)d_in[0];
    const float* w_qkv = (const float*)d_in[1];
    const float* b_qkv = (const float*)d_in[2];
    const float* w_out = (const float*)d_in[3];
    const float* b_out = (const float*)d_in[4];
    float* out = (float*)d_out;

    __nv_bfloat16 *xh, *xl, *zh, *zl, *wqkvT_h, *wqkvT_l, *woutT_h, *woutT_l;
    cudaGetSymbolAddress((void**)&xh, g_xh);
    cudaGetSymbolAddress((void**)&xl, g_xl);
    cudaGetSymbolAddress((void**)&zh, g_zh);
    cudaGetSymbolAddress((void**)&zl, g_zl);
    cudaGetSymbolAddress((void**)&wqkvT_h, g_wqkvT_h);
    cudaGetSymbolAddress((void**)&wqkvT_l, g_wqkvT_l);
    cudaGetSymbolAddress((void**)&woutT_h, g_woutT_h);
    cudaGetSymbolAddress((void**)&woutT_l, g_woutT_l);

    cudaFuncSetAttribute(tc_gemm_kernel<true>,
                         cudaFuncAttributeMaxDynamicSharedMemorySize, GEMM_SMEM);
    cudaFuncSetAttribute(tc_gemm_kernel<false>,
                         cudaFuncAttributeMaxDynamicSharedMemorySize, GEMM_SMEM);
    cudaFuncSetAttribute(attn_tc_kernel,
                         cudaFuncAttributeMaxDynamicSharedMemorySize, AT_SMEM);

    // 0. Preprocess: split x; transpose+split weights
    {
        int n4 = TOK * MODEL_DIM / 4;
        split_kernel<<<(n4 + 255) / 256, 256>>>(x, xh, xl, n4);
        transpose_split_kernel<<<dim3(QKV_DIM / 32, MODEL_DIM / 32), dim3(32, 8)>>>(
            w_qkv, wqkvT_h, wqkvT_l, MODEL_DIM, QKV_DIM);
        transpose_split_kernel<<<dim3(MODEL_DIM / 32, MODEL_DIM / 32), dim3(32, 8)>>>(
            w_out, woutT_h, woutT_l, MODEL_DIM, MODEL_DIM);
    }

    // 1. QKV projection with fused split/transpose epilogue
    tc_gemm_kernel<true><<<dim3(QKV_DIM / 128, TOK / 128), 256, GEMM_SMEM>>>(
        xh, xl, wqkvT_h, wqkvT_l, b_qkv, nullptr, TOK, QKV_DIM, MODEL_DIM);

    // 2. Tensor-core flash attention (writes g_zh/g_zl directly)
    attn_tc_kernel<<<dim3(SEQ / 128, BH), 256, AT_SMEM>>>();

    // 3. Output projection
    tc_gemm_kernel<false><<<dim3(MODEL_DIM / 128, TOK / 128), 256, GEMM_SMEM>>>(
        zh, zl, woutT_h, woutT_l, b_out, out, TOK, MODEL_DIM, MODEL_DIM);
}

// round 12
// speedup vs baseline: 3.8692x; 1.2741x over previous
#include <cuda_runtime.h>
#include <cuda_bf16.h>
#include <cuda_fp16.h>
#include <math_constants.h>
#include <cstdint>

// Problem constants
static constexpr int MODEL_DIM = 1024;
static constexpr int HEAD      = 16;
static constexpr int HEAD_DIM  = 64;
static constexpr int BATCH     = 2;
static constexpr int SEQ       = 2048;
static constexpr int TOK       = BATCH * SEQ;      // 4096
static constexpr int QKV_DIM   = 3 * MODEL_DIM;    // 3072
static constexpr int BH        = BATCH * HEAD;     // 32

// Weight scale trick: store W*1024 in fp16 (keeps lo-part normal); epilogue
// multiplies by 1/1024.
static constexpr float WSCALE     = 1024.0f;
static constexpr float INV_WSCALE = 1.0f / 1024.0f;

// Scratch (__device__ globals; no runtime allocation allowed)
__device__ __half g_x16[TOK * MODEL_DIM];              // x, single fp16
__device__ __half g_z16[TOK * MODEL_DIM];              // attn out, single fp16
__device__ __half g_wqkvT_h[QKV_DIM * MODEL_DIM];      // w^T*1024 hi [N][K]
__device__ __half g_wqkvT_l[QKV_DIM * MODEL_DIM];      // w^T*1024 lo
__device__ __half g_woutT_h[MODEL_DIM * MODEL_DIM];
__device__ __half g_woutT_l[MODEL_DIM * MODEL_DIM];
// Attention operands, split bf16 (3-pass path unchanged). Q pre-scaled 0.125.
__device__ __nv_bfloat16 g_qh[BH * SEQ * HEAD_DIM];    // [bh][s][d]
__device__ __nv_bfloat16 g_ql[BH * SEQ * HEAD_DIM];
__device__ __nv_bfloat16 g_kh[BH * SEQ * HEAD_DIM];    // [bh][s][d]
__device__ __nv_bfloat16 g_kl[BH * SEQ * HEAD_DIM];
__device__ __nv_bfloat16 g_vth[BH * HEAD_DIM * SEQ];   // [bh][d][s]
__device__ __nv_bfloat16 g_vtl[BH * HEAD_DIM * SEQ];

// ---------------------------------------------------------------------------
// PTX helpers (sm_80-compatible)
// ---------------------------------------------------------------------------
__device__ __forceinline__ uint32_t smem_to_u32(const void* p) {
    uint32_t a;
    asm("{ .reg .u64 tmp; cvta.to.shared.u64 tmp, %1; cvt.u32.u64 %0, tmp; }"
        : "=r"(a) : "l"(p));
    return a;
}
__device__ __forceinline__ void ldsm_x4(uint32_t* r, uint32_t addr) {
    asm volatile("ldmatrix.sync.aligned.m8n8.x4.shared.b16 {%0,%1,%2,%3}, [%4];"
                 : "=r"(r[0]), "=r"(r[1]), "=r"(r[2]), "=r"(r[3]) : "r"(addr));
}
__device__ __forceinline__ void mma_bf16(float* c, const uint32_t* a, const uint32_t* b) {
    asm volatile(
        "mma.sync.aligned.m16n8k16.row.col.f32.bf16.bf16.f32 "
        "{%0,%1,%2,%3}, {%4,%5,%6,%7}, {%8,%9}, {%0,%1,%2,%3};"
        : "+f"(c[0]), "+f"(c[1]), "+f"(c[2]), "+f"(c[3])
        : "r"(a[0]), "r"(a[1]), "r"(a[2]), "r"(a[3]), "r"(b[0]), "r"(b[1]));
}
__device__ __forceinline__ void mma_f16(float* c, const uint32_t* a, const uint32_t* b) {
    asm volatile(
        "mma.sync.aligned.m16n8k16.row.col.f32.f16.f16.f32 "
        "{%0,%1,%2,%3}, {%4,%5,%6,%7}, {%8,%9}, {%0,%1,%2,%3};"
        : "+f"(c[0]), "+f"(c[1]), "+f"(c[2]), "+f"(c[3])
        : "r"(a[0]), "r"(a[1]), "r"(a[2]), "r"(a[3]), "r"(b[0]), "r"(b[1]));
}
__device__ __forceinline__ void cp_async16(uint32_t dst, const void* src) {
    asm volatile("cp.async.cg.shared.global [%0], [%1], 16;" :: "r"(dst), "l"(src));
}
#define CP_COMMIT() asm volatile("cp.async.commit_group;" ::: "memory")
#define CP_WAIT1()  asm volatile("cp.async.wait_group 1;" ::: "memory")
#define CP_WAIT0()  asm volatile("cp.async.wait_group 0;" ::: "memory")
__device__ __forceinline__ uint32_t pack_bf16x2(float lo, float hi) {
    uint32_t r;
    asm("cvt.rn.bf16x2.f32 %0, %1, %2;" : "=r"(r) : "f"(hi), "f"(lo));
    return r;
}

// ---------------------------------------------------------------------------
// x convert: fp32 -> single fp16
// ---------------------------------------------------------------------------
__global__ void convert_f16_kernel(const float* __restrict__ X,
                                   __half* __restrict__ X16, int n4)
{
    int i = blockIdx.x * blockDim.x + threadIdx.x;
    if (i >= n4) return;
    float4 v = reinterpret_cast<const float4*>(X)[i];
    __half2 p0; p0.x = __float2half(v.x); p0.y = __float2half(v.y);
    __half2 p1; p1.x = __float2half(v.z); p1.y = __float2half(v.w);
    reinterpret_cast<__half2*>(X16)[i * 2]     = p0;
    reinterpret_cast<__half2*>(X16)[i * 2 + 1] = p1;
}

// ---------------------------------------------------------------------------
// Weight transpose + fp16 split with x1024 scale: W[K][N] -> Th/Tl[N][K]
// ---------------------------------------------------------------------------
__global__ void transpose_split_f16_kernel(const float* __restrict__ W,
                                           __half* __restrict__ Th,
                                           __half* __restrict__ Tl,
                                           int K, int N)
{
    __shared__ float tile[32][33];
    const int n0 = blockIdx.x * 32, k0 = blockIdx.y * 32;
    const int tx = threadIdx.x, ty = threadIdx.y;
#pragma unroll
    for (int i = 0; i < 32; i += 8)
        tile[ty + i][tx] = W[(size_t)(k0 + ty + i) * N + n0 + tx];
    __syncthreads();
#pragma unroll
    for (int i = 0; i < 32; i += 8) {
        float v = tile[tx][ty + i] * WSCALE;
        __half h = __float2half(v);
        __half l = __float2half(v - __half2float(h));
        size_t o = (size_t)(n0 + ty + i) * K + k0 + tx;
        Th[o] = h;
        Tl[o] = l;
    }
}

// ---------------------------------------------------------------------------
// fp16 2-pass GEMM: C = A[M,K](fp16) @ (Bh+Bl)^T /1024 + bias
// BM=BN=128, BK=64. 2-stage cp.async pipeline, 2 CTAs/SM.
// QKV_EPI=true: fused epilogue writing split-bf16 attention operand layouts.
// ---------------------------------------------------------------------------
static constexpr int TSTRIDE   = 144;                 // 128B data + 16B pad
static constexpr int TILE_B    = 128 * TSTRIDE;       // 18432
static constexpr int STAGE_B   = 3 * TILE_B;          // A,Bh,Bl = 55296
static constexpr int GEMM_SMEM = 2 * STAGE_B;         // 110592 (x2 CTA = 221184)

template <bool QKV_EPI>
__global__ __launch_bounds__(256, 2)
void tc_gemm_kernel(const __half* __restrict__ A,
                    const __half* __restrict__ Bh,
                    const __half* __restrict__ Bl,
                    const float* __restrict__ bias,
                    float* __restrict__ C,
                    int M, int N, int K)
{
    extern __shared__ char smem[];
    const uint32_t sb = smem_to_u32(smem);
    const int t    = threadIdx.x;
    const int wid  = t >> 5;
    const int lane = t & 31;
    const int wm   = wid & 1;
    const int wn   = wid >> 1;
    const int bm   = blockIdx.y * 128;
    const int bn   = blockIdx.x * 128;

    // loader: 3 tiles x 1024 chunks of 16B = 3072 chunks; 12 per thread
    auto stage_load = [&](int s, int k0) {
#pragma unroll
        for (int i = 0; i < 12; i++) {
            int idx = t + i * 256;            // 0..3071
            int tensor = idx >> 10;           // 0=A 1=Bh 2=Bl
            int rem = idx & 1023;
            int r = rem >> 3;                 // 0..127
            int c16 = (rem & 7) * 16;         // 0..112
            const char* src;
            if (tensor == 0)      src = (const char*)(A  + (size_t)(bm + r) * K + k0) + c16;
            else if (tensor == 1) src = (const char*)(Bh + (size_t)(bn + r) * K + k0) + c16;
            else                  src = (const char*)(Bl + (size_t)(bn + r) * K + k0) + c16;
            cp_async16(sb + s * STAGE_B + tensor * TILE_B + r * TSTRIDE + c16, src);
        }
    };

    float acc[4][4][4];
#pragma unroll
    for (int i = 0; i < 4; i++)
#pragma unroll
        for (int j = 0; j < 4; j++)
#pragma unroll
            for (int k = 0; k < 4; k++) acc[i][j][k] = 0.0f;

    stage_load(0, 0);  CP_COMMIT();
    stage_load(1, 64); CP_COMMIT();

    const int sel  = lane >> 3;
    const int lrow = lane & 7;
    const int a_row_off = ((sel & 1) ? 8 : 0) + lrow;
    const int a_kc      = sel >> 1;
    const int b_row_off = ((sel >> 1) ? 8 : 0) + lrow;
    const int b_kc      = sel & 1;

    const int nch = K / 64;
    for (int ch = 0; ch < nch; ch++) {
        CP_WAIT1();
        __syncthreads();
        const uint32_t st = sb + (ch & 1) * STAGE_B;

#pragma unroll
        for (int ks = 0; ks < 4; ks++) {
            const uint32_t kbyte = ks * 32;
            uint32_t af[4][4], bhf[2][4], blf[2][4];
#pragma unroll
            for (int mt = 0; mt < 4; mt++)
                ldsm_x4(af[mt], st + (wm * 64 + mt * 16 + a_row_off) * TSTRIDE
                                   + kbyte + a_kc * 16);
#pragma unroll
            for (int p = 0; p < 2; p++)
                ldsm_x4(bhf[p], st + TILE_B
                                   + (wn * 32 + p * 16 + b_row_off) * TSTRIDE
                                   + kbyte + b_kc * 16);
#pragma unroll
            for (int mt = 0; mt < 4; mt++)
#pragma unroll
                for (int nt = 0; nt < 4; nt++)
                    mma_f16(acc[mt][nt], af[mt], &bhf[nt >> 1][(nt & 1) * 2]);
#pragma unroll
            for (int p = 0; p < 2; p++)
                ldsm_x4(blf[p], st + 2 * TILE_B
                                   + (wn * 32 + p * 16 + b_row_off) * TSTRIDE
                                   + kbyte + b_kc * 16);
#pragma unroll
            for (int mt = 0; mt < 4; mt++)
#pragma unroll
                for (int nt = 0; nt < 4; nt++)
                    mma_f16(acc[mt][nt], af[mt], &blf[nt >> 1][(nt & 1) * 2]);
        }
        __syncthreads();
        if (ch + 2 < nch) stage_load(ch & 1, (ch + 2) * 64);
        CP_COMMIT();
    }
    CP_WAIT0();

    const int g  = lane >> 2;
    const int tq = lane & 3;

    if constexpr (!QKV_EPI) {
        // out-projection: fp32 C = acc/1024 + bias
#pragma unroll
        for (int mt = 0; mt < 4; mt++) {
#pragma unroll
            for (int nt = 0; nt < 4; nt++) {
                int row = bm + wm * 64 + mt * 16 + g;
                int col = bn + wn * 32 + nt * 8 + tq * 2;
                float b0 = bias[col], b1 = bias[col + 1];
                float2 v0 = make_float2(fmaf(acc[mt][nt][0], INV_WSCALE, b0),
                                        fmaf(acc[mt][nt][1], INV_WSCALE, b1));
                float2 v1 = make_float2(fmaf(acc[mt][nt][2], INV_WSCALE, b0),
                                        fmaf(acc[mt][nt][3], INV_WSCALE, b1));
                *reinterpret_cast<float2*>(C + (size_t)row * N + col)       = v0;
                *reinterpret_cast<float2*>(C + (size_t)(row + 8) * N + col) = v1;
            }
        }
    } else {
        // Fused QKV epilogue: write split bf16 attention operands directly.
        const int sec = bn >> 10;              // 0=q, 1=k, 2=v
#pragma unroll
        for (int mt = 0; mt < 4; mt++) {
#pragma unroll
            for (int nt = 0; nt < 4; nt++) {
                int row = bm + wm * 64 + mt * 16 + g;         // token
                int col = bn + wn * 32 + nt * 8 + tq * 2;     // global qkv col
                float b0 = bias[col], b1 = bias[col + 1];
                float v0 = fmaf(acc[mt][nt][0], INV_WSCALE, b0);
                float v1 = fmaf(acc[mt][nt][1], INV_WSCALE, b1);
                float v2 = fmaf(acc[mt][nt][2], INV_WSCALE, b0);
                float v3 = fmaf(acc[mt][nt][3], INV_WSCALE, b1);
                if (sec == 0) { v0 *= 0.125f; v1 *= 0.125f; v2 *= 0.125f; v3 *= 0.125f; }
                __nv_bfloat16 h0 = __float2bfloat16(v0), h1 = __float2bfloat16(v1);
                __nv_bfloat16 h2 = __float2bfloat16(v2), h3 = __float2bfloat16(v3);
                __nv_bfloat16 l0 = __float2bfloat16(v0 - __bfloat162float(h0));
                __nv_bfloat16 l1 = __float2bfloat16(v1 - __bfloat162float(h1));
                __nv_bfloat16 l2 = __float2bfloat16(v2 - __bfloat162float(h2));
                __nv_bfloat16 l3 = __float2bfloat16(v3 - __bfloat162float(h3));
                int cc = col & 1023;
                int h  = cc >> 6, d = cc & 63;
                int b  = row >> 11, sq = row & 2047;
                int bh = b * 16 + h;
                if (sec < 2) {
                    __nv_bfloat16* dh = (sec == 0) ? g_qh : g_kh;
                    __nv_bfloat16* dl = (sec == 0) ? g_ql : g_kl;
                    size_t o = ((size_t)bh * SEQ + sq) * HEAD_DIM + d;
                    __nv_bfloat162 ph0; ph0.x = h0; ph0.y = h1;
                    __nv_bfloat162 ph1; ph1.x = h2; ph1.y = h3;
                    __nv_bfloat162 pl0; pl0.x = l0; pl0.y = l1;
                    __nv_bfloat162 pl1; pl1.x = l2; pl1.y = l3;
                    *reinterpret_cast<__nv_bfloat162*>(dh + o)                 = ph0;
                    *reinterpret_cast<__nv_bfloat162*>(dl + o)                 = pl0;
                    *reinterpret_cast<__nv_bfloat162*>(dh + o + 8 * HEAD_DIM)  = ph1;
                    *reinterpret_cast<__nv_bfloat162*>(dl + o + 8 * HEAD_DIM)  = pl1;
                } else {
                    size_t ob = (size_t)bh * HEAD_DIM * SEQ;
                    size_t o0 = ob + (size_t)d * SEQ + sq;
                    size_t o1 = ob + (size_t)(d + 1) * SEQ + sq;
                    g_vth[o0]     = h0;  g_vtl[o0]     = l0;
                    g_vth[o1]     = h1;  g_vtl[o1]     = l1;
                    g_vth[o0 + 8] = h2;  g_vtl[o0 + 8] = l2;
                    g_vth[o1 + 8] = h3;  g_vtl[o1 + 8] = l3;
                }
            }
        }
    }
}

// ---------------------------------------------------------------------------
// Tensor-core flash attention (split bf16, 3-pass) — unchanged mainloop.
// Epilogue writes single-fp16 z for the fp16 out-projection.
// ---------------------------------------------------------------------------
static constexpr int AT_STRIDE = 144;
static constexpr int AT_TILE   = 64 * AT_STRIDE;    // 9216
static constexpr int AT_STAGE  = 4 * AT_TILE;       // 36864
static constexpr int Q_TILE    = 128 * AT_STRIDE;   // 18432
static constexpr int QS_OFF    = 2 * AT_STAGE;      // 73728
static constexpr int AT_SMEM   = QS_OFF + 2 * Q_TILE;  // 110592 (x2 = 221184)

__global__ __launch_bounds__(256, 2)
void attn_tc_kernel()
{
    extern __shared__ char smem[];
    const uint32_t sb = smem_to_u32(smem);
    const int t    = threadIdx.x;
    const int wid  = t >> 5;
    const int lane = t & 31;
    const int g    = lane >> 2;
    const int tq   = lane & 3;
    const int bh   = blockIdx.y;
    const int q0   = blockIdx.x * 128;
    const int wrow = wid * 16;

    const int sel  = lane >> 3;
    const int lrow = lane & 7;
    const int a_row_off = ((sel & 1) ? 8 : 0) + lrow;
    const int a_kc      = sel >> 1;
    const int b_row_off = ((sel >> 1) ? 8 : 0) + lrow;
    const int b_kc      = sel & 1;

    // Q tile load into smem (hi+lo)
    {
        const char* baseQh = (const char*)(g_qh + ((size_t)bh * SEQ + q0) * HEAD_DIM);
        const char* baseQl = (const char*)(g_ql + ((size_t)bh * SEQ + q0) * HEAD_DIM);
#pragma unroll
        for (int i = 0; i < 4; i++) {
            int idx = t + i * 256;
            int r = idx >> 3, c16 = (idx & 7) * 16;
            cp_async16(sb + QS_OFF + r * AT_STRIDE + c16, baseQh + (size_t)r * 128 + c16);
            cp_async16(sb + QS_OFF + Q_TILE + r * AT_STRIDE + c16, baseQl + (size_t)r * 128 + c16);
        }
    }

    auto load_stage = [&](int s, int kk0) {
        const char* baseK  = (const char*)(g_kh + ((size_t)bh * SEQ + kk0) * HEAD_DIM);
        const char* baseKl = (const char*)(g_kl + ((size_t)bh * SEQ + kk0) * HEAD_DIM);
        const char* baseV  = (const char*)(g_vth + (size_t)bh * HEAD_DIM * SEQ + kk0);
        const char* baseVl = (const char*)(g_vtl + (size_t)bh * HEAD_DIM * SEQ + kk0);
#pragma unroll
        for (int i = 0; i < 8; i++) {
            int idx = t + i * 256;
            int tensor = idx >> 9;
            int rem = idx & 511;
            int r = rem >> 3;
            int c16 = (rem & 7) * 16;
            const char* src;
            if (tensor == 0)      src = baseK  + (size_t)r * 128 + c16;
            else if (tensor == 1) src = baseKl + (size_t)r * 128 + c16;
            else if (tensor == 2) src = baseV  + (size_t)r * (SEQ * 2) + c16;
            else                  src = baseVl + (size_t)r * (SEQ * 2) + c16;
            cp_async16(sb + s * AT_STAGE + tensor * AT_TILE + r * AT_STRIDE + c16, src);
        }
    };

    float o[8][4];
#pragma unroll
    for (int i = 0; i < 8; i++)
#pragma unroll
        for (int j = 0; j < 4; j++) o[i][j] = 0.0f;
    float m0 = -CUDART_INF_F, m1 = -CUDART_INF_F, l0 = 0.0f, l1 = 0.0f;

    load_stage(0, 0);  CP_COMMIT();
    load_stage(1, 64); CP_COMMIT();

    const int nkt = SEQ / 64;
    for (int kt = 0; kt < nkt; kt++) {
        CP_WAIT1();
        __syncthreads();
        const uint32_t st = sb + (kt & 1) * AT_STAGE;

        // ---- S = Q K^T (3 passes) ----
        float s[8][4];
#pragma unroll
        for (int i = 0; i < 8; i++)
#pragma unroll
            for (int j = 0; j < 4; j++) s[i][j] = 0.0f;
#pragma unroll
        for (int ks = 0; ks < 4; ks++) {
            const uint32_t kbyte = ks * 32;
            const uint32_t qaddr = sb + QS_OFF + (wrow + a_row_off) * AT_STRIDE
                                   + kbyte + a_kc * 16;
            uint32_t qh4[4], ql4[4];
            ldsm_x4(qh4, qaddr);
            ldsm_x4(ql4, qaddr + Q_TILE);
            uint32_t kf[4][4], klf[4][4];
#pragma unroll
            for (int ng = 0; ng < 4; ng++)
                ldsm_x4(kf[ng], st + (ng * 16 + b_row_off) * AT_STRIDE + kbyte + b_kc * 16);
#pragma unroll
            for (int ng = 0; ng < 4; ng++)
                ldsm_x4(klf[ng], st + AT_TILE + (ng * 16 + b_row_off) * AT_STRIDE + kbyte + b_kc * 16);
#pragma unroll
            for (int ng = 0; ng < 4; ng++) {
                mma_bf16(s[ng * 2],     qh4, &kf[ng][0]);
                mma_bf16(s[ng * 2 + 1], qh4, &kf[ng][2]);
            }
#pragma unroll
            for (int ng = 0; ng < 4; ng++) {
                mma_bf16(s[ng * 2],     ql4, &kf[ng][0]);
                mma_bf16(s[ng * 2 + 1], ql4, &kf[ng][2]);
            }
#pragma unroll
            for (int ng = 0; ng < 4; ng++) {
                mma_bf16(s[ng * 2],     qh4, &klf[ng][0]);
                mma_bf16(s[ng * 2 + 1], qh4, &klf[ng][2]);
            }
        }

        // ---- online softmax ----
        float mt0 = -CUDART_INF_F, mt1 = -CUDART_INF_F;
#pragma unroll
        for (int nt = 0; nt < 8; nt++) {
            mt0 = fmaxf(mt0, fmaxf(s[nt][0], s[nt][1]));
            mt1 = fmaxf(mt1, fmaxf(s[nt][2], s[nt][3]));
        }
        mt0 = fmaxf(mt0, __shfl_xor_sync(0xFFFFFFFF, mt0, 1));
        mt0 = fmaxf(mt0, __shfl_xor_sync(0xFFFFFFFF, mt0, 2));
        mt1 = fmaxf(mt1, __shfl_xor_sync(0xFFFFFFFF, mt1, 1));
        mt1 = fmaxf(mt1, __shfl_xor_sync(0xFFFFFFFF, mt1, 2));
        float mn0 = fmaxf(m0, mt0), mn1 = fmaxf(m1, mt1);
        float c0 = __expf(m0 - mn0), c1 = __expf(m1 - mn1);
        m0 = mn0; m1 = mn1;
        float ls0 = 0.0f, ls1 = 0.0f;
#pragma unroll
        for (int nt = 0; nt < 8; nt++) {
            s[nt][0] = __expf(s[nt][0] - m0);
            s[nt][1] = __expf(s[nt][1] - m0);
            s[nt][2] = __expf(s[nt][2] - m1);
            s[nt][3] = __expf(s[nt][3] - m1);
            ls0 += s[nt][0] + s[nt][1];
            ls1 += s[nt][2] + s[nt][3];
        }
        l0 = l0 * c0 + ls0;
        l1 = l1 * c1 + ls1;
#pragma unroll
        for (int nt = 0; nt < 8; nt++) {
            o[nt][0] *= c0; o[nt][1] *= c0;
            o[nt][2] *= c1; o[nt][3] *= c1;
        }

        // ---- O += P V (3 passes) ----
#pragma unroll
        for (int ks = 0; ks < 4; ks++) {
            uint32_t pa_h[4], pa_l[4];
#pragma unroll
            for (int half = 0; half < 2; half++) {
                const float* sp = s[2 * ks + half];
                float h0 = __bfloat162float(__float2bfloat16(sp[0]));
                float h1 = __bfloat162float(__float2bfloat16(sp[1]));
                float h2 = __bfloat162float(__float2bfloat16(sp[2]));
                float h3 = __bfloat162float(__float2bfloat16(sp[3]));
                pa_h[half * 2]     = pack_bf16x2(sp[0], sp[1]);
                pa_h[half * 2 + 1] = pack_bf16x2(sp[2], sp[3]);
                pa_l[half * 2]     = pack_bf16x2(sp[0] - h0, sp[1] - h1);
                pa_l[half * 2 + 1] = pack_bf16x2(sp[2] - h2, sp[3] - h3);
            }
            const uint32_t kbyte = ks * 32 + b_kc * 16;
            uint32_t vf[4][4], vlf[4][4];
#pragma unroll
            for (int ng = 0; ng < 4; ng++)
                ldsm_x4(vf[ng], st + 2 * AT_TILE + (ng * 16 + b_row_off) * AT_STRIDE + kbyte);
#pragma unroll
            for (int ng = 0; ng < 4; ng++)
                ldsm_x4(vlf[ng], st + 3 * AT_TILE + (ng * 16 + b_row_off) * AT_STRIDE + kbyte);
#pragma unroll
            for (int ng = 0; ng < 4; ng++) {
                mma_bf16(o[ng * 2],     pa_h, &vf[ng][0]);
                mma_bf16(o[ng * 2 + 1], pa_h, &vf[ng][2]);
            }
#pragma unroll
            for (int ng = 0; ng < 4; ng++) {
                mma_bf16(o[ng * 2],     pa_l, &vf[ng][0]);
                mma_bf16(o[ng * 2 + 1], pa_l, &vf[ng][2]);
            }
#pragma unroll
            for (int ng = 0; ng < 4; ng++) {
                mma_bf16(o[ng * 2],     pa_h, &vlf[ng][0]);
                mma_bf16(o[ng * 2 + 1], pa_h, &vlf[ng][2]);
            }
        }
        __syncthreads();
        if (kt + 2 < nkt) load_stage(kt & 1, (kt + 2) * 64);
        CP_COMMIT();
    }
    CP_WAIT0();

    // ---- finalize: write single fp16 z ----
    l0 += __shfl_xor_sync(0xFFFFFFFF, l0, 1);
    l0 += __shfl_xor_sync(0xFFFFFFFF, l0, 2);
    l1 += __shfl_xor_sync(0xFFFFFFFF, l1, 1);
    l1 += __shfl_xor_sync(0xFFFFFFFF, l1, 2);
    float inv0 = 1.0f / l0, inv1 = 1.0f / l1;

    const int b = bh >> 4, h = bh & 15;
    const size_t tok0 = (size_t)b * SEQ + q0 + wrow + g;
#pragma unroll
    for (int nt = 0; nt < 8; nt++) {
        int col = h * HEAD_DIM + nt * 8 + tq * 2;
        __half2 p0, p1;
        p0.x = __float2half(o[nt][0] * inv0);
        p0.y = __float2half(o[nt][1] * inv0);
        p1.x = __float2half(o[nt][2] * inv1);
        p1.y = __float2half(o[nt][3] * inv1);
        *reinterpret_cast<__half2*>(g_z16 + tok0 * MODEL_DIM + col)       = p0;
        *reinterpret_cast<__half2*>(g_z16 + (tok0 + 8) * MODEL_DIM + col) = p1;
    }
}

// ---------------------------------------------------------------------------
// Launch
// ---------------------------------------------------------------------------
extern "C" void kernel_launch(void* const* d_in, const int* in_sizes, int n_in,
                              void* d_out, int out_size)
{
    const float* x     = (const float*)d_in[0];
    const float* w_qkv = (const float*)d_in[1];
    const float* b_qkv = (const float*)d_in[2];
    const float* w_out = (const float*)d_in[3];
    const float* b_out = (const float*)d_in[4];
    float* out = (float*)d_out;

    __half *x16, *z16, *wqkvT_h, *wqkvT_l, *woutT_h, *woutT_l;
    cudaGetSymbolAddress((void**)&x16, g_x16);
    cudaGetSymbolAddress((void**)&z16, g_z16);
    cudaGetSymbolAddress((void**)&wqkvT_h, g_wqkvT_h);
    cudaGetSymbolAddress((void**)&wqkvT_l, g_wqkvT_l);
    cudaGetSymbolAddress((void**)&woutT_h, g_woutT_h);
    cudaGetSymbolAddress((void**)&woutT_l, g_woutT_l);

    cudaFuncSetAttribute(tc_gemm_kernel<true>,
                         cudaFuncAttributeMaxDynamicSharedMemorySize, GEMM_SMEM);
    cudaFuncSetAttribute(tc_gemm_kernel<false>,
                         cudaFuncAttributeMaxDynamicSharedMemorySize, GEMM_SMEM);
    cudaFuncSetAttribute(attn_tc_kernel,
                         cudaFuncAttributeMaxDynamicSharedMemorySize, AT_SMEM);

    // 0. Preprocess: x -> fp16; weights -> transposed fp16 hi/lo (x1024)
    {
        int n4 = TOK * MODEL_DIM / 4;
        convert_f16_kernel<<<(n4 + 255) / 256, 256>>>(x, x16, n4);
        transpose_split_f16_kernel<<<dim3(QKV_DIM / 32, MODEL_DIM / 32), dim3(32, 8)>>>(
            w_qkv, wqkvT_h, wqkvT_l, MODEL_DIM, QKV_DIM);
        transpose_split_f16_kernel<<<dim3(MODEL_DIM / 32, MODEL_DIM / 32), dim3(32, 8)>>>(
            w_out, woutT_h, woutT_l, MODEL_DIM, MODEL_DIM);
    }

    // 1. QKV projection (fp16 2-pass) with fused split/transpose epilogue
    tc_gemm_kernel<true><<<dim3(QKV_DIM / 128, TOK / 128), 256, GEMM_SMEM>>>(
        x16, wqkvT_h, wqkvT_l, b_qkv, nullptr, TOK, QKV_DIM, MODEL_DIM);

    // 2. Tensor-core flash attention (bf16 3-pass; writes fp16 z)
    attn_tc_kernel<<<dim3(SEQ / 128, BH), 256, AT_SMEM>>>();

    // 3. Output projection (fp16 2-pass)
    tc_gemm_kernel<false><<<dim3(MODEL_DIM / 128, TOK / 128), 256, GEMM_SMEM>>>(
        z16, woutT_h, woutT_l, b_out, out, TOK, MODEL_DIM, MODEL_DIM);
}

// round 13
// speedup vs baseline: 4.5614x; 1.1789x over previous
#include <cuda_runtime.h>
#include <cuda_bf16.h>
#include <cuda_fp16.h>
#include <math_constants.h>
#include <cstdint>

// Problem constants
static constexpr int MODEL_DIM = 1024;
static constexpr int HEAD      = 16;
static constexpr int HEAD_DIM  = 64;
static constexpr int BATCH     = 2;
static constexpr int SEQ       = 2048;
static constexpr int TOK       = BATCH * SEQ;      // 4096
static constexpr int QKV_DIM   = 3 * MODEL_DIM;    // 3072
static constexpr int BH        = BATCH * HEAD;     // 32

// Scale tricks: weights and V stored x1024 (keeps fp16 lo-parts normal);
// Q stored x128 (= 0.125 softmax scale x 1024). Descale via INV_WSCALE.
static constexpr float WSCALE     = 1024.0f;
static constexpr float INV_WSCALE = 1.0f / 1024.0f;

// Scratch (__device__ globals; no runtime allocation allowed)
__device__ __half g_x16[TOK * MODEL_DIM];              // x, single fp16
__device__ __half g_z16[TOK * MODEL_DIM];              // attn out, single fp16
__device__ __half g_wqkvT_h[QKV_DIM * MODEL_DIM];      // w^T*1024 hi [N][K]
__device__ __half g_wqkvT_l[QKV_DIM * MODEL_DIM];      // w^T*1024 lo
__device__ __half g_woutT_h[MODEL_DIM * MODEL_DIM];
__device__ __half g_woutT_l[MODEL_DIM * MODEL_DIM];
// Attention operands (fp16): Q split x128; K single; V^T split x1024.
__device__ __half g_qh[BH * SEQ * HEAD_DIM];   // [bh][s][d]
__device__ __half g_ql[BH * SEQ * HEAD_DIM];
__device__ __half g_k16[BH * SEQ * HEAD_DIM];  // [bh][s][d]
__device__ __half g_vth[BH * HEAD_DIM * SEQ];  // [bh][d][s]
__device__ __half g_vtl[BH * HEAD_DIM * SEQ];

// ---------------------------------------------------------------------------
// PTX helpers (sm_80-compatible)
// ---------------------------------------------------------------------------
__device__ __forceinline__ uint32_t smem_to_u32(const void* p) {
    uint32_t a;
    asm("{ .reg .u64 tmp; cvta.to.shared.u64 tmp, %1; cvt.u32.u64 %0, tmp; }"
        : "=r"(a) : "l"(p));
    return a;
}
__device__ __forceinline__ void ldsm_x4(uint32_t* r, uint32_t addr) {
    asm volatile("ldmatrix.sync.aligned.m8n8.x4.shared.b16 {%0,%1,%2,%3}, [%4];"
                 : "=r"(r[0]), "=r"(r[1]), "=r"(r[2]), "=r"(r[3]) : "r"(addr));
}
__device__ __forceinline__ void mma_f16(float* c, const uint32_t* a, const uint32_t* b) {
    asm volatile(
        "mma.sync.aligned.m16n8k16.row.col.f32.f16.f16.f32 "
        "{%0,%1,%2,%3}, {%4,%5,%6,%7}, {%8,%9}, {%0,%1,%2,%3};"
        : "+f"(c[0]), "+f"(c[1]), "+f"(c[2]), "+f"(c[3])
        : "r"(a[0]), "r"(a[1]), "r"(a[2]), "r"(a[3]), "r"(b[0]), "r"(b[1]));
}
__device__ __forceinline__ void cp_async16(uint32_t dst, const void* src) {
    asm volatile("cp.async.cg.shared.global [%0], [%1], 16;" :: "r"(dst), "l"(src));
}
#define CP_COMMIT() asm volatile("cp.async.commit_group;" ::: "memory")
#define CP_WAIT1()  asm volatile("cp.async.wait_group 1;" ::: "memory")
#define CP_WAIT0()  asm volatile("cp.async.wait_group 0;" ::: "memory")
__device__ __forceinline__ uint32_t pack_f16x2(float lo, float hi) {
    uint32_t r;
    asm("cvt.rn.f16x2.f32 %0, %1, %2;" : "=r"(r) : "f"(hi), "f"(lo));
    return r;
}

// ---------------------------------------------------------------------------
// x convert: fp32 -> single fp16
// ---------------------------------------------------------------------------
__global__ void convert_f16_kernel(const float* __restrict__ X,
                                   __half* __restrict__ X16, int n4)
{
    int i = blockIdx.x * blockDim.x + threadIdx.x;
    if (i >= n4) return;
    float4 v = reinterpret_cast<const float4*>(X)[i];
    __half2 p0; p0.x = __float2half(v.x); p0.y = __float2half(v.y);
    __half2 p1; p1.x = __float2half(v.z); p1.y = __float2half(v.w);
    reinterpret_cast<__half2*>(X16)[i * 2]     = p0;
    reinterpret_cast<__half2*>(X16)[i * 2 + 1] = p1;
}

// ---------------------------------------------------------------------------
// Weight transpose + fp16 split with x1024 scale: W[K][N] -> Th/Tl[N][K]
// ---------------------------------------------------------------------------
__global__ void transpose_split_f16_kernel(const float* __restrict__ W,
                                           __half* __restrict__ Th,
                                           __half* __restrict__ Tl,
                                           int K, int N)
{
    __shared__ float tile[32][33];
    const int n0 = blockIdx.x * 32, k0 = blockIdx.y * 32;
    const int tx = threadIdx.x, ty = threadIdx.y;
#pragma unroll
    for (int i = 0; i < 32; i += 8)
        tile[ty + i][tx] = W[(size_t)(k0 + ty + i) * N + n0 + tx];
    __syncthreads();
#pragma unroll
    for (int i = 0; i < 32; i += 8) {
        float v = tile[tx][ty + i] * WSCALE;
        __half h = __float2half(v);
        __half l = __float2half(v - __half2float(h));
        size_t o = (size_t)(n0 + ty + i) * K + k0 + tx;
        Th[o] = h;
        Tl[o] = l;
    }
}

// ---------------------------------------------------------------------------
// fp16 2-pass GEMM: C = A[M,K](fp16) @ (Bh+Bl)^T /1024 + bias
// BM=BN=128, BK=64. 2-stage cp.async pipeline, 2 CTAs/SM.
// QKV_EPI=true: fused epilogue writing fp16 attention operand layouts.
// ---------------------------------------------------------------------------
static constexpr int TSTRIDE   = 144;                 // 128B data + 16B pad
static constexpr int TILE_B    = 128 * TSTRIDE;       // 18432
static constexpr int STAGE_B   = 3 * TILE_B;          // A,Bh,Bl = 55296
static constexpr int GEMM_SMEM = 2 * STAGE_B;         // 110592 (x2 CTA = 221184)

template <bool QKV_EPI>
__global__ __launch_bounds__(256, 2)
void tc_gemm_kernel(const __half* __restrict__ A,
                    const __half* __restrict__ Bh,
                    const __half* __restrict__ Bl,
                    const float* __restrict__ bias,
                    float* __restrict__ C,
                    int M, int N, int K)
{
    extern __shared__ char smem[];
    const uint32_t sb = smem_to_u32(smem);
    const int t    = threadIdx.x;
    const int wid  = t >> 5;
    const int lane = t & 31;
    const int wm   = wid & 1;
    const int wn   = wid >> 1;
    const int bm   = blockIdx.y * 128;
    const int bn   = blockIdx.x * 128;

    auto stage_load = [&](int s, int k0) {
#pragma unroll
        for (int i = 0; i < 12; i++) {
            int idx = t + i * 256;            // 0..3071
            int tensor = idx >> 10;           // 0=A 1=Bh 2=Bl
            int rem = idx & 1023;
            int r = rem >> 3;                 // 0..127
            int c16 = (rem & 7) * 16;
            const char* src;
            if (tensor == 0)      src = (const char*)(A  + (size_t)(bm + r) * K + k0) + c16;
            else if (tensor == 1) src = (const char*)(Bh + (size_t)(bn + r) * K + k0) + c16;
            else                  src = (const char*)(Bl + (size_t)(bn + r) * K + k0) + c16;
            cp_async16(sb + s * STAGE_B + tensor * TILE_B + r * TSTRIDE + c16, src);
        }
    };

    float acc[4][4][4];
#pragma unroll
    for (int i = 0; i < 4; i++)
#pragma unroll
        for (int j = 0; j < 4; j++)
#pragma unroll
            for (int k = 0; k < 4; k++) acc[i][j][k] = 0.0f;

    stage_load(0, 0);  CP_COMMIT();
    stage_load(1, 64); CP_COMMIT();

    const int sel  = lane >> 3;
    const int lrow = lane & 7;
    const int a_row_off = ((sel & 1) ? 8 : 0) + lrow;
    const int a_kc      = sel >> 1;
    const int b_row_off = ((sel >> 1) ? 8 : 0) + lrow;
    const int b_kc      = sel & 1;

    const int nch = K / 64;
    for (int ch = 0; ch < nch; ch++) {
        CP_WAIT1();
        __syncthreads();
        const uint32_t st = sb + (ch & 1) * STAGE_B;

#pragma unroll
        for (int ks = 0; ks < 4; ks++) {
            const uint32_t kbyte = ks * 32;
            uint32_t af[4][4], bhf[2][4], blf[2][4];
#pragma unroll
            for (int mt = 0; mt < 4; mt++)
                ldsm_x4(af[mt], st + (wm * 64 + mt * 16 + a_row_off) * TSTRIDE
                                   + kbyte + a_kc * 16);
#pragma unroll
            for (int p = 0; p < 2; p++)
                ldsm_x4(bhf[p], st + TILE_B
                                   + (wn * 32 + p * 16 + b_row_off) * TSTRIDE
                                   + kbyte + b_kc * 16);
#pragma unroll
            for (int mt = 0; mt < 4; mt++)
#pragma unroll
                for (int nt = 0; nt < 4; nt++)
                    mma_f16(acc[mt][nt], af[mt], &bhf[nt >> 1][(nt & 1) * 2]);
#pragma unroll
            for (int p = 0; p < 2; p++)
                ldsm_x4(blf[p], st + 2 * TILE_B
                                   + (wn * 32 + p * 16 + b_row_off) * TSTRIDE
                                   + kbyte + b_kc * 16);
#pragma unroll
            for (int mt = 0; mt < 4; mt++)
#pragma unroll
                for (int nt = 0; nt < 4; nt++)
                    mma_f16(acc[mt][nt], af[mt], &blf[nt >> 1][(nt & 1) * 2]);
        }
        __syncthreads();
        if (ch + 2 < nch) stage_load(ch & 1, (ch + 2) * 64);
        CP_COMMIT();
    }
    CP_WAIT0();

    const int g  = lane >> 2;
    const int tq = lane & 3;

    if constexpr (!QKV_EPI) {
        // out-projection: fp32 C = acc/1024 + bias
#pragma unroll
        for (int mt = 0; mt < 4; mt++) {
#pragma unroll
            for (int nt = 0; nt < 4; nt++) {
                int row = bm + wm * 64 + mt * 16 + g;
                int col = bn + wn * 32 + nt * 8 + tq * 2;
                float b0 = bias[col], b1 = bias[col + 1];
                float2 v0 = make_float2(fmaf(acc[mt][nt][0], INV_WSCALE, b0),
                                        fmaf(acc[mt][nt][1], INV_WSCALE, b1));
                float2 v1 = make_float2(fmaf(acc[mt][nt][2], INV_WSCALE, b0),
                                        fmaf(acc[mt][nt][3], INV_WSCALE, b1));
                *reinterpret_cast<float2*>(C + (size_t)row * N + col)       = v0;
                *reinterpret_cast<float2*>(C + (size_t)(row + 8) * N + col) = v1;
            }
        }
    } else {
        // Fused QKV epilogue: q split x128; k single; v split x1024 transposed.
        const int sec = bn >> 10;              // 0=q, 1=k, 2=v
#pragma unroll
        for (int mt = 0; mt < 4; mt++) {
#pragma unroll
            for (int nt = 0; nt < 4; nt++) {
                int row = bm + wm * 64 + mt * 16 + g;         // token
                int col = bn + wn * 32 + nt * 8 + tq * 2;     // global qkv col
                float b0 = bias[col], b1 = bias[col + 1];
                float v0 = fmaf(acc[mt][nt][0], INV_WSCALE, b0);
                float v1 = fmaf(acc[mt][nt][1], INV_WSCALE, b1);
                float v2 = fmaf(acc[mt][nt][2], INV_WSCALE, b0);
                float v3 = fmaf(acc[mt][nt][3], INV_WSCALE, b1);
                int cc = col & 1023;
                int h  = cc >> 6, d = cc & 63;
                int b  = row >> 11, sq = row & 2047;
                int bh = b * 16 + h;
                if (sec == 0) {
                    // q: x128 (0.125 softmax scale x 1024), split fp16
                    v0 *= 128.0f; v1 *= 128.0f; v2 *= 128.0f; v3 *= 128.0f;
                    __half h0 = __float2half(v0), h1 = __float2half(v1);
                    __half h2 = __float2half(v2), h3 = __float2half(v3);
                    __half l0 = __float2half(v0 - __half2float(h0));
                    __half l1 = __float2half(v1 - __half2float(h1));
                    __half l2 = __float2half(v2 - __half2float(h2));
                    __half l3 = __float2half(v3 - __half2float(h3));
                    size_t o = ((size_t)bh * SEQ + sq) * HEAD_DIM + d;
                    __half2 ph0; ph0.x = h0; ph0.y = h1;
                    __half2 ph1; ph1.x = h2; ph1.y = h3;
                    __half2 pl0; pl0.x = l0; pl0.y = l1;
                    __half2 pl1; pl1.x = l2; pl1.y = l3;
                    *reinterpret_cast<__half2*>(g_qh + o)                = ph0;
                    *reinterpret_cast<__half2*>(g_ql + o)                = pl0;
                    *reinterpret_cast<__half2*>(g_qh + o + 8 * HEAD_DIM) = ph1;
                    *reinterpret_cast<__half2*>(g_ql + o + 8 * HEAD_DIM) = pl1;
                } else if (sec == 1) {
                    // k: single fp16
                    size_t o = ((size_t)bh * SEQ + sq) * HEAD_DIM + d;
                    __half2 p0; p0.x = __float2half(v0); p0.y = __float2half(v1);
                    __half2 p1; p1.x = __float2half(v2); p1.y = __float2half(v3);
                    *reinterpret_cast<__half2*>(g_k16 + o)                = p0;
                    *reinterpret_cast<__half2*>(g_k16 + o + 8 * HEAD_DIM) = p1;
                } else {
                    // v: x1024 split fp16, transposed [bh][d][s]
                    v0 *= WSCALE; v1 *= WSCALE; v2 *= WSCALE; v3 *= WSCALE;
                    __half h0 = __float2half(v0), h1 = __float2half(v1);
                    __half h2 = __float2half(v2), h3 = __float2half(v3);
                    __half l0 = __float2half(v0 - __half2float(h0));
                    __half l1 = __float2half(v1 - __half2float(h1));
                    __half l2 = __float2half(v2 - __half2float(h2));
                    __half l3 = __float2half(v3 - __half2float(h3));
                    size_t ob = (size_t)bh * HEAD_DIM * SEQ;
                    size_t o0 = ob + (size_t)d * SEQ + sq;
                    size_t o1 = ob + (size_t)(d + 1) * SEQ + sq;
                    g_vth[o0]     = h0;  g_vtl[o0]     = l0;
                    g_vth[o1]     = h1;  g_vtl[o1]     = l1;
                    g_vth[o0 + 8] = h2;  g_vtl[o0 + 8] = l2;
                    g_vth[o1 + 8] = h3;  g_vtl[o1 + 8] = l3;
                }
            }
        }
    }
}

// ---------------------------------------------------------------------------
// Tensor-core flash attention, fp16 2-pass: QK^T = (Qh+Ql)x128 . K;
// PV = P . (Vh+Vl)x1024. Scores and output descaled by 1/1024.
// 2-stage KV pipeline (3 tiles/stage: K,Vh,Vl), Q (2 tiles) in smem, 2 CTAs/SM.
// ---------------------------------------------------------------------------
static constexpr int AT_STRIDE = 144;
static constexpr int AT_TILE   = 64 * AT_STRIDE;    // 9216
static constexpr int AT_STAGE  = 3 * AT_TILE;       // 27648: K, Vh, Vl
static constexpr int Q_TILE    = 128 * AT_STRIDE;   // 18432
static constexpr int QS_OFF    = 2 * AT_STAGE;      // 55296
static constexpr int AT_SMEM   = QS_OFF + 2 * Q_TILE;  // 92160 (x2 = 184320)

__global__ __launch_bounds__(256, 2)
void attn_tc_kernel()
{
    extern __shared__ char smem[];
    const uint32_t sb = smem_to_u32(smem);
    const int t    = threadIdx.x;
    const int wid  = t >> 5;
    const int lane = t & 31;
    const int g    = lane >> 2;
    const int tq   = lane & 3;
    const int bh   = blockIdx.y;
    const int q0   = blockIdx.x * 128;
    const int wrow = wid * 16;

    const int sel  = lane >> 3;
    const int lrow = lane & 7;
    const int a_row_off = ((sel & 1) ? 8 : 0) + lrow;
    const int a_kc      = sel >> 1;
    const int b_row_off = ((sel >> 1) ? 8 : 0) + lrow;
    const int b_kc      = sel & 1;

    // Q tiles (hi+lo) into smem
    {
        const char* baseQh = (const char*)(g_qh + ((size_t)bh * SEQ + q0) * HEAD_DIM);
        const char* baseQl = (const char*)(g_ql + ((size_t)bh * SEQ + q0) * HEAD_DIM);
#pragma unroll
        for (int i = 0; i < 4; i++) {
            int idx = t + i * 256;
            int r = idx >> 3, c16 = (idx & 7) * 16;
            cp_async16(sb + QS_OFF + r * AT_STRIDE + c16, baseQh + (size_t)r * 128 + c16);
            cp_async16(sb + QS_OFF + Q_TILE + r * AT_STRIDE + c16, baseQl + (size_t)r * 128 + c16);
        }
    }

    auto load_stage = [&](int s, int kk0) {
        const char* baseK  = (const char*)(g_k16 + ((size_t)bh * SEQ + kk0) * HEAD_DIM);
        const char* baseVh = (const char*)(g_vth + (size_t)bh * HEAD_DIM * SEQ + kk0);
        const char* baseVl = (const char*)(g_vtl + (size_t)bh * HEAD_DIM * SEQ + kk0);
#pragma unroll
        for (int i = 0; i < 6; i++) {
            int idx = t + i * 256;            // 0..1535
            int tensor = idx >> 9;            // 0=K 1=Vh 2=Vl
            int rem = idx & 511;
            int r = rem >> 3;
            int c16 = (rem & 7) * 16;
            const char* src;
            if (tensor == 0)      src = baseK  + (size_t)r * 128 + c16;
            else if (tensor == 1) src = baseVh + (size_t)r * (SEQ * 2) + c16;
            else                  src = baseVl + (size_t)r * (SEQ * 2) + c16;
            cp_async16(sb + s * AT_STAGE + tensor * AT_TILE + r * AT_STRIDE + c16, src);
        }
    };

    float o[8][4];
#pragma unroll
    for (int i = 0; i < 8; i++)
#pragma unroll
        for (int j = 0; j < 4; j++) o[i][j] = 0.0f;
    float m0 = -CUDART_INF_F, m1 = -CUDART_INF_F, l0 = 0.0f, l1 = 0.0f;

    load_stage(0, 0);  CP_COMMIT();
    load_stage(1, 64); CP_COMMIT();

    const int nkt = SEQ / 64;
    for (int kt = 0; kt < nkt; kt++) {
        CP_WAIT1();
        __syncthreads();
        const uint32_t st = sb + (kt & 1) * AT_STAGE;

        // ---- S*1024 = (Qh+Ql) K^T (2 passes) ----
        float s[8][4];
#pragma unroll
        for (int i = 0; i < 8; i++)
#pragma unroll
            for (int j = 0; j < 4; j++) s[i][j] = 0.0f;
#pragma unroll
        for (int ks = 0; ks < 4; ks++) {
            const uint32_t kbyte = ks * 32;
            const uint32_t qaddr = sb + QS_OFF + (wrow + a_row_off) * AT_STRIDE
                                   + kbyte + a_kc * 16;
            uint32_t qh4[4], ql4[4];
            ldsm_x4(qh4, qaddr);
            ldsm_x4(ql4, qaddr + Q_TILE);
            uint32_t kf[4][4];
#pragma unroll
            for (int ng = 0; ng < 4; ng++)
                ldsm_x4(kf[ng], st + (ng * 16 + b_row_off) * AT_STRIDE + kbyte + b_kc * 16);
#pragma unroll
            for (int ng = 0; ng < 4; ng++) {
                mma_f16(s[ng * 2],     qh4, &kf[ng][0]);
                mma_f16(s[ng * 2 + 1], qh4, &kf[ng][2]);
            }
#pragma unroll
            for (int ng = 0; ng < 4; ng++) {
                mma_f16(s[ng * 2],     ql4, &kf[ng][0]);
                mma_f16(s[ng * 2 + 1], ql4, &kf[ng][2]);
            }
        }
        // descale scores
#pragma unroll
        for (int nt = 0; nt < 8; nt++) {
            s[nt][0] *= INV_WSCALE; s[nt][1] *= INV_WSCALE;
            s[nt][2] *= INV_WSCALE; s[nt][3] *= INV_WSCALE;
        }

        // ---- online softmax ----
        float mt0 = -CUDART_INF_F, mt1 = -CUDART_INF_F;
#pragma unroll
        for (int nt = 0; nt < 8; nt++) {
            mt0 = fmaxf(mt0, fmaxf(s[nt][0], s[nt][1]));
            mt1 = fmaxf(mt1, fmaxf(s[nt][2], s[nt][3]));
        }
        mt0 = fmaxf(mt0, __shfl_xor_sync(0xFFFFFFFF, mt0, 1));
        mt0 = fmaxf(mt0, __shfl_xor_sync(0xFFFFFFFF, mt0, 2));
        mt1 = fmaxf(mt1, __shfl_xor_sync(0xFFFFFFFF, mt1, 1));
        mt1 = fmaxf(mt1, __shfl_xor_sync(0xFFFFFFFF, mt1, 2));
        float mn0 = fmaxf(m0, mt0), mn1 = fmaxf(m1, mt1);
        float c0 = __expf(m0 - mn0), c1 = __expf(m1 - mn1);
        m0 = mn0; m1 = mn1;
        float ls0 = 0.0f, ls1 = 0.0f;
#pragma unroll
        for (int nt = 0; nt < 8; nt++) {
            s[nt][0] = __expf(s[nt][0] - m0);
            s[nt][1] = __expf(s[nt][1] - m0);
            s[nt][2] = __expf(s[nt][2] - m1);
            s[nt][3] = __expf(s[nt][3] - m1);
            ls0 += s[nt][0] + s[nt][1];
            ls1 += s[nt][2] + s[nt][3];
        }
        l0 = l0 * c0 + ls0;
        l1 = l1 * c1 + ls1;
#pragma unroll
        for (int nt = 0; nt < 8; nt++) {
            o[nt][0] *= c0; o[nt][1] *= c0;
            o[nt][2] *= c1; o[nt][3] *= c1;
        }

        // ---- O*1024 += P (Vh+Vl) (2 passes, P single fp16) ----
#pragma unroll
        for (int ks = 0; ks < 4; ks++) {
            uint32_t pa[4];
#pragma unroll
            for (int half = 0; half < 2; half++) {
                const float* sp = s[2 * ks + half];
                pa[half * 2]     = pack_f16x2(sp[0], sp[1]);
                pa[half * 2 + 1] = pack_f16x2(sp[2], sp[3]);
            }
            const uint32_t kbyte = ks * 32 + b_kc * 16;
            uint32_t vh[4][4], vl[4][4];
#pragma unroll
            for (int ng = 0; ng < 4; ng++)
                ldsm_x4(vh[ng], st + AT_TILE + (ng * 16 + b_row_off) * AT_STRIDE + kbyte);
#pragma unroll
            for (int ng = 0; ng < 4; ng++)
                ldsm_x4(vl[ng], st + 2 * AT_TILE + (ng * 16 + b_row_off) * AT_STRIDE + kbyte);
#pragma unroll
            for (int ng = 0; ng < 4; ng++) {
                mma_f16(o[ng * 2],     pa, &vh[ng][0]);
                mma_f16(o[ng * 2 + 1], pa, &vh[ng][2]);
            }
#pragma unroll
            for (int ng = 0; ng < 4; ng++) {
                mma_f16(o[ng * 2],     pa, &vl[ng][0]);
                mma_f16(o[ng * 2 + 1], pa, &vl[ng][2]);
            }
        }
        __syncthreads();
        if (kt + 2 < nkt) load_stage(kt & 1, (kt + 2) * 64);
        CP_COMMIT();
    }
    CP_WAIT0();

    // ---- finalize: out = o / (l * 1024), write single fp16 z ----
    l0 += __shfl_xor_sync(0xFFFFFFFF, l0, 1);
    l0 += __shfl_xor_sync(0xFFFFFFFF, l0, 2);
    l1 += __shfl_xor_sync(0xFFFFFFFF, l1, 1);
    l1 += __shfl_xor_sync(0xFFFFFFFF, l1, 2);
    float inv0 = INV_WSCALE / l0, inv1 = INV_WSCALE / l1;

    const int b = bh >> 4, h = bh & 15;
    const size_t tok0 = (size_t)b * SEQ + q0 + wrow + g;
#pragma unroll
    for (int nt = 0; nt < 8; nt++) {
        int col = h * HEAD_DIM + nt * 8 + tq * 2;
        __half2 p0, p1;
        p0.x = __float2half(o[nt][0] * inv0);
        p0.y = __float2half(o[nt][1] * inv0);
        p1.x = __float2half(o[nt][2] * inv1);
        p1.y = __float2half(o[nt][3] * inv1);
        *reinterpret_cast<__half2*>(g_z16 + tok0 * MODEL_DIM + col)       = p0;
        *reinterpret_cast<__half2*>(g_z16 + (tok0 + 8) * MODEL_DIM + col) = p1;
    }
}

// ---------------------------------------------------------------------------
// Launch
// ---------------------------------------------------------------------------
extern "C" void kernel_launch(void* const* d_in, const int* in_sizes, int n_in,
                              void* d_out, int out_size)
{
    const float* x     = (const float*)d_in[0];
    const float* w_qkv = (const float*)d_in[1];
    const float* b_qkv = (const float*)d_in[2];
    const float* w_out = (const float*)d_in[3];
    const float* b_out = (const float*)d_in[4];
    float* out = (float*)d_out;

    __half *x16, *z16, *wqkvT_h, *wqkvT_l, *woutT_h, *woutT_l;
    cudaGetSymbolAddress((void**)&x16, g_x16);
    cudaGetSymbolAddress((void**)&z16, g_z16);
    cudaGetSymbolAddress((void**)&wqkvT_h, g_wqkvT_h);
    cudaGetSymbolAddress((void**)&wqkvT_l, g_wqkvT_l);
    cudaGetSymbolAddress((void**)&woutT_h, g_woutT_h);
    cudaGetSymbolAddress((void**)&woutT_l, g_woutT_l);

    cudaFuncSetAttribute(tc_gemm_kernel<true>,
                         cudaFuncAttributeMaxDynamicSharedMemorySize, GEMM_SMEM);
    cudaFuncSetAttribute(tc_gemm_kernel<false>,
                         cudaFuncAttributeMaxDynamicSharedMemorySize, GEMM_SMEM);
    cudaFuncSetAttribute(attn_tc_kernel,
                         cudaFuncAttributeMaxDynamicSharedMemorySize, AT_SMEM);

    // 0. Preprocess: x -> fp16; weights -> transposed fp16 hi/lo (x1024)
    {
        int n4 = TOK * MODEL_DIM / 4;
        convert_f16_kernel<<<(n4 + 255) / 256, 256>>>(x, x16, n4);
        transpose_split_f16_kernel<<<dim3(QKV_DIM / 32, MODEL_DIM / 32), dim3(32, 8)>>>(
            w_qkv, wqkvT_h, wqkvT_l, MODEL_DIM, QKV_DIM);
        transpose_split_f16_kernel<<<dim3(MODEL_DIM / 32, MODEL_DIM / 32), dim3(32, 8)>>>(
            w_out, woutT_h, woutT_l, MODEL_DIM, MODEL_DIM);
    }

    // 1. QKV projection (fp16 2-pass) with fused operand-layout epilogue
    tc_gemm_kernel<true><<<dim3(QKV_DIM / 128, TOK / 128), 256, GEMM_SMEM>>>(
        x16, wqkvT_h, wqkvT_l, b_qkv, nullptr, TOK, QKV_DIM, MODEL_DIM);

    // 2. Tensor-core flash attention (fp16 2-pass; writes fp16 z)
    attn_tc_kernel<<<dim3(SEQ / 128, BH), 256, AT_SMEM>>>();

    // 3. Output projection (fp16 2-pass)
    tc_gemm_kernel<false><<<dim3(MODEL_DIM / 128, TOK / 128), 256, GEMM_SMEM>>>(
        z16, woutT_h, woutT_l, b_out, out, TOK, MODEL_DIM, MODEL_DIM);
}

// round 14
// speedup vs baseline: 5.2235x; 1.1452x over previous
#include <cuda_runtime.h>
#include <cuda_bf16.h>
#include <cuda_fp16.h>
#include <math_constants.h>
#include <cstdint>

// Problem constants
static constexpr int MODEL_DIM = 1024;
static constexpr int HEAD      = 16;
static constexpr int HEAD_DIM  = 64;
static constexpr int BATCH     = 2;
static constexpr int SEQ       = 2048;
static constexpr int TOK       = BATCH * SEQ;      // 4096
static constexpr int QKV_DIM   = 3 * MODEL_DIM;    // 3072
static constexpr int BH        = BATCH * HEAD;     // 32

// Scale tricks: weights and V stored x1024 (keeps fp16 lo-parts normal);
// Q stored x128 (= 0.125 softmax scale x 1024). Descale via INV_WSCALE.
static constexpr float WSCALE     = 1024.0f;
static constexpr float INV_WSCALE = 1.0f / 1024.0f;

// Scratch (__device__ globals; no runtime allocation allowed)
__device__ __half g_x16[TOK * MODEL_DIM];              // x, single fp16
__device__ __half g_z16[TOK * MODEL_DIM];              // attn out, single fp16
__device__ __half g_wqkvT_h[QKV_DIM * MODEL_DIM];      // w^T*1024 hi [N][K]
__device__ __half g_wqkvT_l[QKV_DIM * MODEL_DIM];      // w^T*1024 lo
__device__ __half g_woutT_h[MODEL_DIM * MODEL_DIM];    // w_out^T*1024 single
// Attention operands (fp16): Q single x128; K single; V^T split x1024.
__device__ __half g_q16[BH * SEQ * HEAD_DIM];  // [bh][s][d]
__device__ __half g_k16[BH * SEQ * HEAD_DIM];  // [bh][s][d]
__device__ __half g_vth[BH * HEAD_DIM * SEQ];  // [bh][d][s]
__device__ __half g_vtl[BH * HEAD_DIM * SEQ];

// ---------------------------------------------------------------------------
// PTX helpers (sm_80-compatible)
// ---------------------------------------------------------------------------
__device__ __forceinline__ uint32_t smem_to_u32(const void* p) {
    uint32_t a;
    asm("{ .reg .u64 tmp; cvta.to.shared.u64 tmp, %1; cvt.u32.u64 %0, tmp; }"
        : "=r"(a) : "l"(p));
    return a;
}
__device__ __forceinline__ void ldsm_x4(uint32_t* r, uint32_t addr) {
    asm volatile("ldmatrix.sync.aligned.m8n8.x4.shared.b16 {%0,%1,%2,%3}, [%4];"
                 : "=r"(r[0]), "=r"(r[1]), "=r"(r[2]), "=r"(r[3]) : "r"(addr));
}
__device__ __forceinline__ void mma_f16(float* c, const uint32_t* a, const uint32_t* b) {
    asm volatile(
        "mma.sync.aligned.m16n8k16.row.col.f32.f16.f16.f32 "
        "{%0,%1,%2,%3}, {%4,%5,%6,%7}, {%8,%9}, {%0,%1,%2,%3};"
        : "+f"(c[0]), "+f"(c[1]), "+f"(c[2]), "+f"(c[3])
        : "r"(a[0]), "r"(a[1]), "r"(a[2]), "r"(a[3]), "r"(b[0]), "r"(b[1]));
}
__device__ __forceinline__ void cp_async16(uint32_t dst, const void* src) {
    asm volatile("cp.async.cg.shared.global [%0], [%1], 16;" :: "r"(dst), "l"(src));
}
#define CP_COMMIT() asm volatile("cp.async.commit_group;" ::: "memory")
#define CP_WAIT1()  asm volatile("cp.async.wait_group 1;" ::: "memory")
#define CP_WAIT0()  asm volatile("cp.async.wait_group 0;" ::: "memory")
__device__ __forceinline__ uint32_t pack_f16x2(float lo, float hi) {
    uint32_t r;
    asm("cvt.rn.f16x2.f32 %0, %1, %2;" : "=r"(r) : "f"(hi), "f"(lo));
    return r;
}

// ---------------------------------------------------------------------------
// x convert: fp32 -> single fp16
// ---------------------------------------------------------------------------
__global__ void convert_f16_kernel(const float* __restrict__ X,
                                   __half* __restrict__ X16, int n4)
{
    int i = blockIdx.x * blockDim.x + threadIdx.x;
    if (i >= n4) return;
    float4 v = reinterpret_cast<const float4*>(X)[i];
    __half2 p0; p0.x = __float2half(v.x); p0.y = __float2half(v.y);
    __half2 p1; p1.x = __float2half(v.z); p1.y = __float2half(v.w);
    reinterpret_cast<__half2*>(X16)[i * 2]     = p0;
    reinterpret_cast<__half2*>(X16)[i * 2 + 1] = p1;
}

// ---------------------------------------------------------------------------
// Weight transpose + fp16 with x1024 scale: W[K][N] -> Th (+ optional Tl) [N][K]
// ---------------------------------------------------------------------------
__global__ void transpose_split_f16_kernel(const float* __restrict__ W,
                                           __half* __restrict__ Th,
                                           __half* __restrict__ Tl,  // may be null
                                           int K, int N)
{
    __shared__ float tile[32][33];
    const int n0 = blockIdx.x * 32, k0 = blockIdx.y * 32;
    const int tx = threadIdx.x, ty = threadIdx.y;
#pragma unroll
    for (int i = 0; i < 32; i += 8)
        tile[ty + i][tx] = W[(size_t)(k0 + ty + i) * N + n0 + tx];
    __syncthreads();
#pragma unroll
    for (int i = 0; i < 32; i += 8) {
        float v = tile[tx][ty + i] * WSCALE;
        __half h = __float2half(v);
        size_t o = (size_t)(n0 + ty + i) * K + k0 + tx;
        Th[o] = h;
        if (Tl) Tl[o] = __float2half(v - __half2float(h));
    }
}

// ---------------------------------------------------------------------------
// fp16 GEMM: C = A[M,K](fp16) @ B^T /1024 + bias
// QKV_EPI=true : B split (2-pass) + fused epilogue -> attention operands.
// QKV_EPI=false: B single (1-pass), fp32 C + bias (output projection).
// BM=BN=128, BK=64. 2-stage cp.async pipeline, 2 CTAs/SM.
// ---------------------------------------------------------------------------
static constexpr int TSTRIDE = 144;                 // 128B data + 16B pad
static constexpr int TILE_B  = 128 * TSTRIDE;       // 18432

template <bool QKV_EPI>
__global__ __launch_bounds__(256, 2)
void tc_gemm_kernel(const __half* __restrict__ A,
                    const __half* __restrict__ Bh,
                    const __half* __restrict__ Bl,
                    const float* __restrict__ bias,
                    float* __restrict__ C,
                    int M, int N, int K)
{
    constexpr int NTILES  = QKV_EPI ? 3 : 2;        // A,Bh(,Bl)
    constexpr int STAGE_B = NTILES * TILE_B;
    extern __shared__ char smem[];
    const uint32_t sb = smem_to_u32(smem);
    const int t    = threadIdx.x;
    const int wid  = t >> 5;
    const int lane = t & 31;
    const int wm   = wid & 1;
    const int wn   = wid >> 1;
    const int bm   = blockIdx.y * 128;
    const int bn   = blockIdx.x * 128;

    auto stage_load = [&](int s, int k0) {
#pragma unroll
        for (int i = 0; i < NTILES * 4; i++) {
            int idx = t + i * 256;            // 0..NTILES*1024-1
            int tensor = idx >> 10;           // 0=A 1=Bh (2=Bl)
            int rem = idx & 1023;
            int r = rem >> 3;
            int c16 = (rem & 7) * 16;
            const char* src;
            if (tensor == 0)      src = (const char*)(A  + (size_t)(bm + r) * K + k0) + c16;
            else if (tensor == 1) src = (const char*)(Bh + (size_t)(bn + r) * K + k0) + c16;
            else                  src = (const char*)(Bl + (size_t)(bn + r) * K + k0) + c16;
            cp_async16(sb + s * STAGE_B + tensor * TILE_B + r * TSTRIDE + c16, src);
        }
    };

    float acc[4][4][4];
#pragma unroll
    for (int i = 0; i < 4; i++)
#pragma unroll
        for (int j = 0; j < 4; j++)
#pragma unroll
            for (int k = 0; k < 4; k++) acc[i][j][k] = 0.0f;

    stage_load(0, 0);  CP_COMMIT();
    stage_load(1, 64); CP_COMMIT();

    const int sel  = lane >> 3;
    const int lrow = lane & 7;
    const int a_row_off = ((sel & 1) ? 8 : 0) + lrow;
    const int a_kc      = sel >> 1;
    const int b_row_off = ((sel >> 1) ? 8 : 0) + lrow;
    const int b_kc      = sel & 1;

    const int nch = K / 64;
    for (int ch = 0; ch < nch; ch++) {
        CP_WAIT1();
        __syncthreads();
        const uint32_t st = sb + (ch & 1) * STAGE_B;

#pragma unroll
        for (int ks = 0; ks < 4; ks++) {
            const uint32_t kbyte = ks * 32;
            uint32_t af[4][4], bhf[2][4];
#pragma unroll
            for (int mt = 0; mt < 4; mt++)
                ldsm_x4(af[mt], st + (wm * 64 + mt * 16 + a_row_off) * TSTRIDE
                                   + kbyte + a_kc * 16);
#pragma unroll
            for (int p = 0; p < 2; p++)
                ldsm_x4(bhf[p], st + TILE_B
                                   + (wn * 32 + p * 16 + b_row_off) * TSTRIDE
                                   + kbyte + b_kc * 16);
#pragma unroll
            for (int mt = 0; mt < 4; mt++)
#pragma unroll
                for (int nt = 0; nt < 4; nt++)
                    mma_f16(acc[mt][nt], af[mt], &bhf[nt >> 1][(nt & 1) * 2]);
            if constexpr (QKV_EPI) {
                uint32_t blf[2][4];
#pragma unroll
                for (int p = 0; p < 2; p++)
                    ldsm_x4(blf[p], st + 2 * TILE_B
                                       + (wn * 32 + p * 16 + b_row_off) * TSTRIDE
                                       + kbyte + b_kc * 16);
#pragma unroll
                for (int mt = 0; mt < 4; mt++)
#pragma unroll
                    for (int nt = 0; nt < 4; nt++)
                        mma_f16(acc[mt][nt], af[mt], &blf[nt >> 1][(nt & 1) * 2]);
            }
        }
        __syncthreads();
        if (ch + 2 < nch) stage_load(ch & 1, (ch + 2) * 64);
        CP_COMMIT();
    }
    CP_WAIT0();

    const int g  = lane >> 2;
    const int tq = lane & 3;

    if constexpr (!QKV_EPI) {
        // out-projection: fp32 C = acc/1024 + bias
#pragma unroll
        for (int mt = 0; mt < 4; mt++) {
#pragma unroll
            for (int nt = 0; nt < 4; nt++) {
                int row = bm + wm * 64 + mt * 16 + g;
                int col = bn + wn * 32 + nt * 8 + tq * 2;
                float b0 = bias[col], b1 = bias[col + 1];
                float2 v0 = make_float2(fmaf(acc[mt][nt][0], INV_WSCALE, b0),
                                        fmaf(acc[mt][nt][1], INV_WSCALE, b1));
                float2 v1 = make_float2(fmaf(acc[mt][nt][2], INV_WSCALE, b0),
                                        fmaf(acc[mt][nt][3], INV_WSCALE, b1));
                *reinterpret_cast<float2*>(C + (size_t)row * N + col)       = v0;
                *reinterpret_cast<float2*>(C + (size_t)(row + 8) * N + col) = v1;
            }
        }
    } else {
        // Fused QKV epilogue: q single x128; k single; v split x1024 transposed.
        const int sec = bn >> 10;              // 0=q, 1=k, 2=v
#pragma unroll
        for (int mt = 0; mt < 4; mt++) {
#pragma unroll
            for (int nt = 0; nt < 4; nt++) {
                int row = bm + wm * 64 + mt * 16 + g;
                int col = bn + wn * 32 + nt * 8 + tq * 2;
                float b0 = bias[col], b1 = bias[col + 1];
                float v0 = fmaf(acc[mt][nt][0], INV_WSCALE, b0);
                float v1 = fmaf(acc[mt][nt][1], INV_WSCALE, b1);
                float v2 = fmaf(acc[mt][nt][2], INV_WSCALE, b0);
                float v3 = fmaf(acc[mt][nt][3], INV_WSCALE, b1);
                int cc = col & 1023;
                int h  = cc >> 6, d = cc & 63;
                int b  = row >> 11, sq = row & 2047;
                int bh = b * 16 + h;
                if (sec == 0) {
                    // q single fp16, x128 (0.125 x 1024)
                    size_t o = ((size_t)bh * SEQ + sq) * HEAD_DIM + d;
                    __half2 p0; p0.x = __float2half(v0 * 128.0f); p0.y = __float2half(v1 * 128.0f);
                    __half2 p1; p1.x = __float2half(v2 * 128.0f); p1.y = __float2half(v3 * 128.0f);
                    *reinterpret_cast<__half2*>(g_q16 + o)                = p0;
                    *reinterpret_cast<__half2*>(g_q16 + o + 8 * HEAD_DIM) = p1;
                } else if (sec == 1) {
                    size_t o = ((size_t)bh * SEQ + sq) * HEAD_DIM + d;
                    __half2 p0; p0.x = __float2half(v0); p0.y = __float2half(v1);
                    __half2 p1; p1.x = __float2half(v2); p1.y = __float2half(v3);
                    *reinterpret_cast<__half2*>(g_k16 + o)                = p0;
                    *reinterpret_cast<__half2*>(g_k16 + o + 8 * HEAD_DIM) = p1;
                } else {
                    // v: x1024 split fp16, transposed [bh][d][s]
                    v0 *= WSCALE; v1 *= WSCALE; v2 *= WSCALE; v3 *= WSCALE;
                    __half h0 = __float2half(v0), h1 = __float2half(v1);
                    __half h2 = __float2half(v2), h3 = __float2half(v3);
                    __half l0 = __float2half(v0 - __half2float(h0));
                    __half l1 = __float2half(v1 - __half2float(h1));
                    __half l2 = __float2half(v2 - __half2float(h2));
                    __half l3 = __float2half(v3 - __half2float(h3));
                    size_t ob = (size_t)bh * HEAD_DIM * SEQ;
                    size_t o0 = ob + (size_t)d * SEQ + sq;
                    size_t o1 = ob + (size_t)(d + 1) * SEQ + sq;
                    g_vth[o0]     = h0;  g_vtl[o0]     = l0;
                    g_vth[o1]     = h1;  g_vtl[o1]     = l1;
                    g_vth[o0 + 8] = h2;  g_vtl[o0 + 8] = l2;
                    g_vth[o1 + 8] = h3;  g_vtl[o1 + 8] = l3;
                }
            }
        }
    }
}

static constexpr int GEMM_SMEM_QKV = 2 * 3 * TILE_B;  // 110592
static constexpr int GEMM_SMEM_OUT = 2 * 2 * TILE_B;  // 73728

// ---------------------------------------------------------------------------
// Tensor-core flash attention, fp16: QK^T = Q(x128).K (1 pass);
// PV = P.(Vh+Vl)(x1024) (2 passes). Scores and output descaled by 1/1024.
// 2-stage KV pipeline (K,Vh,Vl), Q (1 tile) in smem, 2 CTAs/SM.
// ---------------------------------------------------------------------------
static constexpr int AT_STRIDE = 144;
static constexpr int AT_TILE   = 64 * AT_STRIDE;    // 9216
static constexpr int AT_STAGE  = 3 * AT_TILE;       // 27648: K, Vh, Vl
static constexpr int Q_TILE    = 128 * AT_STRIDE;   // 18432
static constexpr int QS_OFF    = 2 * AT_STAGE;      // 55296
static constexpr int AT_SMEM   = QS_OFF + Q_TILE;   // 73728 (x2 = 147456)

__global__ __launch_bounds__(256, 2)
void attn_tc_kernel()
{
    extern __shared__ char smem[];
    const uint32_t sb = smem_to_u32(smem);
    const int t    = threadIdx.x;
    const int wid  = t >> 5;
    const int lane = t & 31;
    const int g    = lane >> 2;
    const int tq   = lane & 3;
    const int bh   = blockIdx.y;
    const int q0   = blockIdx.x * 128;
    const int wrow = wid * 16;

    const int sel  = lane >> 3;
    const int lrow = lane & 7;
    const int a_row_off = ((sel & 1) ? 8 : 0) + lrow;
    const int a_kc      = sel >> 1;
    const int b_row_off = ((sel >> 1) ? 8 : 0) + lrow;
    const int b_kc      = sel & 1;

    // Q tile into smem
    {
        const char* baseQ = (const char*)(g_q16 + ((size_t)bh * SEQ + q0) * HEAD_DIM);
#pragma unroll
        for (int i = 0; i < 4; i++) {
            int idx = t + i * 256;
            int r = idx >> 3, c16 = (idx & 7) * 16;
            cp_async16(sb + QS_OFF + r * AT_STRIDE + c16, baseQ + (size_t)r * 128 + c16);
        }
    }

    auto load_stage = [&](int s, int kk0) {
        const char* baseK  = (const char*)(g_k16 + ((size_t)bh * SEQ + kk0) * HEAD_DIM);
        const char* baseVh = (const char*)(g_vth + (size_t)bh * HEAD_DIM * SEQ + kk0);
        const char* baseVl = (const char*)(g_vtl + (size_t)bh * HEAD_DIM * SEQ + kk0);
#pragma unroll
        for (int i = 0; i < 6; i++) {
            int idx = t + i * 256;            // 0..1535
            int tensor = idx >> 9;            // 0=K 1=Vh 2=Vl
            int rem = idx & 511;
            int r = rem >> 3;
            int c16 = (rem & 7) * 16;
            const char* src;
            if (tensor == 0)      src = baseK  + (size_t)r * 128 + c16;
            else if (tensor == 1) src = baseVh + (size_t)r * (SEQ * 2) + c16;
            else                  src = baseVl + (size_t)r * (SEQ * 2) + c16;
            cp_async16(sb + s * AT_STAGE + tensor * AT_TILE + r * AT_STRIDE + c16, src);
        }
    };

    float o[8][4];
#pragma unroll
    for (int i = 0; i < 8; i++)
#pragma unroll
        for (int j = 0; j < 4; j++) o[i][j] = 0.0f;
    float m0 = -CUDART_INF_F, m1 = -CUDART_INF_F, l0 = 0.0f, l1 = 0.0f;

    load_stage(0, 0);  CP_COMMIT();
    load_stage(1, 64); CP_COMMIT();

    const int nkt = SEQ / 64;
    for (int kt = 0; kt < nkt; kt++) {
        CP_WAIT1();
        __syncthreads();
        const uint32_t st = sb + (kt & 1) * AT_STAGE;

        // ---- S*1024 = Q K^T (1 pass) ----
        float s[8][4];
#pragma unroll
        for (int i = 0; i < 8; i++)
#pragma unroll
            for (int j = 0; j < 4; j++) s[i][j] = 0.0f;
#pragma unroll
        for (int ks = 0; ks < 4; ks++) {
            const uint32_t kbyte = ks * 32;
            uint32_t q4[4];
            ldsm_x4(q4, sb + QS_OFF + (wrow + a_row_off) * AT_STRIDE
                        + kbyte + a_kc * 16);
            uint32_t kf[4][4];
#pragma unroll
            for (int ng = 0; ng < 4; ng++)
                ldsm_x4(kf[ng], st + (ng * 16 + b_row_off) * AT_STRIDE + kbyte + b_kc * 16);
#pragma unroll
            for (int ng = 0; ng < 4; ng++) {
                mma_f16(s[ng * 2],     q4, &kf[ng][0]);
                mma_f16(s[ng * 2 + 1], q4, &kf[ng][2]);
            }
        }
#pragma unroll
        for (int nt = 0; nt < 8; nt++) {
            s[nt][0] *= INV_WSCALE; s[nt][1] *= INV_WSCALE;
            s[nt][2] *= INV_WSCALE; s[nt][3] *= INV_WSCALE;
        }

        // ---- online softmax ----
        float mt0 = -CUDART_INF_F, mt1 = -CUDART_INF_F;
#pragma unroll
        for (int nt = 0; nt < 8; nt++) {
            mt0 = fmaxf(mt0, fmaxf(s[nt][0], s[nt][1]));
            mt1 = fmaxf(mt1, fmaxf(s[nt][2], s[nt][3]));
        }
        mt0 = fmaxf(mt0, __shfl_xor_sync(0xFFFFFFFF, mt0, 1));
        mt0 = fmaxf(mt0, __shfl_xor_sync(0xFFFFFFFF, mt0, 2));
        mt1 = fmaxf(mt1, __shfl_xor_sync(0xFFFFFFFF, mt1, 1));
        mt1 = fmaxf(mt1, __shfl_xor_sync(0xFFFFFFFF, mt1, 2));
        float mn0 = fmaxf(m0, mt0), mn1 = fmaxf(m1, mt1);
        float c0 = __expf(m0 - mn0), c1 = __expf(m1 - mn1);
        m0 = mn0; m1 = mn1;
        float ls0 = 0.0f, ls1 = 0.0f;
#pragma unroll
        for (int nt = 0; nt < 8; nt++) {
            s[nt][0] = __expf(s[nt][0] - m0);
            s[nt][1] = __expf(s[nt][1] - m0);
            s[nt][2] = __expf(s[nt][2] - m1);
            s[nt][3] = __expf(s[nt][3] - m1);
            ls0 += s[nt][0] + s[nt][1];
            ls1 += s[nt][2] + s[nt][3];
        }
        l0 = l0 * c0 + ls0;
        l1 = l1 * c1 + ls1;
#pragma unroll
        for (int nt = 0; nt < 8; nt++) {
            o[nt][0] *= c0; o[nt][1] *= c0;
            o[nt][2] *= c1; o[nt][3] *= c1;
        }

        // ---- O*1024 += P (Vh+Vl) (2 passes) ----
#pragma unroll
        for (int ks = 0; ks < 4; ks++) {
            uint32_t pa[4];
#pragma unroll
            for (int half = 0; half < 2; half++) {
                const float* sp = s[2 * ks + half];
                pa[half * 2]     = pack_f16x2(sp[0], sp[1]);
                pa[half * 2 + 1] = pack_f16x2(sp[2], sp[3]);
            }
            const uint32_t kbyte = ks * 32 + b_kc * 16;
            uint32_t vh[4][4], vl[4][4];
#pragma unroll
            for (int ng = 0; ng < 4; ng++)
                ldsm_x4(vh[ng], st + AT_TILE + (ng * 16 + b_row_off) * AT_STRIDE + kbyte);
#pragma unroll
            for (int ng = 0; ng < 4; ng++)
                ldsm_x4(vl[ng], st + 2 * AT_TILE + (ng * 16 + b_row_off) * AT_STRIDE + kbyte);
#pragma unroll
            for (int ng = 0; ng < 4; ng++) {
                mma_f16(o[ng * 2],     pa, &vh[ng][0]);
                mma_f16(o[ng * 2 + 1], pa, &vh[ng][2]);
            }
#pragma unroll
            for (int ng = 0; ng < 4; ng++) {
                mma_f16(o[ng * 2],     pa, &vl[ng][0]);
                mma_f16(o[ng * 2 + 1], pa, &vl[ng][2]);
            }
        }
        __syncthreads();
        if (kt + 2 < nkt) load_stage(kt & 1, (kt + 2) * 64);
        CP_COMMIT();
    }
    CP_WAIT0();

    // ---- finalize: out = o / (l * 1024), write single fp16 z ----
    l0 += __shfl_xor_sync(0xFFFFFFFF, l0, 1);
    l0 += __shfl_xor_sync(0xFFFFFFFF, l0, 2);
    l1 += __shfl_xor_sync(0xFFFFFFFF, l1, 1);
    l1 += __shfl_xor_sync(0xFFFFFFFF, l1, 2);
    float inv0 = INV_WSCALE / l0, inv1 = INV_WSCALE / l1;

    const int b = bh >> 4, h = bh & 15;
    const size_t tok0 = (size_t)b * SEQ + q0 + wrow + g;
#pragma unroll
    for (int nt = 0; nt < 8; nt++) {
        int col = h * HEAD_DIM + nt * 8 + tq * 2;
        __half2 p0, p1;
        p0.x = __float2half(o[nt][0] * inv0);
        p0.y = __float2half(o[nt][1] * inv0);
        p1.x = __float2half(o[nt][2] * inv1);
        p1.y = __float2half(o[nt][3] * inv1);
        *reinterpret_cast<__half2*>(g_z16 + tok0 * MODEL_DIM + col)       = p0;
        *reinterpret_cast<__half2*>(g_z16 + (tok0 + 8) * MODEL_DIM + col) = p1;
    }
}

// ---------------------------------------------------------------------------
// Launch
// ---------------------------------------------------------------------------
extern "C" void kernel_launch(void* const* d_in, const int* in_sizes, int n_in,
                              void* d_out, int out_size)
{
    const float* x     = (const float*)d_in[0];
    const float* w_qkv = (const float*)d_in[1];
    const float* b_qkv = (const float*)d_in[2];
    const float* w_out = (const float*)d_in[3];
    const float* b_out = (const float*)d_in[4];
    float* out = (float*)d_out;

    __half *x16, *z16, *wqkvT_h, *wqkvT_l, *woutT_h;
    cudaGetSymbolAddress((void**)&x16, g_x16);
    cudaGetSymbolAddress((void**)&z16, g_z16);
    cudaGetSymbolAddress((void**)&wqkvT_h, g_wqkvT_h);
    cudaGetSymbolAddress((void**)&wqkvT_l, g_wqkvT_l);
    cudaGetSymbolAddress((void**)&woutT_h, g_woutT_h);

    cudaFuncSetAttribute(tc_gemm_kernel<true>,
                         cudaFuncAttributeMaxDynamicSharedMemorySize, GEMM_SMEM_QKV);
    cudaFuncSetAttribute(tc_gemm_kernel<false>,
                         cudaFuncAttributeMaxDynamicSharedMemorySize, GEMM_SMEM_OUT);
    cudaFuncSetAttribute(attn_tc_kernel,
                         cudaFuncAttributeMaxDynamicSharedMemorySize, AT_SMEM);

    // 0. Preprocess: x -> fp16; weights -> transposed fp16 (x1024)
    {
        int n4 = TOK * MODEL_DIM / 4;
        convert_f16_kernel<<<(n4 + 255) / 256, 256>>>(x, x16, n4);
        transpose_split_f16_kernel<<<dim3(QKV_DIM / 32, MODEL_DIM / 32), dim3(32, 8)>>>(
            w_qkv, wqkvT_h, wqkvT_l, MODEL_DIM, QKV_DIM);
        transpose_split_f16_kernel<<<dim3(MODEL_DIM / 32, MODEL_DIM / 32), dim3(32, 8)>>>(
            w_out, woutT_h, nullptr, MODEL_DIM, MODEL_DIM);
    }

    // 1. QKV projection (fp16 2-pass) with fused operand-layout epilogue
    tc_gemm_kernel<true><<<dim3(QKV_DIM / 128, TOK / 128), 256, GEMM_SMEM_QKV>>>(
        x16, wqkvT_h, wqkvT_l, b_qkv, nullptr, TOK, QKV_DIM, MODEL_DIM);

    // 2. Tensor-core flash attention (fp16; QK 1-pass, PV 2-pass)
    attn_tc_kernel<<<dim3(SEQ / 128, BH), 256, AT_SMEM>>>();

    // 3. Output projection (fp16 1-pass, single-B)
    tc_gemm_kernel<false><<<dim3(MODEL_DIM / 128, TOK / 128), 256, GEMM_SMEM_OUT>>>(
        z16, woutT_h, nullptr, b_out, out, TOK, MODEL_DIM, MODEL_DIM);
}

// round 15
// speedup vs baseline: 6.3317x; 1.2121x over previous
#include <cuda_runtime.h>
#include <cuda_bf16.h>
#include <cuda_fp16.h>
#include <math_constants.h>
#include <cstdint>

// Problem constants
static constexpr int MODEL_DIM = 1024;
static constexpr int HEAD      = 16;
static constexpr int HEAD_DIM  = 64;
static constexpr int BATCH     = 2;
static constexpr int SEQ       = 2048;
static constexpr int TOK       = BATCH * SEQ;      // 4096
static constexpr int QKV_DIM   = 3 * MODEL_DIM;    // 3072
static constexpr int BH        = BATCH * HEAD;     // 32

// Scale tricks: weights and V stored x1024 (keeps fp16 V lo-part normal);
// Q stored x128 (= 0.125 softmax scale x 1024). Descale via INV_WSCALE.
static constexpr float WSCALE     = 1024.0f;
static constexpr float INV_WSCALE = 1.0f / 1024.0f;

// Scratch (__device__ globals; no runtime allocation allowed)
__device__ __half g_x16[TOK * MODEL_DIM];              // x, single fp16
__device__ __half g_z16[TOK * MODEL_DIM];              // attn out, single fp16
__device__ __half g_wqkvT[QKV_DIM * MODEL_DIM];        // w_qkv^T*1024 [N][K]
__device__ __half g_woutT[MODEL_DIM * MODEL_DIM];      // w_out^T*1024
// Attention operands (fp16): Q single x128; K single; V^T split x1024.
__device__ __half g_q16[BH * SEQ * HEAD_DIM];  // [bh][s][d]
__device__ __half g_k16[BH * SEQ * HEAD_DIM];  // [bh][s][d]
__device__ __half g_vth[BH * HEAD_DIM * SEQ];  // [bh][d][s]
__device__ __half g_vtl[BH * HEAD_DIM * SEQ];

// ---------------------------------------------------------------------------
// PTX helpers (sm_80-compatible)
// ---------------------------------------------------------------------------
__device__ __forceinline__ uint32_t smem_to_u32(const void* p) {
    uint32_t a;
    asm("{ .reg .u64 tmp; cvta.to.shared.u64 tmp, %1; cvt.u32.u64 %0, tmp; }"
        : "=r"(a) : "l"(p));
    return a;
}
__device__ __forceinline__ void ldsm_x4(uint32_t* r, uint32_t addr) {
    asm volatile("ldmatrix.sync.aligned.m8n8.x4.shared.b16 {%0,%1,%2,%3}, [%4];"
                 : "=r"(r[0]), "=r"(r[1]), "=r"(r[2]), "=r"(r[3]) : "r"(addr));
}
__device__ __forceinline__ void mma_f16(float* c, const uint32_t* a, const uint32_t* b) {
    asm volatile(
        "mma.sync.aligned.m16n8k16.row.col.f32.f16.f16.f32 "
        "{%0,%1,%2,%3}, {%4,%5,%6,%7}, {%8,%9}, {%0,%1,%2,%3};"
        : "+f"(c[0]), "+f"(c[1]), "+f"(c[2]), "+f"(c[3])
        : "r"(a[0]), "r"(a[1]), "r"(a[2]), "r"(a[3]), "r"(b[0]), "r"(b[1]));
}
__device__ __forceinline__ void cp_async16(uint32_t dst, const void* src) {
    asm volatile("cp.async.cg.shared.global [%0], [%1], 16;" :: "r"(dst), "l"(src));
}
#define CP_COMMIT() asm volatile("cp.async.commit_group;" ::: "memory")
#define CP_WAIT1()  asm volatile("cp.async.wait_group 1;" ::: "memory")
#define CP_WAIT0()  asm volatile("cp.async.wait_group 0;" ::: "memory")
__device__ __forceinline__ uint32_t pack_f16x2(float lo, float hi) {
    uint32_t r;
    asm("cvt.rn.f16x2.f32 %0, %1, %2;" : "=r"(r) : "f"(hi), "f"(lo));
    return r;
}

// ---------------------------------------------------------------------------
// x convert: fp32 -> single fp16
// ---------------------------------------------------------------------------
__global__ void convert_f16_kernel(const float* __restrict__ X,
                                   __half* __restrict__ X16, int n4)
{
    int i = blockIdx.x * blockDim.x + threadIdx.x;
    if (i >= n4) return;
    float4 v = reinterpret_cast<const float4*>(X)[i];
    __half2 p0; p0.x = __float2half(v.x); p0.y = __float2half(v.y);
    __half2 p1; p1.x = __float2half(v.z); p1.y = __float2half(v.w);
    reinterpret_cast<__half2*>(X16)[i * 2]     = p0;
    reinterpret_cast<__half2*>(X16)[i * 2 + 1] = p1;
}

// ---------------------------------------------------------------------------
// Weight transpose to fp16 with x1024 scale: W[K][N] -> T[N][K]
// ---------------------------------------------------------------------------
__global__ void transpose_f16_kernel(const float* __restrict__ W,
                                     __half* __restrict__ T,
                                     int K, int N)
{
    __shared__ float tile[32][33];
    const int n0 = blockIdx.x * 32, k0 = blockIdx.y * 32;
    const int tx = threadIdx.x, ty = threadIdx.y;
#pragma unroll
    for (int i = 0; i < 32; i += 8)
        tile[ty + i][tx] = W[(size_t)(k0 + ty + i) * N + n0 + tx];
    __syncthreads();
#pragma unroll
    for (int i = 0; i < 32; i += 8) {
        float v = tile[tx][ty + i] * WSCALE;
        T[(size_t)(n0 + ty + i) * K + k0 + tx] = __float2half(v);
    }
}

// ---------------------------------------------------------------------------
// fp16 1-pass GEMM: C = A[M,K](fp16) @ B^T /1024 + bias
// QKV_EPI=true: fused epilogue writing fp16 attention operand layouts.
// BM=BN=128, BK=64. 2-stage cp.async pipeline (A,B tiles), 2 CTAs/SM.
// ---------------------------------------------------------------------------
static constexpr int TSTRIDE   = 144;               // 128B data + 16B pad
static constexpr int TILE_B    = 128 * TSTRIDE;     // 18432
static constexpr int STAGE_B   = 2 * TILE_B;        // A,B = 36864
static constexpr int GEMM_SMEM = 2 * STAGE_B;       // 73728 (x2 CTA = 147456)

template <bool QKV_EPI>
__global__ __launch_bounds__(256, 2)
void tc_gemm_kernel(const __half* __restrict__ A,
                    const __half* __restrict__ B,
                    const float* __restrict__ bias,
                    float* __restrict__ C,
                    int M, int N, int K)
{
    extern __shared__ char smem[];
    const uint32_t sb = smem_to_u32(smem);
    const int t    = threadIdx.x;
    const int wid  = t >> 5;
    const int lane = t & 31;
    const int wm   = wid & 1;
    const int wn   = wid >> 1;
    const int bm   = blockIdx.y * 128;
    const int bn   = blockIdx.x * 128;

    auto stage_load = [&](int s, int k0) {
#pragma unroll
        for (int i = 0; i < 8; i++) {
            int idx = t + i * 256;            // 0..2047
            int tensor = idx >> 10;           // 0=A 1=B
            int rem = idx & 1023;
            int r = rem >> 3;
            int c16 = (rem & 7) * 16;
            const char* src = (tensor == 0)
                ? (const char*)(A + (size_t)(bm + r) * K + k0) + c16
                : (const char*)(B + (size_t)(bn + r) * K + k0) + c16;
            cp_async16(sb + s * STAGE_B + tensor * TILE_B + r * TSTRIDE + c16, src);
        }
    };

    float acc[4][4][4];
#pragma unroll
    for (int i = 0; i < 4; i++)
#pragma unroll
        for (int j = 0; j < 4; j++)
#pragma unroll
            for (int k = 0; k < 4; k++) acc[i][j][k] = 0.0f;

    stage_load(0, 0);  CP_COMMIT();
    stage_load(1, 64); CP_COMMIT();

    const int sel  = lane >> 3;
    const int lrow = lane & 7;
    const int a_row_off = ((sel & 1) ? 8 : 0) + lrow;
    const int a_kc      = sel >> 1;
    const int b_row_off = ((sel >> 1) ? 8 : 0) + lrow;
    const int b_kc      = sel & 1;

    const int nch = K / 64;
    for (int ch = 0; ch < nch; ch++) {
        CP_WAIT1();
        __syncthreads();
        const uint32_t st = sb + (ch & 1) * STAGE_B;

#pragma unroll
        for (int ks = 0; ks < 4; ks++) {
            const uint32_t kbyte = ks * 32;
            uint32_t af[4][4], bf[2][4];
#pragma unroll
            for (int mt = 0; mt < 4; mt++)
                ldsm_x4(af[mt], st + (wm * 64 + mt * 16 + a_row_off) * TSTRIDE
                                   + kbyte + a_kc * 16);
#pragma unroll
            for (int p = 0; p < 2; p++)
                ldsm_x4(bf[p], st + TILE_B
                                  + (wn * 32 + p * 16 + b_row_off) * TSTRIDE
                                  + kbyte + b_kc * 16);
#pragma unroll
            for (int mt = 0; mt < 4; mt++)
#pragma unroll
                for (int nt = 0; nt < 4; nt++)
                    mma_f16(acc[mt][nt], af[mt], &bf[nt >> 1][(nt & 1) * 2]);
        }
        __syncthreads();
        if (ch + 2 < nch) stage_load(ch & 1, (ch + 2) * 64);
        CP_COMMIT();
    }
    CP_WAIT0();

    const int g  = lane >> 2;
    const int tq = lane & 3;

    if constexpr (!QKV_EPI) {
        // out-projection: fp32 C = acc/1024 + bias
#pragma unroll
        for (int mt = 0; mt < 4; mt++) {
#pragma unroll
            for (int nt = 0; nt < 4; nt++) {
                int row = bm + wm * 64 + mt * 16 + g;
                int col = bn + wn * 32 + nt * 8 + tq * 2;
                float b0 = bias[col], b1 = bias[col + 1];
                float2 v0 = make_float2(fmaf(acc[mt][nt][0], INV_WSCALE, b0),
                                        fmaf(acc[mt][nt][1], INV_WSCALE, b1));
                float2 v1 = make_float2(fmaf(acc[mt][nt][2], INV_WSCALE, b0),
                                        fmaf(acc[mt][nt][3], INV_WSCALE, b1));
                *reinterpret_cast<float2*>(C + (size_t)row * N + col)       = v0;
                *reinterpret_cast<float2*>(C + (size_t)(row + 8) * N + col) = v1;
            }
        }
    } else {
        // Fused QKV epilogue: q single x128; k single; v split x1024 transposed.
        const int sec = bn >> 10;              // 0=q, 1=k, 2=v
#pragma unroll
        for (int mt = 0; mt < 4; mt++) {
#pragma unroll
            for (int nt = 0; nt < 4; nt++) {
                int row = bm + wm * 64 + mt * 16 + g;
                int col = bn + wn * 32 + nt * 8 + tq * 2;
                float b0 = bias[col], b1 = bias[col + 1];
                float v0 = fmaf(acc[mt][nt][0], INV_WSCALE, b0);
                float v1 = fmaf(acc[mt][nt][1], INV_WSCALE, b1);
                float v2 = fmaf(acc[mt][nt][2], INV_WSCALE, b0);
                float v3 = fmaf(acc[mt][nt][3], INV_WSCALE, b1);
                int cc = col & 1023;
                int h  = cc >> 6, d = cc & 63;
                int b  = row >> 11, sq = row & 2047;
                int bh = b * 16 + h;
                if (sec == 0) {
                    size_t o = ((size_t)bh * SEQ + sq) * HEAD_DIM + d;
                    __half2 p0; p0.x = __float2half(v0 * 128.0f); p0.y = __float2half(v1 * 128.0f);
                    __half2 p1; p1.x = __float2half(v2 * 128.0f); p1.y = __float2half(v3 * 128.0f);
                    *reinterpret_cast<__half2*>(g_q16 + o)                = p0;
                    *reinterpret_cast<__half2*>(g_q16 + o + 8 * HEAD_DIM) = p1;
                } else if (sec == 1) {
                    size_t o = ((size_t)bh * SEQ + sq) * HEAD_DIM + d;
                    __half2 p0; p0.x = __float2half(v0); p0.y = __float2half(v1);
                    __half2 p1; p1.x = __float2half(v2); p1.y = __float2half(v3);
                    *reinterpret_cast<__half2*>(g_k16 + o)                = p0;
                    *reinterpret_cast<__half2*>(g_k16 + o + 8 * HEAD_DIM) = p1;
                } else {
                    // v: x1024 split fp16, transposed [bh][d][s]
                    v0 *= WSCALE; v1 *= WSCALE; v2 *= WSCALE; v3 *= WSCALE;
                    __half h0 = __float2half(v0), h1 = __float2half(v1);
                    __half h2 = __float2half(v2), h3 = __float2half(v3);
                    __half l0 = __float2half(v0 - __half2float(h0));
                    __half l1 = __float2half(v1 - __half2float(h1));
                    __half l2 = __float2half(v2 - __half2float(h2));
                    __half l3 = __float2half(v3 - __half2float(h3));
                    size_t ob = (size_t)bh * HEAD_DIM * SEQ;
                    size_t o0 = ob + (size_t)d * SEQ + sq;
                    size_t o1 = ob + (size_t)(d + 1) * SEQ + sq;
                    g_vth[o0]     = h0;  g_vtl[o0]     = l0;
                    g_vth[o1]     = h1;  g_vtl[o1]     = l1;
                    g_vth[o0 + 8] = h2;  g_vtl[o0 + 8] = l2;
                    g_vth[o1 + 8] = h3;  g_vtl[o1 + 8] = l3;
                }
            }
        }
    }
}

// ---------------------------------------------------------------------------
// Tensor-core flash attention, fp16: QK^T = Q(x128).K (1 pass);
// PV = P.(Vh+Vl)(x1024) (2 passes). Scores and output descaled by 1/1024.
// 2-stage KV pipeline (K,Vh,Vl), Q (1 tile) in smem, 2 CTAs/SM.
// ---------------------------------------------------------------------------
static constexpr int AT_STRIDE = 144;
static constexpr int AT_TILE   = 64 * AT_STRIDE;    // 9216
static constexpr int AT_STAGE  = 3 * AT_TILE;       // 27648: K, Vh, Vl
static constexpr int Q_TILE    = 128 * AT_STRIDE;   // 18432
static constexpr int QS_OFF    = 2 * AT_STAGE;      // 55296
static constexpr int AT_SMEM   = QS_OFF + Q_TILE;   // 73728 (x2 = 147456)

__global__ __launch_bounds__(256, 2)
void attn_tc_kernel()
{
    extern __shared__ char smem[];
    const uint32_t sb = smem_to_u32(smem);
    const int t    = threadIdx.x;
    const int wid  = t >> 5;
    const int lane = t & 31;
    const int g    = lane >> 2;
    const int tq   = lane & 3;
    const int bh   = blockIdx.y;
    const int q0   = blockIdx.x * 128;
    const int wrow = wid * 16;

    const int sel  = lane >> 3;
    const int lrow = lane & 7;
    const int a_row_off = ((sel & 1) ? 8 : 0) + lrow;
    const int a_kc      = sel >> 1;
    const int b_row_off = ((sel >> 1) ? 8 : 0) + lrow;
    const int b_kc      = sel & 1;

    // Q tile into smem
    {
        const char* baseQ = (const char*)(g_q16 + ((size_t)bh * SEQ + q0) * HEAD_DIM);
#pragma unroll
        for (int i = 0; i < 4; i++) {
            int idx = t + i * 256;
            int r = idx >> 3, c16 = (idx & 7) * 16;
            cp_async16(sb + QS_OFF + r * AT_STRIDE + c16, baseQ + (size_t)r * 128 + c16);
        }
    }

    auto load_stage = [&](int s, int kk0) {
        const char* baseK  = (const char*)(g_k16 + ((size_t)bh * SEQ + kk0) * HEAD_DIM);
        const char* baseVh = (const char*)(g_vth + (size_t)bh * HEAD_DIM * SEQ + kk0);
        const char* baseVl = (const char*)(g_vtl + (size_t)bh * HEAD_DIM * SEQ + kk0);
#pragma unroll
        for (int i = 0; i < 6; i++) {
            int idx = t + i * 256;            // 0..1535
            int tensor = idx >> 9;            // 0=K 1=Vh 2=Vl
            int rem = idx & 511;
            int r = rem >> 3;
            int c16 = (rem & 7) * 16;
            const char* src;
            if (tensor == 0)      src = baseK  + (size_t)r * 128 + c16;
            else if (tensor == 1) src = baseVh + (size_t)r * (SEQ * 2) + c16;
            else                  src = baseVl + (size_t)r * (SEQ * 2) + c16;
            cp_async16(sb + s * AT_STAGE + tensor * AT_TILE + r * AT_STRIDE + c16, src);
        }
    };

    float o[8][4];
#pragma unroll
    for (int i = 0; i < 8; i++)
#pragma unroll
        for (int j = 0; j < 4; j++) o[i][j] = 0.0f;
    float m0 = -CUDART_INF_F, m1 = -CUDART_INF_F, l0 = 0.0f, l1 = 0.0f;

    load_stage(0, 0);  CP_COMMIT();
    load_stage(1, 64); CP_COMMIT();

    const int nkt = SEQ / 64;
    for (int kt = 0; kt < nkt; kt++) {
        CP_WAIT1();
        __syncthreads();
        const uint32_t st = sb + (kt & 1) * AT_STAGE;

        // ---- S*1024 = Q K^T (1 pass) ----
        float s[8][4];
#pragma unroll
        for (int i = 0; i < 8; i++)
#pragma unroll
            for (int j = 0; j < 4; j++) s[i][j] = 0.0f;
#pragma unroll
        for (int ks = 0; ks < 4; ks++) {
            const uint32_t kbyte = ks * 32;
            uint32_t q4[4];
            ldsm_x4(q4, sb + QS_OFF + (wrow + a_row_off) * AT_STRIDE
                        + kbyte + a_kc * 16);
            uint32_t kf[4][4];
#pragma unroll
            for (int ng = 0; ng < 4; ng++)
                ldsm_x4(kf[ng], st + (ng * 16 + b_row_off) * AT_STRIDE + kbyte + b_kc * 16);
#pragma unroll
            for (int ng = 0; ng < 4; ng++) {
                mma_f16(s[ng * 2],     q4, &kf[ng][0]);
                mma_f16(s[ng * 2 + 1], q4, &kf[ng][2]);
            }
        }
#pragma unroll
        for (int nt = 0; nt < 8; nt++) {
            s[nt][0] *= INV_WSCALE; s[nt][1] *= INV_WSCALE;
            s[nt][2] *= INV_WSCALE; s[nt][3] *= INV_WSCALE;
        }

        // ---- online softmax ----
        float mt0 = -CUDART_INF_F, mt1 = -CUDART_INF_F;
#pragma unroll
        for (int nt = 0; nt < 8; nt++) {
            mt0 = fmaxf(mt0, fmaxf(s[nt][0], s[nt][1]));
            mt1 = fmaxf(mt1, fmaxf(s[nt][2], s[nt][3]));
        }
        mt0 = fmaxf(mt0, __shfl_xor_sync(0xFFFFFFFF, mt0, 1));
        mt0 = fmaxf(mt0, __shfl_xor_sync(0xFFFFFFFF, mt0, 2));
        mt1 = fmaxf(mt1, __shfl_xor_sync(0xFFFFFFFF, mt1, 1));
        mt1 = fmaxf(mt1, __shfl_xor_sync(0xFFFFFFFF, mt1, 2));
        float mn0 = fmaxf(m0, mt0), mn1 = fmaxf(m1, mt1);
        float c0 = __expf(m0 - mn0), c1 = __expf(m1 - mn1);
        m0 = mn0; m1 = mn1;
        float ls0 = 0.0f, ls1 = 0.0f;
#pragma unroll
        for (int nt = 0; nt < 8; nt++) {
            s[nt][0] = __expf(s[nt][0] - m0);
            s[nt][1] = __expf(s[nt][1] - m0);
            s[nt][2] = __expf(s[nt][2] - m1);
            s[nt][3] = __expf(s[nt][3] - m1);
            ls0 += s[nt][0] + s[nt][1];
            ls1 += s[nt][2] + s[nt][3];
        }
        l0 = l0 * c0 + ls0;
        l1 = l1 * c1 + ls1;
#pragma unroll
        for (int nt = 0; nt < 8; nt++) {
            o[nt][0] *= c0; o[nt][1] *= c0;
            o[nt][2] *= c1; o[nt][3] *= c1;
        }

        // ---- O*1024 += P (Vh+Vl) (2 passes) ----
#pragma unroll
        for (int ks = 0; ks < 4; ks++) {
            uint32_t pa[4];
#pragma unroll
            for (int half = 0; half < 2; half++) {
                const float* sp = s[2 * ks + half];
                pa[half * 2]     = pack_f16x2(sp[0], sp[1]);
                pa[half * 2 + 1] = pack_f16x2(sp[2], sp[3]);
            }
            const uint32_t kbyte = ks * 32 + b_kc * 16;
            uint32_t vh[4][4], vl[4][4];
#pragma unroll
            for (int ng = 0; ng < 4; ng++)
                ldsm_x4(vh[ng], st + AT_TILE + (ng * 16 + b_row_off) * AT_STRIDE + kbyte);
#pragma unroll
            for (int ng = 0; ng < 4; ng++)
                ldsm_x4(vl[ng], st + 2 * AT_TILE + (ng * 16 + b_row_off) * AT_STRIDE + kbyte);
#pragma unroll
            for (int ng = 0; ng < 4; ng++) {
                mma_f16(o[ng * 2],     pa, &vh[ng][0]);
                mma_f16(o[ng * 2 + 1], pa, &vh[ng][2]);
            }
#pragma unroll
            for (int ng = 0; ng < 4; ng++) {
                mma_f16(o[ng * 2],     pa, &vl[ng][0]);
                mma_f16(o[ng * 2 + 1], pa, &vl[ng][2]);
            }
        }
        __syncthreads();
        if (kt + 2 < nkt) load_stage(kt & 1, (kt + 2) * 64);
        CP_COMMIT();
    }
    CP_WAIT0();

    // ---- finalize: out = o / (l * 1024), write single fp16 z ----
    l0 += __shfl_xor_sync(0xFFFFFFFF, l0, 1);
    l0 += __shfl_xor_sync(0xFFFFFFFF, l0, 2);
    l1 += __shfl_xor_sync(0xFFFFFFFF, l1, 1);
    l1 += __shfl_xor_sync(0xFFFFFFFF, l1, 2);
    float inv0 = INV_WSCALE / l0, inv1 = INV_WSCALE / l1;

    const int b = bh >> 4, h = bh & 15;
    const size_t tok0 = (size_t)b * SEQ + q0 + wrow + g;
#pragma unroll
    for (int nt = 0; nt < 8; nt++) {
        int col = h * HEAD_DIM + nt * 8 + tq * 2;
        __half2 p0, p1;
        p0.x = __float2half(o[nt][0] * inv0);
        p0.y = __float2half(o[nt][1] * inv0);
        p1.x = __float2half(o[nt][2] * inv1);
        p1.y = __float2half(o[nt][3] * inv1);
        *reinterpret_cast<__half2*>(g_z16 + tok0 * MODEL_DIM + col)       = p0;
        *reinterpret_cast<__half2*>(g_z16 + (tok0 + 8) * MODEL_DIM + col) = p1;
    }
}

// ---------------------------------------------------------------------------
// Launch
// ---------------------------------------------------------------------------
extern "C" void kernel_launch(void* const* d_in, const int* in_sizes, int n_in,
                              void* d_out, int out_size)
{
    const float* x     = (const float*)d_in[0];
    const float* w_qkv = (const float*)d_in[1];
    const float* b_qkv = (const float*)d_in[2];
    const float* w_out = (const float*)d_in[3];
    const float* b_out = (const float*)d_in[4];
    float* out = (float*)d_out;

    __half *x16, *z16, *wqkvT, *woutT;
    cudaGetSymbolAddress((void**)&x16, g_x16);
    cudaGetSymbolAddress((void**)&z16, g_z16);
    cudaGetSymbolAddress((void**)&wqkvT, g_wqkvT);
    cudaGetSymbolAddress((void**)&woutT, g_woutT);

    cudaFuncSetAttribute(tc_gemm_kernel<true>,
                         cudaFuncAttributeMaxDynamicSharedMemorySize, GEMM_SMEM);
    cudaFuncSetAttribute(tc_gemm_kernel<false>,
                         cudaFuncAttributeMaxDynamicSharedMemorySize, GEMM_SMEM);
    cudaFuncSetAttribute(attn_tc_kernel,
                         cudaFuncAttributeMaxDynamicSharedMemorySize, AT_SMEM);

    // 0. Preprocess: x -> fp16; weights -> transposed fp16 (x1024)
    {
        int n4 = TOK * MODEL_DIM / 4;
        convert_f16_kernel<<<(n4 + 255) / 256, 256>>>(x, x16, n4);
        transpose_f16_kernel<<<dim3(QKV_DIM / 32, MODEL_DIM / 32), dim3(32, 8)>>>(
            w_qkv, wqkvT, MODEL_DIM, QKV_DIM);
        transpose_f16_kernel<<<dim3(MODEL_DIM / 32, MODEL_DIM / 32), dim3(32, 8)>>>(
            w_out, woutT, MODEL_DIM, MODEL_DIM);
    }

    // 1. QKV projection (fp16 1-pass) with fused operand-layout epilogue
    tc_gemm_kernel<true><<<dim3(QKV_DIM / 128, TOK / 128), 256, GEMM_SMEM>>>(
        x16, wqkvT, b_qkv, nullptr, TOK, QKV_DIM, MODEL_DIM);

    // 2. Tensor-core flash attention (fp16; QK 1-pass, PV 2-pass)
    attn_tc_kernel<<<dim3(SEQ / 128, BH), 256, AT_SMEM>>>();

    // 3. Output projection (fp16 1-pass)
    tc_gemm_kernel<false><<<dim3(MODEL_DIM / 128, TOK / 128), 256, GEMM_SMEM>>>(
        z16, woutT, b_out, out, TOK, MODEL_DIM, MODEL_DIM);
}

// round 17
// speedup vs baseline: 7.4533x; 1.1771x over previous
#include <cuda_runtime.h>
#include <cuda_bf16.h>
#include <cuda_fp16.h>
#include <math_constants.h>
#include <cstdint>

// Problem constants
static constexpr int MODEL_DIM = 1024;
static constexpr int HEAD      = 16;
static constexpr int HEAD_DIM  = 64;
static constexpr int BATCH     = 2;
static constexpr int SEQ       = 2048;
static constexpr int TOK       = BATCH * SEQ;      // 4096
static constexpr int QKV_DIM   = 3 * MODEL_DIM;    // 3072
static constexpr int BH        = BATCH * HEAD;     // 32

// Scale tricks: weights stored x1024 in fp16; Q stored x128 (0.125 x 1024).
// Scores descaled by 1/1024 before softmax. V plain fp16 (O(1) magnitudes).
static constexpr float WSCALE     = 1024.0f;
static constexpr float INV_WSCALE = 1.0f / 1024.0f;

// Scratch (__device__ globals; no runtime allocation allowed)
__device__ __half g_x16[TOK * MODEL_DIM];              // x, single fp16
__device__ __half g_z16[TOK * MODEL_DIM];              // attn out, single fp16
__device__ __half g_wqkvT[QKV_DIM * MODEL_DIM];        // w_qkv^T*1024 [N][K]
__device__ __half g_woutT[MODEL_DIM * MODEL_DIM];      // w_out^T*1024
// Attention operands (fp16, all single): Q x128; K; V^T plain.
__device__ __half g_q16[BH * SEQ * HEAD_DIM];  // [bh][s][d]
__device__ __half g_k16[BH * SEQ * HEAD_DIM];  // [bh][s][d]
__device__ __half g_vt16[BH * HEAD_DIM * SEQ]; // [bh][d][s]

// ---------------------------------------------------------------------------
// PTX helpers (sm_80-compatible)
// ---------------------------------------------------------------------------
__device__ __forceinline__ uint32_t smem_to_u32(const void* p) {
    uint32_t a;
    asm("{ .reg .u64 tmp; cvta.to.shared.u64 tmp, %1; cvt.u32.u64 %0, tmp; }"
        : "=r"(a) : "l"(p));
    return a;
}
__device__ __forceinline__ void ldsm_x4(uint32_t* r, uint32_t addr) {
    asm volatile("ldmatrix.sync.aligned.m8n8.x4.shared.b16 {%0,%1,%2,%3}, [%4];"
                 : "=r"(r[0]), "=r"(r[1]), "=r"(r[2]), "=r"(r[3]) : "r"(addr));
}
__device__ __forceinline__ void mma_f16(float* c, const uint32_t* a, const uint32_t* b) {
    asm volatile(
        "mma.sync.aligned.m16n8k16.row.col.f32.f16.f16.f32 "
        "{%0,%1,%2,%3}, {%4,%5,%6,%7}, {%8,%9}, {%0,%1,%2,%3};"
        : "+f"(c[0]), "+f"(c[1]), "+f"(c[2]), "+f"(c[3])
        : "r"(a[0]), "r"(a[1]), "r"(a[2]), "r"(a[3]), "r"(b[0]), "r"(b[1]));
}
__device__ __forceinline__ void cp_async16(uint32_t dst, const void* src) {
    asm volatile("cp.async.cg.shared.global [%0], [%1], 16;" :: "r"(dst), "l"(src));
}
#define CP_COMMIT() asm volatile("cp.async.commit_group;" ::: "memory")
#define CP_WAIT1()  asm volatile("cp.async.wait_group 1;" ::: "memory")
#define CP_WAIT0()  asm volatile("cp.async.wait_group 0;" ::: "memory")
__device__ __forceinline__ uint32_t pack_f16x2(float lo, float hi) {
    uint32_t r;
    asm("cvt.rn.f16x2.f32 %0, %1, %2;" : "=r"(r) : "f"(hi), "f"(lo));
    return r;
}

// ---------------------------------------------------------------------------
// x convert: fp32 -> single fp16
// ---------------------------------------------------------------------------
__global__ void convert_f16_kernel(const float* __restrict__ X,
                                   __half* __restrict__ X16, int n4)
{
    int i = blockIdx.x * blockDim.x + threadIdx.x;
    if (i >= n4) return;
    float4 v = reinterpret_cast<const float4*>(X)[i];
    __half2 p0; p0.x = __float2half(v.x); p0.y = __float2half(v.y);
    __half2 p1; p1.x = __float2half(v.z); p1.y = __float2half(v.w);
    reinterpret_cast<__half2*>(X16)[i * 2]     = p0;
    reinterpret_cast<__half2*>(X16)[i * 2 + 1] = p1;
}

// ---------------------------------------------------------------------------
// Weight transpose to fp16 with x1024 scale: W[K][N] -> T[N][K]
// ---------------------------------------------------------------------------
__global__ void transpose_f16_kernel(const float* __restrict__ W,
                                     __half* __restrict__ T,
                                     int K, int N)
{
    __shared__ float tile[32][33];
    const int n0 = blockIdx.x * 32, k0 = blockIdx.y * 32;
    const int tx = threadIdx.x, ty = threadIdx.y;
#pragma unroll
    for (int i = 0; i < 32; i += 8)
        tile[ty + i][tx] = W[(size_t)(k0 + ty + i) * N + n0 + tx];
    __syncthreads();
#pragma unroll
    for (int i = 0; i < 32; i += 8) {
        float v = tile[tx][ty + i] * WSCALE;
        T[(size_t)(n0 + ty + i) * K + k0 + tx] = __float2half(v);
    }
}

// ---------------------------------------------------------------------------
// fp16 1-pass GEMM: C = A[M,K](fp16) @ B^T /1024 + bias
// QKV_EPI=true: fused epilogue writing fp16 attention operand layouts.
// BM=BN=128, BK=64. 2-stage cp.async pipeline (A,B tiles), 2 CTAs/SM.
// ---------------------------------------------------------------------------
static constexpr int TSTRIDE   = 144;               // 128B data + 16B pad
static constexpr int TILE_B    = 128 * TSTRIDE;     // 18432
static constexpr int STAGE_B   = 2 * TILE_B;        // A,B = 36864
static constexpr int GEMM_SMEM = 2 * STAGE_B;       // 73728 (x2 CTA = 147456)

template <bool QKV_EPI>
__global__ __launch_bounds__(256, 2)
void tc_gemm_kernel(const __half* __restrict__ A,
                    const __half* __restrict__ B,
                    const float* __restrict__ bias,
                    float* __restrict__ C,
                    int M, int N, int K)
{
    extern __shared__ char smem[];
    const uint32_t sb = smem_to_u32(smem);
    const int t    = threadIdx.x;
    const int wid  = t >> 5;
    const int lane = t & 31;
    const int wm   = wid & 1;
    const int wn   = wid >> 1;
    const int bm   = blockIdx.y * 128;
    const int bn   = blockIdx.x * 128;

    auto stage_load = [&](int s, int k0) {
#pragma unroll
        for (int i = 0; i < 8; i++) {
            int idx = t + i * 256;            // 0..2047
            int tensor = idx >> 10;           // 0=A 1=B
            int rem = idx & 1023;
            int r = rem >> 3;
            int c16 = (rem & 7) * 16;
            const char* src = (tensor == 0)
                ? (const char*)(A + (size_t)(bm + r) * K + k0) + c16
                : (const char*)(B + (size_t)(bn + r) * K + k0) + c16;
            cp_async16(sb + s * STAGE_B + tensor * TILE_B + r * TSTRIDE + c16, src);
        }
    };

    float acc[4][4][4];
#pragma unroll
    for (int i = 0; i < 4; i++)
#pragma unroll
        for (int j = 0; j < 4; j++)
#pragma unroll
            for (int k = 0; k < 4; k++) acc[i][j][k] = 0.0f;

    stage_load(0, 0);  CP_COMMIT();
    stage_load(1, 64); CP_COMMIT();

    const int sel  = lane >> 3;
    const int lrow = lane & 7;
    const int a_row_off = ((sel & 1) ? 8 : 0) + lrow;
    const int a_kc      = sel >> 1;
    const int b_row_off = ((sel >> 1) ? 8 : 0) + lrow;
    const int b_kc      = sel & 1;

    const int nch = K / 64;
    for (int ch = 0; ch < nch; ch++) {
        CP_WAIT1();
        __syncthreads();
        const uint32_t st = sb + (ch & 1) * STAGE_B;

#pragma unroll
        for (int ks = 0; ks < 4; ks++) {
            const uint32_t kbyte = ks * 32;
            uint32_t af[4][4], bf[2][4];
#pragma unroll
            for (int mt = 0; mt < 4; mt++)
                ldsm_x4(af[mt], st + (wm * 64 + mt * 16 + a_row_off) * TSTRIDE
                                   + kbyte + a_kc * 16);
#pragma unroll
            for (int p = 0; p < 2; p++)
                ldsm_x4(bf[p], st + TILE_B
                                  + (wn * 32 + p * 16 + b_row_off) * TSTRIDE
                                  + kbyte + b_kc * 16);
#pragma unroll
            for (int mt = 0; mt < 4; mt++)
#pragma unroll
                for (int nt = 0; nt < 4; nt++)
                    mma_f16(acc[mt][nt], af[mt], &bf[nt >> 1][(nt & 1) * 2]);
        }
        __syncthreads();
        if (ch + 2 < nch) stage_load(ch & 1, (ch + 2) * 64);
        CP_COMMIT();
    }
    CP_WAIT0();

    const int g  = lane >> 2;
    const int tq = lane & 3;

    if constexpr (!QKV_EPI) {
        // out-projection: fp32 C = acc/1024 + bias
#pragma unroll
        for (int mt = 0; mt < 4; mt++) {
#pragma unroll
            for (int nt = 0; nt < 4; nt++) {
                int row = bm + wm * 64 + mt * 16 + g;
                int col = bn + wn * 32 + nt * 8 + tq * 2;
                float b0 = bias[col], b1 = bias[col + 1];
                float2 v0 = make_float2(fmaf(acc[mt][nt][0], INV_WSCALE, b0),
                                        fmaf(acc[mt][nt][1], INV_WSCALE, b1));
                float2 v1 = make_float2(fmaf(acc[mt][nt][2], INV_WSCALE, b0),
                                        fmaf(acc[mt][nt][3], INV_WSCALE, b1));
                *reinterpret_cast<float2*>(C + (size_t)row * N + col)       = v0;
                *reinterpret_cast<float2*>(C + (size_t)(row + 8) * N + col) = v1;
            }
        }
    } else {
        // Fused QKV epilogue: q x128; k plain; v plain transposed. All single fp16.
        const int sec = bn >> 10;              // 0=q, 1=k, 2=v
#pragma unroll
        for (int mt = 0; mt < 4; mt++) {
#pragma unroll
            for (int nt = 0; nt < 4; nt++) {
                int row = bm + wm * 64 + mt * 16 + g;
                int col = bn + wn * 32 + nt * 8 + tq * 2;
                float b0 = bias[col], b1 = bias[col + 1];
                float v0 = fmaf(acc[mt][nt][0], INV_WSCALE, b0);
                float v1 = fmaf(acc[mt][nt][1], INV_WSCALE, b1);
                float v2 = fmaf(acc[mt][nt][2], INV_WSCALE, b0);
                float v3 = fmaf(acc[mt][nt][3], INV_WSCALE, b1);
                int cc = col & 1023;
                int h  = cc >> 6, d = cc & 63;
                int b  = row >> 11, sq = row & 2047;
                int bh = b * 16 + h;
                if (sec == 0) {
                    size_t o = ((size_t)bh * SEQ + sq) * HEAD_DIM + d;
                    __half2 p0; p0.x = __float2half(v0 * 128.0f); p0.y = __float2half(v1 * 128.0f);
                    __half2 p1; p1.x = __float2half(v2 * 128.0f); p1.y = __float2half(v3 * 128.0f);
                    *reinterpret_cast<__half2*>(g_q16 + o)                = p0;
                    *reinterpret_cast<__half2*>(g_q16 + o + 8 * HEAD_DIM) = p1;
                } else if (sec == 1) {
                    size_t o = ((size_t)bh * SEQ + sq) * HEAD_DIM + d;
                    __half2 p0; p0.x = __float2half(v0); p0.y = __float2half(v1);
                    __half2 p1; p1.x = __float2half(v2); p1.y = __float2half(v3);
                    *reinterpret_cast<__half2*>(g_k16 + o)                = p0;
                    *reinterpret_cast<__half2*>(g_k16 + o + 8 * HEAD_DIM) = p1;
                } else {
                    // v: plain fp16, transposed [bh][d][s]
                    size_t ob = (size_t)bh * HEAD_DIM * SEQ;
                    size_t o0 = ob + (size_t)d * SEQ + sq;
                    size_t o1 = ob + (size_t)(d + 1) * SEQ + sq;
                    g_vt16[o0]     = __float2half(v0);
                    g_vt16[o1]     = __float2half(v1);
                    g_vt16[o0 + 8] = __float2half(v2);
                    g_vt16[o1 + 8] = __float2half(v3);
                }
            }
        }
    }
}

// ---------------------------------------------------------------------------
// Tensor-core flash attention, fp16 all-single: QK^T = Q(x128).K (1 pass, /1024);
// PV = P.V (1 pass, plain). 2-stage KV pipeline (K,V), Q in smem, 2 CTAs/SM.
// ---------------------------------------------------------------------------
static constexpr int AT_STRIDE = 144;
static constexpr int AT_TILE   = 64 * AT_STRIDE;    // 9216
static constexpr int AT_STAGE  = 2 * AT_TILE;       // 18432: K, V
static constexpr int Q_TILE    = 128 * AT_STRIDE;   // 18432
static constexpr int QS_OFF    = 2 * AT_STAGE;      // 36864
static constexpr int AT_SMEM   = QS_OFF + Q_TILE;   // 55296 (x2 = 110592)

__global__ __launch_bounds__(256, 2)
void attn_tc_kernel()
{
    extern __shared__ char smem[];
    const uint32_t sb = smem_to_u32(smem);
    const int t    = threadIdx.x;
    const int wid  = t >> 5;
    const int lane = t & 31;
    const int g    = lane >> 2;
    const int tq   = lane & 3;
    const int bh   = blockIdx.y;
    const int q0   = blockIdx.x * 128;
    const int wrow = wid * 16;

    const int sel  = lane >> 3;
    const int lrow = lane & 7;
    const int a_row_off = ((sel & 1) ? 8 : 0) + lrow;
    const int a_kc      = sel >> 1;
    const int b_row_off = ((sel >> 1) ? 8 : 0) + lrow;
    const int b_kc      = sel & 1;

    // Q tile into smem
    {
        const char* baseQ = (const char*)(g_q16 + ((size_t)bh * SEQ + q0) * HEAD_DIM);
#pragma unroll
        for (int i = 0; i < 4; i++) {
            int idx = t + i * 256;
            int r = idx >> 3, c16 = (idx & 7) * 16;
            cp_async16(sb + QS_OFF + r * AT_STRIDE + c16, baseQ + (size_t)r * 128 + c16);
        }
    }

    auto load_stage = [&](int s, int kk0) {
        const char* baseK = (const char*)(g_k16 + ((size_t)bh * SEQ + kk0) * HEAD_DIM);
        const char* baseV = (const char*)(g_vt16 + (size_t)bh * HEAD_DIM * SEQ + kk0);
#pragma unroll
        for (int i = 0; i < 4; i++) {
            int idx = t + i * 256;            // 0..1023
            int tensor = idx >> 9;            // 0=K 1=V
            int rem = idx & 511;
            int r = rem >> 3;
            int c16 = (rem & 7) * 16;
            const char* src = (tensor == 0)
                ? baseK + (size_t)r * 128 + c16
                : baseV + (size_t)r * (SEQ * 2) + c16;
            cp_async16(sb + s * AT_STAGE + tensor * AT_TILE + r * AT_STRIDE + c16, src);
        }
    };

    float o[8][4];
#pragma unroll
    for (int i = 0; i < 8; i++)
#pragma unroll
        for (int j = 0; j < 4; j++) o[i][j] = 0.0f;
    float m0 = -CUDART_INF_F, m1 = -CUDART_INF_F, l0 = 0.0f, l1 = 0.0f;

    load_stage(0, 0);  CP_COMMIT();
    load_stage(1, 64); CP_COMMIT();

    const int nkt = SEQ / 64;
    for (int kt = 0; kt < nkt; kt++) {
        CP_WAIT1();
        __syncthreads();
        const uint32_t st = sb + (kt & 1) * AT_STAGE;

        // ---- S*1024 = Q K^T (1 pass) ----
        float s[8][4];
#pragma unroll
        for (int i = 0; i < 8; i++)
#pragma unroll
            for (int j = 0; j < 4; j++) s[i][j] = 0.0f;
#pragma unroll
        for (int ks = 0; ks < 4; ks++) {
            const uint32_t kbyte = ks * 32;
            uint32_t q4[4];
            ldsm_x4(q4, sb + QS_OFF + (wrow + a_row_off) * AT_STRIDE
                        + kbyte + a_kc * 16);
            uint32_t kf[4][4];
#pragma unroll
            for (int ng = 0; ng < 4; ng++)
                ldsm_x4(kf[ng], st + (ng * 16 + b_row_off) * AT_STRIDE + kbyte + b_kc * 16);
#pragma unroll
            for (int ng = 0; ng < 4; ng++) {
                mma_f16(s[ng * 2],     q4, &kf[ng][0]);
                mma_f16(s[ng * 2 + 1], q4, &kf[ng][2]);
            }
        }
#pragma unroll
        for (int nt = 0; nt < 8; nt++) {
            s[nt][0] *= INV_WSCALE; s[nt][1] *= INV_WSCALE;
            s[nt][2] *= INV_WSCALE; s[nt][3] *= INV_WSCALE;
        }

        // ---- online softmax ----
        float mt0 = -CUDART_INF_F, mt1 = -CUDART_INF_F;
#pragma unroll
        for (int nt = 0; nt < 8; nt++) {
            mt0 = fmaxf(mt0, fmaxf(s[nt][0], s[nt][1]));
            mt1 = fmaxf(mt1, fmaxf(s[nt][2], s[nt][3]));
        }
        mt0 = fmaxf(mt0, __shfl_xor_sync(0xFFFFFFFF, mt0, 1));
        mt0 = fmaxf(mt0, __shfl_xor_sync(0xFFFFFFFF, mt0, 2));
        mt1 = fmaxf(mt1, __shfl_xor_sync(0xFFFFFFFF, mt1, 1));
        mt1 = fmaxf(mt1, __shfl_xor_sync(0xFFFFFFFF, mt1, 2));
        float mn0 = fmaxf(m0, mt0), mn1 = fmaxf(m1, mt1);
        float c0 = __expf(m0 - mn0), c1 = __expf(m1 - mn1);
        m0 = mn0; m1 = mn1;
        float ls0 = 0.0f, ls1 = 0.0f;
#pragma unroll
        for (int nt = 0; nt < 8; nt++) {
            s[nt][0] = __expf(s[nt][0] - m0);
            s[nt][1] = __expf(s[nt][1] - m0);
            s[nt][2] = __expf(s[nt][2] - m1);
            s[nt][3] = __expf(s[nt][3] - m1);
            ls0 += s[nt][0] + s[nt][1];
            ls1 += s[nt][2] + s[nt][3];
        }
        l0 = l0 * c0 + ls0;
        l1 = l1 * c1 + ls1;
#pragma unroll
        for (int nt = 0; nt < 8; nt++) {
            o[nt][0] *= c0; o[nt][1] *= c0;
            o[nt][2] *= c1; o[nt][3] *= c1;
        }

        // ---- O += P V (1 pass) ----
#pragma unroll
        for (int ks = 0; ks < 4; ks++) {
            uint32_t pa[4];
#pragma unroll
            for (int half = 0; half < 2; half++) {
                const float* sp = s[2 * ks + half];
                pa[half * 2]     = pack_f16x2(sp[0], sp[1]);
                pa[half * 2 + 1] = pack_f16x2(sp[2], sp[3]);
            }
            const uint32_t kbyte = ks * 32 + b_kc * 16;
            uint32_t vf[4][4];
#pragma unroll
            for (int ng = 0; ng < 4; ng++)
                ldsm_x4(vf[ng], st + AT_TILE + (ng * 16 + b_row_off) * AT_STRIDE + kbyte);
#pragma unroll
            for (int ng = 0; ng < 4; ng++) {
                mma_f16(o[ng * 2],     pa, &vf[ng][0]);
                mma_f16(o[ng * 2 + 1], pa, &vf[ng][2]);
            }
        }
        __syncthreads();
        if (kt + 2 < nkt) load_stage(kt & 1, (kt + 2) * 64);
        CP_COMMIT();
    }
    CP_WAIT0();

    // ---- finalize: out = o / l, write single fp16 z ----
    l0 += __shfl_xor_sync(0xFFFFFFFF, l0, 1);
    l0 += __shfl_xor_sync(0xFFFFFFFF, l0, 2);
    l1 += __shfl_xor_sync(0xFFFFFFFF, l1, 1);
    l1 += __shfl_xor_sync(0xFFFFFFFF, l1, 2);
    float inv0 = 1.0f / l0, inv1 = 1.0f / l1;

    const int b = bh >> 4, h = bh & 15;
    const size_t tok0 = (size_t)b * SEQ + q0 + wrow + g;
#pragma unroll
    for (int nt = 0; nt < 8; nt++) {
        int col = h * HEAD_DIM + nt * 8 + tq * 2;
        __half2 p0, p1;
        p0.x = __float2half(o[nt][0] * inv0);
        p0.y = __float2half(o[nt][1] * inv0);
        p1.x = __float2half(o[nt][2] * inv1);
        p1.y = __float2half(o[nt][3] * inv1);
        *reinterpret_cast<__half2*>(g_z16 + tok0 * MODEL_DIM + col)       = p0;
        *reinterpret_cast<__half2*>(g_z16 + (tok0 + 8) * MODEL_DIM + col) = p1;
    }
}

// ---------------------------------------------------------------------------
// Launch
// ---------------------------------------------------------------------------
extern "C" void kernel_launch(void* const* d_in, const int* in_sizes, int n_in,
                              void* d_out, int out_size)
{
    const float* x     = (const float*)d_in[0];
    const float* w_qkv = (const float*)d_in[1];
    const float* b_qkv = (const float*)d_in[2];
    const float* w_out = (const float*)d_in[3];
    const float* b_out = (const float*)d_in[4];
    float* out = (float*)d_out;

    __half *x16, *z16, *wqkvT, *woutT;
    cudaGetSymbolAddress((void**)&x16, g_x16);
    cudaGetSymbolAddress((void**)&z16, g_z16);
    cudaGetSymbolAddress((void**)&wqkvT, g_wqkvT);
    cudaGetSymbolAddress((void**)&woutT, g_woutT);

    cudaFuncSetAttribute(tc_gemm_kernel<true>,
                         cudaFuncAttributeMaxDynamicSharedMemorySize, GEMM_SMEM);
    cudaFuncSetAttribute(tc_gemm_kernel<false>,
                         cudaFuncAttributeMaxDynamicSharedMemorySize, GEMM_SMEM);
    cudaFuncSetAttribute(attn_tc_kernel,
                         cudaFuncAttributeMaxDynamicSharedMemorySize, AT_SMEM);

    // 0. Preprocess: x -> fp16; weights -> transposed fp16 (x1024)
    {
        int n4 = TOK * MODEL_DIM / 4;
        convert_f16_kernel<<<(n4 + 255) / 256, 256>>>(x, x16, n4);
        transpose_f16_kernel<<<dim3(QKV_DIM / 32, MODEL_DIM / 32), dim3(32, 8)>>>(
            w_qkv, wqkvT, MODEL_DIM, QKV_DIM);
        transpose_f16_kernel<<<dim3(MODEL_DIM / 32, MODEL_DIM / 32), dim3(32, 8)>>>(
            w_out, woutT, MODEL_DIM, MODEL_DIM);
    }

    // 1. QKV projection (fp16 1-pass) with fused operand-layout epilogue
    tc_gemm_kernel<true><<<dim3(QKV_DIM / 128, TOK / 128), 256, GEMM_SMEM>>>(
        x16, wqkvT, b_qkv, nullptr, TOK, QKV_DIM, MODEL_DIM);

    // 2. Tensor-core flash attention (fp16; QK 1-pass, PV 1-pass)
    attn_tc_kernel<<<dim3(SEQ / 128, BH), 256, AT_SMEM>>>();

    // 3. Output projection (fp16 1-pass)
    tc_gemm_kernel<false><<<dim3(MODEL_DIM / 128, TOK / 128), 256, GEMM_SMEM>>>(
        z16, woutT, b_out, out, TOK, MODEL_DIM, MODEL_DIM);
}